// round 1
// baseline (speedup 1.0000x reference)
#include <cuda_runtime.h>
#include <math.h>

#define B_  8
#define N_  1024
#define D_  768
#define V_  30000
#define C_  512
#define Hh_ 768
#define INV_T 5.0f
#define BN_EPS 1e-5f

// ---------------- scratch (static device globals; no allocs allowed) ----------------
__device__ float g_vinv[V_];                  // 1/||vocab row||
__device__ float g_h[(size_t)V_ * Hh_];       // h = norm(vocab) @ W1
__device__ float g_proto[(size_t)V_ * D_];    // prototypes (in-place normalized)
__device__ float g_pt[(size_t)B_ * N_ * D_];  // normalized patch tokens
__device__ float g_colsum[Hh_], g_colsq[Hh_];
__device__ float g_scale[Hh_], g_shift[Hh_];

// ---------------- small helpers ----------------
__device__ __forceinline__ float warpSum(float v) {
    #pragma unroll
    for (int o = 16; o; o >>= 1) v += __shfl_xor_sync(0xffffffffu, v, o);
    return v;
}

// returns the block-wide sum to all threads (blockDim.x multiple of 32, <=1024)
__device__ float blockSumAll(float v) {
    __shared__ float sb[33];
    int lane = threadIdx.x & 31, w = threadIdx.x >> 5;
    v = warpSum(v);
    if (lane == 0) sb[w] = v;
    __syncthreads();
    if (threadIdx.x == 0) {
        float s = 0.f;
        int nw = (blockDim.x + 31) >> 5;
        for (int i = 0; i < nw; i++) s += sb[i];
        sb[32] = s;
    }
    __syncthreads();
    return sb[32];
}

// ---------------- stage kernels ----------------

// 1/||vocab row||  (V rows of C)
__global__ void vnorm_kernel(const float* __restrict__ vocab) {
    int r = blockIdx.x;
    const float* row = vocab + (size_t)r * C_;
    float s = 0.f;
    for (int c = threadIdx.x; c < C_; c += 256) { float x = row[c]; s += x * x; }
    s = blockSumAll(s);
    if (threadIdx.x == 0) g_vinv[r] = 1.0f / fmaxf(sqrtf(s), 1e-12f);
}

// normalize patch tokens -> g_pt  (B*N rows of D)
__global__ void ptnorm_kernel(const float* __restrict__ pt) {
    int r = blockIdx.x;
    const float* row = pt + (size_t)r * D_;
    float* orow = g_pt + (size_t)r * D_;
    int t = threadIdx.x;
    float x0 = row[t], x1 = row[t + 256], x2 = row[t + 512];
    float s = blockSumAll(x0 * x0 + x1 * x1 + x2 * x2);
    float inv = 1.0f / fmaxf(sqrtf(s), 1e-12f);
    orow[t] = x0 * inv; orow[t + 256] = x1 * inv; orow[t + 512] = x2 * inv;
}

__global__ void zero_stats_kernel() {
    int t = threadIdx.x;
    if (t < Hh_) { g_colsum[t] = 0.f; g_colsq[t] = 0.f; }
}

// GEMM1: g_h[m,n] = (vocab[m,:]*g_vinv[m]) @ W1[:,n]   M=V K=C N=Hh
__global__ __launch_bounds__(256, 2) void gemm1_kernel(const float* __restrict__ A,
                                                       const float* __restrict__ Bw) {
    __shared__ float As[16][132];
    __shared__ float Bs[16][132];
    const int mb = blockIdx.y * 128, nb = blockIdx.x * 128;
    const int t = threadIdx.x, tx = t & 15, ty = t >> 4;
    float acc[8][8];
    #pragma unroll
    for (int i = 0; i < 8; i++)
        #pragma unroll
        for (int j = 0; j < 8; j++) acc[i][j] = 0.f;

    for (int k0 = 0; k0 < C_; k0 += 16) {
        __syncthreads();
        #pragma unroll
        for (int p = 0; p < 2; p++) {
            int m = p * 64 + (t >> 2);
            int kq = (t & 3) * 4;
            int gm = mb + m;
            float4 v = (gm < V_) ? *(const float4*)(A + (size_t)gm * C_ + k0 + kq)
                                 : make_float4(0.f, 0.f, 0.f, 0.f);
            As[kq + 0][m] = v.x; As[kq + 1][m] = v.y; As[kq + 2][m] = v.z; As[kq + 3][m] = v.w;
        }
        #pragma unroll
        for (int p = 0; p < 2; p++) {
            int idx = p * 256 + t;
            int k = idx >> 5, nq = (idx & 31) * 4;
            *(float4*)&Bs[k][nq] = *(const float4*)(Bw + (size_t)(k0 + k) * Hh_ + nb + nq);
        }
        __syncthreads();
        #pragma unroll
        for (int kk = 0; kk < 16; kk++) {
            float4 a0 = *(const float4*)&As[kk][ty * 4];
            float4 a1 = *(const float4*)&As[kk][64 + ty * 4];
            float4 b0 = *(const float4*)&Bs[kk][tx * 4];
            float4 b1 = *(const float4*)&Bs[kk][64 + tx * 4];
            float av[8] = {a0.x, a0.y, a0.z, a0.w, a1.x, a1.y, a1.z, a1.w};
            float bv[8] = {b0.x, b0.y, b0.z, b0.w, b1.x, b1.y, b1.z, b1.w};
            #pragma unroll
            for (int i = 0; i < 8; i++)
                #pragma unroll
                for (int j = 0; j < 8; j++) acc[i][j] = fmaf(av[i], bv[j], acc[i][j]);
        }
    }
    #pragma unroll
    for (int i = 0; i < 8; i++) {
        int m = mb + ((i < 4) ? ty * 4 + i : 64 + ty * 4 + i - 4);
        if (m >= V_) continue;
        float inv = g_vinv[m];
        #pragma unroll
        for (int j = 0; j < 8; j++) {
            int n = nb + ((j < 4) ? tx * 4 + j : 64 + tx * 4 + j - 4);
            g_h[(size_t)m * Hh_ + n] = acc[i][j] * inv;
        }
    }
}

// column sums / sumsq of g_h over V rows
__global__ void bnstats_kernel() {
    int c = blockIdx.x * 256 + threadIdx.x;         // grid.x = 3 -> 768 cols
    int chunk = blockIdx.y;                          // 32 chunks
    const int RC = (V_ + 31) / 32;
    int r0 = chunk * RC, r1 = min(V_, r0 + RC);
    float s = 0.f, sq = 0.f;
    for (int r = r0; r < r1; r++) {
        float x = g_h[(size_t)r * Hh_ + c];
        s += x; sq += x * x;
    }
    atomicAdd(&g_colsum[c], s);
    atomicAdd(&g_colsq[c], sq);
}

__global__ void bnfinal_kernel(const float* __restrict__ gamma, const float* __restrict__ beta) {
    int c = threadIdx.x;
    if (c < Hh_) {
        float mean = g_colsum[c] / (float)V_;
        float var = g_colsq[c] / (float)V_ - mean * mean;
        float sc = gamma[c] / sqrtf(var + BN_EPS);
        g_scale[c] = sc;
        g_shift[c] = beta[c] - mean * sc;
    }
}

// GEMM2: g_proto[m,n] = relu(bn(g_h[m,:])) @ W2[:,n] + b2[n]   M=V K=Hh N=D
__global__ __launch_bounds__(256, 2) void gemm2_kernel(const float* __restrict__ Bw,
                                                       const float* __restrict__ b2) {
    __shared__ float As[16][132];
    __shared__ float Bs[16][132];
    const int mb = blockIdx.y * 128, nb = blockIdx.x * 128;
    const int t = threadIdx.x, tx = t & 15, ty = t >> 4;
    float acc[8][8];
    #pragma unroll
    for (int i = 0; i < 8; i++)
        #pragma unroll
        for (int j = 0; j < 8; j++) acc[i][j] = 0.f;

    for (int k0 = 0; k0 < Hh_; k0 += 16) {
        __syncthreads();
        #pragma unroll
        for (int p = 0; p < 2; p++) {
            int m = p * 64 + (t >> 2);
            int kq = (t & 3) * 4;
            int gm = mb + m;
            float4 v = (gm < V_) ? *(const float4*)(g_h + (size_t)gm * Hh_ + k0 + kq)
                                 : make_float4(0.f, 0.f, 0.f, 0.f);
            int kb = k0 + kq;
            v.x = fmaxf(fmaf(v.x, g_scale[kb + 0], g_shift[kb + 0]), 0.f);
            v.y = fmaxf(fmaf(v.y, g_scale[kb + 1], g_shift[kb + 1]), 0.f);
            v.z = fmaxf(fmaf(v.z, g_scale[kb + 2], g_shift[kb + 2]), 0.f);
            v.w = fmaxf(fmaf(v.w, g_scale[kb + 3], g_shift[kb + 3]), 0.f);
            As[kq + 0][m] = v.x; As[kq + 1][m] = v.y; As[kq + 2][m] = v.z; As[kq + 3][m] = v.w;
        }
        #pragma unroll
        for (int p = 0; p < 2; p++) {
            int idx = p * 256 + t;
            int k = idx >> 5, nq = (idx & 31) * 4;
            *(float4*)&Bs[k][nq] = *(const float4*)(Bw + (size_t)(k0 + k) * D_ + nb + nq);
        }
        __syncthreads();
        #pragma unroll
        for (int kk = 0; kk < 16; kk++) {
            float4 a0 = *(const float4*)&As[kk][ty * 4];
            float4 a1 = *(const float4*)&As[kk][64 + ty * 4];
            float4 b0 = *(const float4*)&Bs[kk][tx * 4];
            float4 b1 = *(const float4*)&Bs[kk][64 + tx * 4];
            float av[8] = {a0.x, a0.y, a0.z, a0.w, a1.x, a1.y, a1.z, a1.w};
            float bv[8] = {b0.x, b0.y, b0.z, b0.w, b1.x, b1.y, b1.z, b1.w};
            #pragma unroll
            for (int i = 0; i < 8; i++)
                #pragma unroll
                for (int j = 0; j < 8; j++) acc[i][j] = fmaf(av[i], bv[j], acc[i][j]);
        }
    }
    #pragma unroll
    for (int i = 0; i < 8; i++) {
        int m = mb + ((i < 4) ? ty * 4 + i : 64 + ty * 4 + i - 4);
        if (m >= V_) continue;
        #pragma unroll
        for (int j = 0; j < 8; j++) {
            int n = nb + ((j < 4) ? tx * 4 + j : 64 + tx * 4 + j - 4);
            g_proto[(size_t)m * D_ + n] = acc[i][j] + b2[n];
        }
    }
}

// row-normalize prototypes in place (V rows of D)
__global__ void pnorm_kernel() {
    int r = blockIdx.x;
    float* row = g_proto + (size_t)r * D_;
    int t = threadIdx.x;
    float x0 = row[t], x1 = row[t + 256], x2 = row[t + 512];
    float s = blockSumAll(x0 * x0 + x1 * x1 + x2 * x2);
    float inv = 1.0f / fmaxf(sqrtf(s), 1e-12f);
    row[t] = x0 * inv; row[t + 256] = x1 * inv; row[t + 512] = x2 * inv;
}

// logits GEMM fused with max over N:
// out[b,v] = max_n  g_pt[b,n,:] . g_proto[v,:]
__global__ __launch_bounds__(256, 2) void k5_kernel(float* __restrict__ out) {
    __shared__ float As[16][132];      // pt tile, k-major
    __shared__ float Bs[16][132];      // proto tile, k-major
    __shared__ float red[16][128];
    __shared__ float rmax[128];
    const int b = blockIdx.y;
    const int vb = blockIdx.x * 128;
    const int t = threadIdx.x, tx = t & 15, ty = t >> 4;
    if (t < 128) rmax[t] = -1e30f;
    const float* Ab = g_pt + (size_t)b * N_ * D_;

    for (int n0 = 0; n0 < N_; n0 += 128) {
        float acc[8][8];
        #pragma unroll
        for (int i = 0; i < 8; i++)
            #pragma unroll
            for (int j = 0; j < 8; j++) acc[i][j] = 0.f;

        for (int k0 = 0; k0 < D_; k0 += 16) {
            __syncthreads();
            #pragma unroll
            for (int p = 0; p < 2; p++) {
                int m = p * 64 + (t >> 2);
                int kq = (t & 3) * 4;
                float4 v = *(const float4*)(Ab + (size_t)(n0 + m) * D_ + k0 + kq);
                As[kq + 0][m] = v.x; As[kq + 1][m] = v.y; As[kq + 2][m] = v.z; As[kq + 3][m] = v.w;
            }
            #pragma unroll
            for (int p = 0; p < 2; p++) {
                int m = p * 64 + (t >> 2);
                int kq = (t & 3) * 4;
                int gv = vb + m;
                float4 v = (gv < V_) ? *(const float4*)(g_proto + (size_t)gv * D_ + k0 + kq)
                                     : make_float4(0.f, 0.f, 0.f, 0.f);
                Bs[kq + 0][m] = v.x; Bs[kq + 1][m] = v.y; Bs[kq + 2][m] = v.z; Bs[kq + 3][m] = v.w;
            }
            __syncthreads();
            #pragma unroll
            for (int kk = 0; kk < 16; kk++) {
                float4 a0 = *(const float4*)&As[kk][ty * 4];
                float4 a1 = *(const float4*)&As[kk][64 + ty * 4];
                float4 b0 = *(const float4*)&Bs[kk][tx * 4];
                float4 b1 = *(const float4*)&Bs[kk][64 + tx * 4];
                float av[8] = {a0.x, a0.y, a0.z, a0.w, a1.x, a1.y, a1.z, a1.w};
                float bv[8] = {b0.x, b0.y, b0.z, b0.w, b1.x, b1.y, b1.z, b1.w};
                #pragma unroll
                for (int i = 0; i < 8; i++)
                    #pragma unroll
                    for (int j = 0; j < 8; j++) acc[i][j] = fmaf(av[i], bv[j], acc[i][j]);
            }
        }
        // per-thread max over its 8 n's, then cross-thread reduce per v
        float vmax[8];
        #pragma unroll
        for (int j = 0; j < 8; j++) {
            float m = acc[0][j];
            #pragma unroll
            for (int i = 1; i < 8; i++) m = fmaxf(m, acc[i][j]);
            vmax[j] = m;
        }
        __syncthreads();
        #pragma unroll
        for (int j = 0; j < 8; j++) {
            int v = (j < 4) ? tx * 4 + j : 64 + tx * 4 + j - 4;
            red[ty][v] = vmax[j];
        }
        __syncthreads();
        if (t < 128) {
            float m = rmax[t];
            #pragma unroll
            for (int r = 0; r < 16; r++) m = fmaxf(m, red[r][t]);
            rmax[t] = m;
        }
    }
    __syncthreads();
    if (t < 128) {
        int gv = vb + t;
        if (gv < V_) out[(size_t)b * V_ + gv] = rmax[t];
    }
}

// in-place softmax over V per batch row, with 1/T scaling
__global__ void softmax_kernel(float* __restrict__ out) {
    int b = blockIdx.x;
    float* row = out + (size_t)b * V_;
    __shared__ float sb[33];
    int t = threadIdx.x, lane = t & 31, w = t >> 5;

    float m = -1e30f;
    for (int v = t; v < V_; v += 1024) m = fmaxf(m, row[v]);
    #pragma unroll
    for (int o = 16; o; o >>= 1) m = fmaxf(m, __shfl_xor_sync(0xffffffffu, m, o));
    if (lane == 0) sb[w] = m;
    __syncthreads();
    if (t == 0) {
        float mm = -1e30f;
        for (int i = 0; i < 32; i++) mm = fmaxf(mm, sb[i]);
        sb[32] = mm;
    }
    __syncthreads();
    float M = sb[32];

    float s = 0.f;
    for (int v = t; v < V_; v += 1024) s += expf((row[v] - M) * INV_T);
    s = warpSum(s);
    __syncthreads();
    if (lane == 0) sb[w] = s;
    __syncthreads();
    if (t == 0) {
        float ss = 0.f;
        for (int i = 0; i < 32; i++) ss += sb[i];
        sb[32] = ss;
    }
    __syncthreads();
    float inv = 1.0f / sb[32];
    for (int v = t; v < V_; v += 1024) row[v] = expf((row[v] - M) * INV_T) * inv;
}

// ---------------- launch ----------------
extern "C" void kernel_launch(void* const* d_in, const int* in_sizes, int n_in,
                              void* d_out, int out_size) {
    const float* patch = (const float*)d_in[0];
    const float* vocab = (const float*)d_in[1];
    const float* W1    = (const float*)d_in[2];
    const float* gamma = (const float*)d_in[3];
    const float* beta  = (const float*)d_in[4];
    const float* W2    = (const float*)d_in[5];
    const float* b2    = (const float*)d_in[6];
    float* out = (float*)d_out;

    const int VT = (V_ + 127) / 128;   // 235

    vnorm_kernel<<<V_, 256>>>(vocab);
    ptnorm_kernel<<<B_ * N_, 256>>>(patch);
    zero_stats_kernel<<<1, Hh_>>>();
    gemm1_kernel<<<dim3(Hh_ / 128, VT), 256>>>(vocab, W1);
    bnstats_kernel<<<dim3(3, 32), 256>>>();
    bnfinal_kernel<<<1, Hh_>>>(gamma, beta);
    gemm2_kernel<<<dim3(D_ / 128, VT), 256>>>(W2, b2);
    pnorm_kernel<<<V_, 256>>>();
    k5_kernel<<<dim3(VT, B_), 256>>>(out);
    softmax_kernel<<<B_, 1024>>>(out);
}

// round 4
// speedup vs baseline: 1.9884x; 1.9884x over previous
#include <cuda_runtime.h>
#include <cuda_bf16.h>
#include <math.h>
#include <stdint.h>

#define B_  8
#define N_  1024
#define D_  768
#define V_  30000
#define C_  512
#define Hh_ 768
#define INV_T 5.0f
#define BN_EPS 1e-5f

// ---------------- scratch (static device globals; no allocs allowed) ----------------
__device__ float g_vinv[V_];
__device__ float g_h[(size_t)V_ * Hh_];
__device__ float g_proto[(size_t)V_ * D_];
__device__ float g_colsum[Hh_], g_colsq[Hh_];
__device__ float g_scale[Hh_], g_shift[Hh_];
// split-bf16 operands for the tensor-core logits GEMM
__device__ __nv_bfloat16 g_proto_hi[(size_t)V_ * D_];
__device__ __nv_bfloat16 g_proto_lo[(size_t)V_ * D_];
__device__ __nv_bfloat16 g_pt_hi[(size_t)B_ * N_ * D_];
__device__ __nv_bfloat16 g_pt_lo[(size_t)B_ * N_ * D_];

// ---------------- helpers ----------------
__device__ __forceinline__ uint32_t smem_u32(const void* p) {
    uint32_t a;
    asm("{ .reg .u64 t; cvta.to.shared.u64 t, %1; cvt.u32.u64 %0, t; }" : "=r"(a) : "l"(p));
    return a;
}
__device__ __forceinline__ float warpSum(float v) {
    #pragma unroll
    for (int o = 16; o; o >>= 1) v += __shfl_xor_sync(0xffffffffu, v, o);
    return v;
}
__device__ float blockSumAll(float v) {
    __shared__ float sb[33];
    int lane = threadIdx.x & 31, w = threadIdx.x >> 5;
    v = warpSum(v);
    if (lane == 0) sb[w] = v;
    __syncthreads();
    if (threadIdx.x == 0) {
        float s = 0.f;
        int nw = (blockDim.x + 31) >> 5;
        for (int i = 0; i < nw; i++) s += sb[i];
        sb[32] = s;
    }
    __syncthreads();
    return sb[32];
}
__device__ __forceinline__ void split_bf16(float x, __nv_bfloat16& hi, __nv_bfloat16& lo) {
    hi = __float2bfloat16_rn(x);
    lo = __float2bfloat16_rn(x - __bfloat162float(hi));
}

__device__ __forceinline__ void ldsm_x4(uint32_t addr, uint32_t& r0, uint32_t& r1,
                                        uint32_t& r2, uint32_t& r3) {
    asm volatile("ldmatrix.sync.aligned.m8n8.x4.shared.b16 {%0,%1,%2,%3}, [%4];"
                 : "=r"(r0), "=r"(r1), "=r"(r2), "=r"(r3) : "r"(addr));
}
__device__ __forceinline__ void mma_bf16(float* d, const uint32_t* a, uint32_t b0, uint32_t b1) {
    asm volatile(
        "mma.sync.aligned.m16n8k16.row.col.f32.bf16.bf16.f32 "
        "{%0,%1,%2,%3}, {%4,%5,%6,%7}, {%8,%9}, {%0,%1,%2,%3};"
        : "+f"(d[0]), "+f"(d[1]), "+f"(d[2]), "+f"(d[3])
        : "r"(a[0]), "r"(a[1]), "r"(a[2]), "r"(a[3]), "r"(b0), "r"(b1));
}

// ---------------- stage kernels ----------------
__global__ void vnorm_kernel(const float* __restrict__ vocab) {
    int r = blockIdx.x;
    const float* row = vocab + (size_t)r * C_;
    float s = 0.f;
    for (int c = threadIdx.x; c < C_; c += 256) { float x = row[c]; s += x * x; }
    s = blockSumAll(s);
    if (threadIdx.x == 0) g_vinv[r] = 1.0f / fmaxf(sqrtf(s), 1e-12f);
}

// normalize patch tokens -> split bf16 hi/lo
__global__ void ptnorm_kernel(const float* __restrict__ pt) {
    int r = blockIdx.x;
    const float* row = pt + (size_t)r * D_;
    int t = threadIdx.x;
    float x0 = row[t], x1 = row[t + 256], x2 = row[t + 512];
    float s = blockSumAll(x0 * x0 + x1 * x1 + x2 * x2);
    float inv = 1.0f / fmaxf(sqrtf(s), 1e-12f);
    size_t o = (size_t)r * D_;
    __nv_bfloat16 h, l;
    split_bf16(x0 * inv, h, l); g_pt_hi[o + t] = h;       g_pt_lo[o + t] = l;
    split_bf16(x1 * inv, h, l); g_pt_hi[o + t + 256] = h; g_pt_lo[o + t + 256] = l;
    split_bf16(x2 * inv, h, l); g_pt_hi[o + t + 512] = h; g_pt_lo[o + t + 512] = l;
}

__global__ void zero_stats_kernel() {
    int t = threadIdx.x;
    if (t < Hh_) { g_colsum[t] = 0.f; g_colsq[t] = 0.f; }
}

// GEMM1: g_h = (vocab * vinv) @ W1
__global__ __launch_bounds__(256, 2) void gemm1_kernel(const float* __restrict__ A,
                                                       const float* __restrict__ Bw) {
    __shared__ float As[16][132];
    __shared__ float Bs[16][132];
    const int mb = blockIdx.y * 128, nb = blockIdx.x * 128;
    const int t = threadIdx.x, tx = t & 15, ty = t >> 4;
    float acc[8][8];
    #pragma unroll
    for (int i = 0; i < 8; i++)
        #pragma unroll
        for (int j = 0; j < 8; j++) acc[i][j] = 0.f;

    for (int k0 = 0; k0 < C_; k0 += 16) {
        __syncthreads();
        #pragma unroll
        for (int p = 0; p < 2; p++) {
            int m = p * 64 + (t >> 2);
            int kq = (t & 3) * 4;
            int gm = mb + m;
            float4 v = (gm < V_) ? *(const float4*)(A + (size_t)gm * C_ + k0 + kq)
                                 : make_float4(0.f, 0.f, 0.f, 0.f);
            As[kq + 0][m] = v.x; As[kq + 1][m] = v.y; As[kq + 2][m] = v.z; As[kq + 3][m] = v.w;
        }
        #pragma unroll
        for (int p = 0; p < 2; p++) {
            int idx = p * 256 + t;
            int k = idx >> 5, nq = (idx & 31) * 4;
            *(float4*)&Bs[k][nq] = *(const float4*)(Bw + (size_t)(k0 + k) * Hh_ + nb + nq);
        }
        __syncthreads();
        #pragma unroll
        for (int kk = 0; kk < 16; kk++) {
            float4 a0 = *(const float4*)&As[kk][ty * 4];
            float4 a1 = *(const float4*)&As[kk][64 + ty * 4];
            float4 b0 = *(const float4*)&Bs[kk][tx * 4];
            float4 b1 = *(const float4*)&Bs[kk][64 + tx * 4];
            float av[8] = {a0.x, a0.y, a0.z, a0.w, a1.x, a1.y, a1.z, a1.w};
            float bv[8] = {b0.x, b0.y, b0.z, b0.w, b1.x, b1.y, b1.z, b1.w};
            #pragma unroll
            for (int i = 0; i < 8; i++)
                #pragma unroll
                for (int j = 0; j < 8; j++) acc[i][j] = fmaf(av[i], bv[j], acc[i][j]);
        }
    }
    #pragma unroll
    for (int i = 0; i < 8; i++) {
        int m = mb + ((i < 4) ? ty * 4 + i : 64 + ty * 4 + i - 4);
        if (m >= V_) continue;
        float inv = g_vinv[m];
        #pragma unroll
        for (int j = 0; j < 8; j++) {
            int n = nb + ((j < 4) ? tx * 4 + j : 64 + tx * 4 + j - 4);
            g_h[(size_t)m * Hh_ + n] = acc[i][j] * inv;
        }
    }
}

__global__ void bnstats_kernel() {
    int c = blockIdx.x * 256 + threadIdx.x;
    int chunk = blockIdx.y;
    const int RC = (V_ + 31) / 32;
    int r0 = chunk * RC, r1 = min(V_, r0 + RC);
    float s = 0.f, sq = 0.f;
    for (int r = r0; r < r1; r++) {
        float x = g_h[(size_t)r * Hh_ + c];
        s += x; sq += x * x;
    }
    atomicAdd(&g_colsum[c], s);
    atomicAdd(&g_colsq[c], sq);
}

__global__ void bnfinal_kernel(const float* __restrict__ gamma, const float* __restrict__ beta) {
    int c = threadIdx.x;
    if (c < Hh_) {
        float mean = g_colsum[c] / (float)V_;
        float var = g_colsq[c] / (float)V_ - mean * mean;
        float sc = gamma[c] / sqrtf(var + BN_EPS);
        g_scale[c] = sc;
        g_shift[c] = beta[c] - mean * sc;
    }
}

// GEMM2: g_proto = relu(bn(g_h)) @ W2 + b2
__global__ __launch_bounds__(256, 2) void gemm2_kernel(const float* __restrict__ Bw,
                                                       const float* __restrict__ b2) {
    __shared__ float As[16][132];
    __shared__ float Bs[16][132];
    const int mb = blockIdx.y * 128, nb = blockIdx.x * 128;
    const int t = threadIdx.x, tx = t & 15, ty = t >> 4;
    float acc[8][8];
    #pragma unroll
    for (int i = 0; i < 8; i++)
        #pragma unroll
        for (int j = 0; j < 8; j++) acc[i][j] = 0.f;

    for (int k0 = 0; k0 < Hh_; k0 += 16) {
        __syncthreads();
        #pragma unroll
        for (int p = 0; p < 2; p++) {
            int m = p * 64 + (t >> 2);
            int kq = (t & 3) * 4;
            int gm = mb + m;
            float4 v = (gm < V_) ? *(const float4*)(g_h + (size_t)gm * Hh_ + k0 + kq)
                                 : make_float4(0.f, 0.f, 0.f, 0.f);
            int kb = k0 + kq;
            v.x = fmaxf(fmaf(v.x, g_scale[kb + 0], g_shift[kb + 0]), 0.f);
            v.y = fmaxf(fmaf(v.y, g_scale[kb + 1], g_shift[kb + 1]), 0.f);
            v.z = fmaxf(fmaf(v.z, g_scale[kb + 2], g_shift[kb + 2]), 0.f);
            v.w = fmaxf(fmaf(v.w, g_scale[kb + 3], g_shift[kb + 3]), 0.f);
            As[kq + 0][m] = v.x; As[kq + 1][m] = v.y; As[kq + 2][m] = v.z; As[kq + 3][m] = v.w;
        }
        #pragma unroll
        for (int p = 0; p < 2; p++) {
            int idx = p * 256 + t;
            int k = idx >> 5, nq = (idx & 31) * 4;
            *(float4*)&Bs[k][nq] = *(const float4*)(Bw + (size_t)(k0 + k) * D_ + nb + nq);
        }
        __syncthreads();
        #pragma unroll
        for (int kk = 0; kk < 16; kk++) {
            float4 a0 = *(const float4*)&As[kk][ty * 4];
            float4 a1 = *(const float4*)&As[kk][64 + ty * 4];
            float4 b0 = *(const float4*)&Bs[kk][tx * 4];
            float4 b1 = *(const float4*)&Bs[kk][64 + tx * 4];
            float av[8] = {a0.x, a0.y, a0.z, a0.w, a1.x, a1.y, a1.z, a1.w};
            float bv[8] = {b0.x, b0.y, b0.z, b0.w, b1.x, b1.y, b1.z, b1.w};
            #pragma unroll
            for (int i = 0; i < 8; i++)
                #pragma unroll
                for (int j = 0; j < 8; j++) acc[i][j] = fmaf(av[i], bv[j], acc[i][j]);
        }
    }
    #pragma unroll
    for (int i = 0; i < 8; i++) {
        int m = mb + ((i < 4) ? ty * 4 + i : 64 + ty * 4 + i - 4);
        if (m >= V_) continue;
        #pragma unroll
        for (int j = 0; j < 8; j++) {
            int n = nb + ((j < 4) ? tx * 4 + j : 64 + tx * 4 + j - 4);
            g_proto[(size_t)m * D_ + n] = acc[i][j] + b2[n];
        }
    }
}

// row-normalize prototypes; emit split bf16 hi/lo
__global__ void pnorm_kernel() {
    int r = blockIdx.x;
    float* row = g_proto + (size_t)r * D_;
    int t = threadIdx.x;
    float x0 = row[t], x1 = row[t + 256], x2 = row[t + 512];
    float s = blockSumAll(x0 * x0 + x1 * x1 + x2 * x2);
    float inv = 1.0f / fmaxf(sqrtf(s), 1e-12f);
    size_t o = (size_t)r * D_;
    __nv_bfloat16 h, l;
    split_bf16(x0 * inv, h, l); g_proto_hi[o + t] = h;       g_proto_lo[o + t] = l;
    split_bf16(x1 * inv, h, l); g_proto_hi[o + t + 256] = h; g_proto_lo[o + t + 256] = l;
    split_bf16(x2 * inv, h, l); g_proto_hi[o + t + 512] = h; g_proto_lo[o + t + 512] = l;
}

// ---------------- HMMA logits GEMM fused with max over tokens ----------------
// out[b, v] = max_n pt[b,n,:] . proto[v,:]
// Block: 128 v x 128 tokens; warps 4(m) x 2(n); warp tile 32v x 64tok.
// 3 split passes x 12 K-chunks of 64. Tiles in smem with 128B XOR swizzle.

// stage one 128x64 bf16 tile (row-major, 128B rows, swizzled) into smem
__device__ __forceinline__ void load_tile_k5(char* dst, const __nv_bfloat16* __restrict__ src,
                                             int rowbase, int kb, bool guard) {
    const int t = threadIdx.x;
    #pragma unroll
    for (int s = 0; s < 4; s++) {
        int idx = t + s * 256;
        int row = idx >> 3, kq = idx & 7;
        int gr = rowbase + row;
        uint4 v = make_uint4(0u, 0u, 0u, 0u);
        if (!guard || gr < V_) v = *(const uint4*)(src + (size_t)gr * D_ + kb + kq * 8);
        uint32_t off = (uint32_t)(row << 7) + (uint32_t)(kq << 4);
        off ^= (uint32_t)(row & 7) << 4;
        *(uint4*)(dst + off) = v;
    }
}

__global__ __launch_bounds__(256, 2) void k5_mma_kernel(float* __restrict__ out) {
    __shared__ alignas(128) __nv_bfloat16 As[128 * 64];
    __shared__ alignas(128) __nv_bfloat16 Bs[128 * 64];
    __shared__ float redbuf[2][128];
    __shared__ float rmax[128];

    const int t = threadIdx.x;
    const int lane = t & 31, wid = t >> 5;
    const int wm = wid >> 1, wn = wid & 1;
    const int b = blockIdx.x;                 // batch fastest -> batches share proto tiles in L2
    const int vb = blockIdx.y * 128;
    const bool guard = (vb + 128 > V_);

    if (t < 128) rmax[t] = -1e30f;

    const uint32_t sA = smem_u32(As), sB = smem_u32(Bs);

    // ldmatrix lane addressing (constant parts)
    const int rowA = wm * 32 + (lane & 15);                 // + mf*16
    const uint32_t swA = (uint32_t)(rowA & 7) << 4;
    const uint32_t kselA = (uint32_t)(lane >> 4) << 4;      // + ks*32
    const int rowBn = wn * 64 + ((lane >> 4) << 3) + (lane & 7);  // + nf2*16
    const uint32_t swB = (uint32_t)(lane & 7) << 4;
    const uint32_t kselB = (uint32_t)((lane >> 3) & 1) << 4;

    for (int tt = 0; tt < 8; tt++) {
        float acc[2][8][4];
        #pragma unroll
        for (int mf = 0; mf < 2; mf++)
            #pragma unroll
            for (int nf = 0; nf < 8; nf++)
                #pragma unroll
                for (int e = 0; e < 4; e++) acc[mf][nf][e] = 0.f;

        const int tokbase = b * N_ + tt * 128;

        #pragma unroll 1
        for (int pass = 0; pass < 3; pass++) {
            const __nv_bfloat16* Asrc = (pass < 2) ? g_proto_hi : g_proto_lo;
            const __nv_bfloat16* Bsrc = (pass == 1) ? g_pt_lo : g_pt_hi;
            #pragma unroll 1
            for (int chunk = 0; chunk < 12; chunk++) {
                const int kb = chunk * 64;
                __syncthreads();
                load_tile_k5((char*)As, Asrc, vb, kb, guard);
                load_tile_k5((char*)Bs, Bsrc, tokbase, kb, false);
                __syncthreads();

                #pragma unroll
                for (int ks = 0; ks < 4; ks++) {
                    // A fragments: 2 x m16k16
                    uint32_t a[2][4];
                    #pragma unroll
                    for (int mf = 0; mf < 2; mf++) {
                        uint32_t addr = sA + (uint32_t)((rowA + mf * 16) << 7)
                                      + (((uint32_t)(ks * 32) + kselA) ^ swA);
                        ldsm_x4(addr, a[mf][0], a[mf][1], a[mf][2], a[mf][3]);
                    }
                    // B fragments: 4 x (two n8k16 frags each)
                    uint32_t bf[4][4];
                    #pragma unroll
                    for (int nf2 = 0; nf2 < 4; nf2++) {
                        uint32_t addr = sB + (uint32_t)((rowBn + nf2 * 16) << 7)
                                      + (((uint32_t)(ks * 32) + kselB) ^ swB);
                        ldsm_x4(addr, bf[nf2][0], bf[nf2][1], bf[nf2][2], bf[nf2][3]);
                    }
                    #pragma unroll
                    for (int mf = 0; mf < 2; mf++)
                        #pragma unroll
                        for (int nf = 0; nf < 8; nf++)
                            mma_bf16(acc[mf][nf], a[mf],
                                     bf[nf >> 1][(nf & 1) * 2], bf[nf >> 1][(nf & 1) * 2 + 1]);
                }
            }
        }

        // ---- fused max over the 128 tokens of this tile ----
        float m4[2][2];
        #pragma unroll
        for (int mf = 0; mf < 2; mf++)
            #pragma unroll
            for (int h = 0; h < 2; h++) {
                float m = -1e30f;
                #pragma unroll
                for (int nf = 0; nf < 8; nf++)
                    m = fmaxf(m, fmaxf(acc[mf][nf][h * 2], acc[mf][nf][h * 2 + 1]));
                m4[mf][h] = m;
            }
        #pragma unroll
        for (int mf = 0; mf < 2; mf++)
            #pragma unroll
            for (int h = 0; h < 2; h++) {
                float m = m4[mf][h];
                m = fmaxf(m, __shfl_xor_sync(0xffffffffu, m, 1));
                m = fmaxf(m, __shfl_xor_sync(0xffffffffu, m, 2));
                m4[mf][h] = m;
            }
        __syncthreads();
        if ((lane & 3) == 0) {
            #pragma unroll
            for (int mf = 0; mf < 2; mf++)
                #pragma unroll
                for (int h = 0; h < 2; h++)
                    redbuf[wn][wm * 32 + mf * 16 + (lane >> 2) + h * 8] = m4[mf][h];
        }
        __syncthreads();
        if (t < 128) rmax[t] = fmaxf(rmax[t], fmaxf(redbuf[0][t], redbuf[1][t]));
    }

    if (t < 128) {
        int gv = vb + t;
        if (gv < V_) out[(size_t)b * V_ + gv] = rmax[t];
    }
}

// in-place softmax over V per batch row
__global__ void softmax_kernel(float* __restrict__ out) {
    int b = blockIdx.x;
    float* row = out + (size_t)b * V_;
    __shared__ float sb[33];
    int t = threadIdx.x, lane = t & 31, w = t >> 5;

    float m = -1e30f;
    for (int v = t; v < V_; v += 1024) m = fmaxf(m, row[v]);
    #pragma unroll
    for (int o = 16; o; o >>= 1) m = fmaxf(m, __shfl_xor_sync(0xffffffffu, m, o));
    if (lane == 0) sb[w] = m;
    __syncthreads();
    if (t == 0) {
        float mm = -1e30f;
        for (int i = 0; i < 32; i++) mm = fmaxf(mm, sb[i]);
        sb[32] = mm;
    }
    __syncthreads();
    float M = sb[32];

    float s = 0.f;
    for (int v = t; v < V_; v += 1024) s += expf((row[v] - M) * INV_T);
    s = warpSum(s);
    __syncthreads();
    if (lane == 0) sb[w] = s;
    __syncthreads();
    if (t == 0) {
        float ss = 0.f;
        for (int i = 0; i < 32; i++) ss += sb[i];
        sb[32] = ss;
    }
    __syncthreads();
    float inv = 1.0f / sb[32];
    for (int v = t; v < V_; v += 1024) row[v] = expf((row[v] - M) * INV_T) * inv;
}

// ---------------- launch ----------------
extern "C" void kernel_launch(void* const* d_in, const int* in_sizes, int n_in,
                              void* d_out, int out_size) {
    const float* patch = (const float*)d_in[0];
    const float* vocab = (const float*)d_in[1];
    const float* W1    = (const float*)d_in[2];
    const float* gamma = (const float*)d_in[3];
    const float* beta  = (const float*)d_in[4];
    const float* W2    = (const float*)d_in[5];
    const float* b2    = (const float*)d_in[6];
    float* out = (float*)d_out;

    const int VT = (V_ + 127) / 128;   // 235

    vnorm_kernel<<<V_, 256>>>(vocab);
    ptnorm_kernel<<<B_ * N_, 256>>>(patch);
    zero_stats_kernel<<<1, Hh_>>>();
    gemm1_kernel<<<dim3(Hh_ / 128, VT), 256>>>(vocab, W1);
    bnstats_kernel<<<dim3(3, 32), 256>>>();
    bnfinal_kernel<<<1, Hh_>>>(gamma, beta);
    gemm2_kernel<<<dim3(D_ / 128, VT), 256>>>(W2, b2);
    pnorm_kernel<<<V_, 256>>>();
    k5_mma_kernel<<<dim3(B_, VT), 256>>>(out);
    softmax_kernel<<<B_, 1024>>>(out);
}

// round 10
// speedup vs baseline: 3.0637x; 1.5407x over previous
#include <cuda_runtime.h>
#include <cuda_bf16.h>
#include <math.h>
#include <stdint.h>

#define B_  8
#define N_  1024
#define D_  768
#define V_  30000
#define C_  512
#define Hh_ 768
#define INV_T 5.0f
#define BN_EPS 1e-5f

// ---------------- scratch (static device globals; no allocs allowed) ----------------
__device__ float g_h[(size_t)V_ * Hh_];
__device__ float g_proto[(size_t)V_ * D_];
__device__ float g_colsum[Hh_], g_colsq[Hh_];
__device__ float g_scale[Hh_], g_shift[Hh_];
// split operands
__device__ __nv_bfloat16 g_vn_hi[(size_t)V_ * C_], g_vn_lo[(size_t)V_ * C_];
__device__ __nv_bfloat16 g_w1t_hi[(size_t)Hh_ * C_], g_w1t_lo[(size_t)Hh_ * C_];
__device__ __nv_bfloat16 g_hb_hi[(size_t)V_ * Hh_], g_hb_lo[(size_t)V_ * Hh_];
__device__ __nv_bfloat16 g_w2t_hi[(size_t)D_ * Hh_], g_w2t_lo[(size_t)D_ * Hh_];
__device__ __nv_bfloat16 g_proto_hi[(size_t)V_ * D_];
__device__ __nv_bfloat16 g_proto_lo[(size_t)V_ * D_];
__device__ __nv_bfloat16 g_pt_hi[(size_t)B_ * N_ * D_];

// ---------------- helpers ----------------
__device__ __forceinline__ uint32_t smem_u32(const void* p) {
    uint32_t a;
    asm("{ .reg .u64 t; cvta.to.shared.u64 t, %1; cvt.u32.u64 %0, t; }" : "=r"(a) : "l"(p));
    return a;
}
__device__ __forceinline__ float warpSum(float v) {
    #pragma unroll
    for (int o = 16; o; o >>= 1) v += __shfl_xor_sync(0xffffffffu, v, o);
    return v;
}
__device__ float blockSumAll(float v) {
    __shared__ float sb[33];
    int lane = threadIdx.x & 31, w = threadIdx.x >> 5;
    v = warpSum(v);
    if (lane == 0) sb[w] = v;
    __syncthreads();
    if (threadIdx.x == 0) {
        float s = 0.f;
        int nw = (blockDim.x + 31) >> 5;
        for (int i = 0; i < nw; i++) s += sb[i];
        sb[32] = s;
    }
    __syncthreads();
    return sb[32];
}
__device__ __forceinline__ void split_bf16(float x, __nv_bfloat16& hi, __nv_bfloat16& lo) {
    hi = __float2bfloat16_rn(x);
    lo = __float2bfloat16_rn(x - __bfloat162float(hi));
}
__device__ __forceinline__ void ldsm_x4(uint32_t addr, uint32_t& r0, uint32_t& r1,
                                        uint32_t& r2, uint32_t& r3) {
    asm volatile("ldmatrix.sync.aligned.m8n8.x4.shared.b16 {%0,%1,%2,%3}, [%4];"
                 : "=r"(r0), "=r"(r1), "=r"(r2), "=r"(r3) : "r"(addr));
}
__device__ __forceinline__ void mma_bf16(float* d, const uint32_t* a, uint32_t b0, uint32_t b1) {
    asm volatile(
        "mma.sync.aligned.m16n8k16.row.col.f32.bf16.bf16.f32 "
        "{%0,%1,%2,%3}, {%4,%5,%6,%7}, {%8,%9}, {%0,%1,%2,%3};"
        : "+f"(d[0]), "+f"(d[1]), "+f"(d[2]), "+f"(d[3])
        : "r"(a[0]), "r"(a[1]), "r"(a[2]), "r"(a[3]), "r"(b0), "r"(b1));
}
// stage one 128x64 bf16 tile (row-major, swizzled) into smem. ldk = source row stride
__device__ __forceinline__ void load_tile(char* dst, const __nv_bfloat16* __restrict__ src,
                                          int rowbase, int kb, int ldk, int rowmax) {
    const int t = threadIdx.x;
    #pragma unroll
    for (int s = 0; s < 4; s++) {
        int idx = t + s * 256;
        int row = idx >> 3, kq = idx & 7;
        int gr = rowbase + row;
        uint4 v = make_uint4(0u, 0u, 0u, 0u);
        if (gr < rowmax) v = *(const uint4*)(src + (size_t)gr * ldk + kb + kq * 8);
        uint32_t off = (uint32_t)(row << 7) + (uint32_t)(kq << 4);
        off ^= (uint32_t)(row & 7) << 4;
        *(uint4*)(dst + off) = v;
    }
}

// ---------------- elementwise / prep kernels ----------------
__global__ void vnorm_split_kernel(const float* __restrict__ vocab) {
    int r = blockIdx.x;
    const float* row = vocab + (size_t)r * C_;
    int t = threadIdx.x;
    float x0 = row[t], x1 = row[t + 256];
    float s = blockSumAll(x0 * x0 + x1 * x1);
    float inv = 1.0f / fmaxf(sqrtf(s), 1e-12f);
    size_t o = (size_t)r * C_;
    __nv_bfloat16 h, l;
    split_bf16(x0 * inv, h, l); g_vn_hi[o + t] = h;       g_vn_lo[o + t] = l;
    split_bf16(x1 * inv, h, l); g_vn_hi[o + t + 256] = h; g_vn_lo[o + t + 256] = l;
}

__global__ void ptnorm_kernel(const float* __restrict__ pt) {
    int r = blockIdx.x;
    const float* row = pt + (size_t)r * D_;
    int t = threadIdx.x;
    float x0 = row[t], x1 = row[t + 256], x2 = row[t + 512];
    float s = blockSumAll(x0 * x0 + x1 * x1 + x2 * x2);
    float inv = 1.0f / fmaxf(sqrtf(s), 1e-12f);
    size_t o = (size_t)r * D_;
    g_pt_hi[o + t] = __float2bfloat16_rn(x0 * inv);
    g_pt_hi[o + t + 256] = __float2bfloat16_rn(x1 * inv);
    g_pt_hi[o + t + 512] = __float2bfloat16_rn(x2 * inv);
}

__global__ void w1t_kernel(const float* __restrict__ W1) {
    int n = blockIdx.x;
    for (int k = threadIdx.x; k < C_; k += 256) {
        __nv_bfloat16 h, l;
        split_bf16(W1[(size_t)k * Hh_ + n], h, l);
        g_w1t_hi[(size_t)n * C_ + k] = h;
        g_w1t_lo[(size_t)n * C_ + k] = l;
    }
}
__global__ void w2t_kernel(const float* __restrict__ W2) {
    int n = blockIdx.x;
    for (int k = threadIdx.x; k < Hh_; k += 256) {
        __nv_bfloat16 h, l;
        split_bf16(W2[(size_t)k * D_ + n], h, l);
        g_w2t_hi[(size_t)n * Hh_ + k] = h;
        g_w2t_lo[(size_t)n * Hh_ + k] = l;
    }
}

__global__ void zero_kernel() {
    int i = blockIdx.x * 256 + threadIdx.x;
    if (i < Hh_) { g_colsum[i] = 0.f; g_colsq[i] = 0.f; }
}

__global__ void bnstats_kernel() {
    int c = blockIdx.x * 256 + threadIdx.x;
    int chunk = blockIdx.y;
    const int RC = (V_ + 31) / 32;
    int r0 = chunk * RC, r1 = min(V_, r0 + RC);
    float s = 0.f, sq = 0.f;
    for (int r = r0; r < r1; r++) {
        float x = g_h[(size_t)r * Hh_ + c];
        s += x; sq += x * x;
    }
    atomicAdd(&g_colsum[c], s);
    atomicAdd(&g_colsq[c], sq);
}

__global__ void bnfinal_kernel(const float* __restrict__ gamma, const float* __restrict__ beta) {
    int c = threadIdx.x;
    if (c < Hh_) {
        float mean = g_colsum[c] / (float)V_;
        float var = g_colsq[c] / (float)V_ - mean * mean;
        float sc = gamma[c] / sqrtf(var + BN_EPS);
        g_scale[c] = sc;
        g_shift[c] = beta[c] - mean * sc;
    }
}

__global__ void hsplit_kernel() {
    int r = blockIdx.x;
    int t = threadIdx.x;
    size_t o = (size_t)r * Hh_;
    #pragma unroll
    for (int p = 0; p < 3; p++) {
        int c = t + p * 256;
        float y = fmaxf(fmaf(g_h[o + c], g_scale[c], g_shift[c]), 0.f);
        __nv_bfloat16 h, l;
        split_bf16(y, h, l);
        g_hb_hi[o + c] = h; g_hb_lo[o + c] = l;
    }
}

// proto row norm + split to bf16 hi/lo
__global__ void pnorm_kernel() {
    int r = blockIdx.x;
    const float* row = g_proto + (size_t)r * D_;
    int t = threadIdx.x;
    float x0 = row[t], x1 = row[t + 256], x2 = row[t + 512];
    float s = blockSumAll(x0 * x0 + x1 * x1 + x2 * x2);
    float inv = 1.0f / fmaxf(sqrtf(s), 1e-12f);
    size_t o = (size_t)r * D_;
    __nv_bfloat16 h, l;
    split_bf16(x0 * inv, h, l); g_proto_hi[o + t] = h;       g_proto_lo[o + t] = l;
    split_bf16(x1 * inv, h, l); g_proto_hi[o + t + 256] = h; g_proto_lo[o + t + 256] = l;
    split_bf16(x2 * inv, h, l); g_proto_hi[o + t + 512] = h; g_proto_lo[o + t + 512] = l;
}

// ---------------- generic 3-pass split-bf16 HMMA GEMM (device body) ----------------
// C[m, n] (+bias) = A[m,:] . Bt[n,:],  M rows guarded at V_, N = 768 exact, K in {512, 768}
// NOTE: must be called with the global-symbol pointers bound in DEVICE code (wrapper
// kernels below). Passing __device__ symbols from host is UB (host shadow address) and
// on GB300 ATS silently dereferences host memory — root cause of the R7/R8 failures.
__device__ __forceinline__ void hgemm3_body(
    const __nv_bfloat16* __restrict__ Ah, const __nv_bfloat16* __restrict__ Al,
    const __nv_bfloat16* __restrict__ Bth, const __nv_bfloat16* __restrict__ Btl,
    float* __restrict__ C, const float* __restrict__ bias, int K) {
    __shared__ alignas(128) __nv_bfloat16 As[128 * 64];
    __shared__ alignas(128) __nv_bfloat16 Bs[128 * 64];
    const int t = threadIdx.x;
    const int lane = t & 31, wid = t >> 5;
    const int wm = wid >> 1, wn = wid & 1;
    const int mb = blockIdx.y * 128, nb = blockIdx.x * 128;

    const uint32_t sA = smem_u32(As), sB = smem_u32(Bs);
    const int rowA = wm * 32 + (lane & 15);
    const uint32_t swA = (uint32_t)(rowA & 7) << 4;
    const uint32_t kselA = (uint32_t)(lane >> 4) << 4;
    const int rowBn = wn * 64 + ((lane >> 4) << 3) + (lane & 7);
    const uint32_t swB = (uint32_t)(lane & 7) << 4;
    const uint32_t kselB = (uint32_t)((lane >> 3) & 1) << 4;

    float acc[2][8][4];
    #pragma unroll
    for (int mf = 0; mf < 2; mf++)
        #pragma unroll
        for (int nf = 0; nf < 8; nf++)
            #pragma unroll
            for (int e = 0; e < 4; e++) acc[mf][nf][e] = 0.f;

    const int nchunk = K >> 6;
    #pragma unroll 1
    for (int pass = 0; pass < 3; pass++) {
        const __nv_bfloat16* Asrc = (pass < 2) ? Ah : Al;
        const __nv_bfloat16* Bsrc = (pass == 1) ? Btl : Bth;
        #pragma unroll 1
        for (int chunk = 0; chunk < nchunk; chunk++) {
            const int kb = chunk * 64;
            __syncthreads();
            load_tile((char*)As, Asrc, mb, kb, K, V_);
            load_tile((char*)Bs, Bsrc, nb, kb, K, 1 << 30);
            __syncthreads();
            #pragma unroll
            for (int ks = 0; ks < 4; ks++) {
                uint32_t a[2][4];
                #pragma unroll
                for (int mf = 0; mf < 2; mf++) {
                    uint32_t addr = sA + (uint32_t)((rowA + mf * 16) << 7)
                                  + (((uint32_t)(ks * 32) + kselA) ^ swA);
                    ldsm_x4(addr, a[mf][0], a[mf][1], a[mf][2], a[mf][3]);
                }
                uint32_t bf[4][4];
                #pragma unroll
                for (int nf2 = 0; nf2 < 4; nf2++) {
                    uint32_t addr = sB + (uint32_t)((rowBn + nf2 * 16) << 7)
                                  + (((uint32_t)(ks * 32) + kselB) ^ swB);
                    ldsm_x4(addr, bf[nf2][0], bf[nf2][1], bf[nf2][2], bf[nf2][3]);
                }
                #pragma unroll
                for (int mf = 0; mf < 2; mf++)
                    #pragma unroll
                    for (int nf = 0; nf < 8; nf++)
                        mma_bf16(acc[mf][nf], a[mf],
                                 bf[nf >> 1][(nf & 1) * 2], bf[nf >> 1][(nf & 1) * 2 + 1]);
            }
        }
    }
    #pragma unroll
    for (int mf = 0; mf < 2; mf++)
        #pragma unroll
        for (int h = 0; h < 2; h++) {
            int row = mb + wm * 32 + mf * 16 + (lane >> 2) + h * 8;
            if (row >= V_) continue;
            #pragma unroll
            for (int nf = 0; nf < 8; nf++) {
                int col = nb + wn * 64 + nf * 8 + (lane & 3) * 2;
                float2 v;
                v.x = acc[mf][nf][h * 2 + 0];
                v.y = acc[mf][nf][h * 2 + 1];
                if (bias) { v.x += bias[col]; v.y += bias[col + 1]; }
                *(float2*)(C + (size_t)row * 768 + col) = v;
            }
        }
}

// wrappers: bind global symbols in device code
__global__ __launch_bounds__(256, 2) void gemm1_bf16_kernel() {
    hgemm3_body(g_vn_hi, g_vn_lo, g_w1t_hi, g_w1t_lo, g_h, nullptr, C_);
}
__global__ __launch_bounds__(256, 2) void gemm2_bf16_kernel(const float* __restrict__ b2) {
    hgemm3_body(g_hb_hi, g_hb_lo, g_w2t_hi, g_w2t_lo, g_proto, b2, Hh_);
}

// ---------------- 2-pass HMMA logits GEMM fused with max over tokens ----------------
// out[b, v] = max_n pt[b,n,:] . proto[v,:]
// pass 0: proto_hi . pt_hi ; pass 1: proto_lo . pt_hi  (dropped proto.pt_lo term: sigma ~4e-5)
__global__ __launch_bounds__(256, 2) void k5_mma_kernel(float* __restrict__ out) {
    __shared__ alignas(128) __nv_bfloat16 As[128 * 64];
    __shared__ alignas(128) __nv_bfloat16 Bs[128 * 64];
    __shared__ float redbuf[2][128];
    __shared__ float rmax[128];

    const int t = threadIdx.x;
    const int lane = t & 31, wid = t >> 5;
    const int wm = wid >> 1, wn = wid & 1;
    const int b = blockIdx.x;                 // batch fastest -> proto tiles shared in L2
    const int vb = blockIdx.y * 128;

    if (t < 128) rmax[t] = -1e30f;

    const uint32_t sA = smem_u32(As), sB = smem_u32(Bs);
    const int rowA = wm * 32 + (lane & 15);
    const uint32_t swA = (uint32_t)(rowA & 7) << 4;
    const uint32_t kselA = (uint32_t)(lane >> 4) << 4;
    const int rowBn = wn * 64 + ((lane >> 4) << 3) + (lane & 7);
    const uint32_t swB = (uint32_t)(lane & 7) << 4;
    const uint32_t kselB = (uint32_t)((lane >> 3) & 1) << 4;

    for (int tt = 0; tt < 8; tt++) {
        float acc[2][8][4];
        #pragma unroll
        for (int mf = 0; mf < 2; mf++)
            #pragma unroll
            for (int nf = 0; nf < 8; nf++)
                #pragma unroll
                for (int e = 0; e < 4; e++) acc[mf][nf][e] = 0.f;

        const int tokbase = b * N_ + tt * 128;
        #pragma unroll 1
        for (int pass = 0; pass < 2; pass++) {
            const __nv_bfloat16* Asrc = (pass == 0) ? g_proto_hi : g_proto_lo;
            #pragma unroll 1
            for (int chunk = 0; chunk < 12; chunk++) {
                const int kb = chunk * 64;
                __syncthreads();
                load_tile((char*)As, Asrc, vb, kb, D_, V_);
                load_tile((char*)Bs, g_pt_hi, tokbase, kb, D_, 1 << 30);
                __syncthreads();
                #pragma unroll
                for (int ks = 0; ks < 4; ks++) {
                    uint32_t a[2][4];
                    #pragma unroll
                    for (int mf = 0; mf < 2; mf++) {
                        uint32_t addr = sA + (uint32_t)((rowA + mf * 16) << 7)
                                      + (((uint32_t)(ks * 32) + kselA) ^ swA);
                        ldsm_x4(addr, a[mf][0], a[mf][1], a[mf][2], a[mf][3]);
                    }
                    uint32_t bf[4][4];
                    #pragma unroll
                    for (int nf2 = 0; nf2 < 4; nf2++) {
                        uint32_t addr = sB + (uint32_t)((rowBn + nf2 * 16) << 7)
                                      + (((uint32_t)(ks * 32) + kselB) ^ swB);
                        ldsm_x4(addr, bf[nf2][0], bf[nf2][1], bf[nf2][2], bf[nf2][3]);
                    }
                    #pragma unroll
                    for (int mf = 0; mf < 2; mf++)
                        #pragma unroll
                        for (int nf = 0; nf < 8; nf++)
                            mma_bf16(acc[mf][nf], a[mf],
                                     bf[nf >> 1][(nf & 1) * 2], bf[nf >> 1][(nf & 1) * 2 + 1]);
                }
            }
        }

        // ---- fused max over the 128 tokens of this tile ----
        float m4[2][2];
        #pragma unroll
        for (int mf = 0; mf < 2; mf++)
            #pragma unroll
            for (int h = 0; h < 2; h++) {
                float m = -1e30f;
                #pragma unroll
                for (int nf = 0; nf < 8; nf++)
                    m = fmaxf(m, fmaxf(acc[mf][nf][h * 2], acc[mf][nf][h * 2 + 1]));
                m4[mf][h] = m;
            }
        #pragma unroll
        for (int mf = 0; mf < 2; mf++)
            #pragma unroll
            for (int h = 0; h < 2; h++) {
                float m = m4[mf][h];
                m = fmaxf(m, __shfl_xor_sync(0xffffffffu, m, 1));
                m = fmaxf(m, __shfl_xor_sync(0xffffffffu, m, 2));
                m4[mf][h] = m;
            }
        __syncthreads();
        if ((lane & 3) == 0) {
            #pragma unroll
            for (int mf = 0; mf < 2; mf++)
                #pragma unroll
                for (int h = 0; h < 2; h++)
                    redbuf[wn][wm * 32 + mf * 16 + (lane >> 2) + h * 8] = m4[mf][h];
        }
        __syncthreads();
        if (t < 128) rmax[t] = fmaxf(rmax[t], fmaxf(redbuf[0][t], redbuf[1][t]));
    }

    if (t < 128) {
        int gv = vb + t;
        if (gv < V_) out[(size_t)b * V_ + gv] = rmax[t];
    }
}

// in-place softmax over V per batch row
__global__ void softmax_kernel(float* __restrict__ out) {
    int b = blockIdx.x;
    float* row = out + (size_t)b * V_;
    __shared__ float sb[33];
    int t = threadIdx.x, lane = t & 31, w = t >> 5;

    float m = -1e30f;
    for (int v = t; v < V_; v += 1024) m = fmaxf(m, row[v]);
    #pragma unroll
    for (int o = 16; o; o >>= 1) m = fmaxf(m, __shfl_xor_sync(0xffffffffu, m, o));
    if (lane == 0) sb[w] = m;
    __syncthreads();
    if (t == 0) {
        float mm = -1e30f;
        for (int i = 0; i < 32; i++) mm = fmaxf(mm, sb[i]);
        sb[32] = mm;
    }
    __syncthreads();
    float M = sb[32];

    float s = 0.f;
    for (int v = t; v < V_; v += 1024) s += expf((row[v] - M) * INV_T);
    s = warpSum(s);
    __syncthreads();
    if (lane == 0) sb[w] = s;
    __syncthreads();
    if (t == 0) {
        float ss = 0.f;
        for (int i = 0; i < 32; i++) ss += sb[i];
        sb[32] = ss;
    }
    __syncthreads();
    float inv = 1.0f / sb[32];
    for (int v = t; v < V_; v += 1024) row[v] = expf((row[v] - M) * INV_T) * inv;
}

// ---------------- launch ----------------
extern "C" void kernel_launch(void* const* d_in, const int* in_sizes, int n_in,
                              void* d_out, int out_size) {
    const float* patch = (const float*)d_in[0];
    const float* vocab = (const float*)d_in[1];
    const float* W1    = (const float*)d_in[2];
    const float* gamma = (const float*)d_in[3];
    const float* beta  = (const float*)d_in[4];
    const float* W2    = (const float*)d_in[5];
    const float* b2    = (const float*)d_in[6];
    float* out = (float*)d_out;

    const int VT = (V_ + 127) / 128;   // 235

    vnorm_split_kernel<<<V_, 256>>>(vocab);
    ptnorm_kernel<<<B_ * N_, 256>>>(patch);
    w1t_kernel<<<Hh_, 256>>>(W1);
    w2t_kernel<<<D_, 256>>>(W2);
    zero_kernel<<<3, 256>>>();
    gemm1_bf16_kernel<<<dim3(Hh_ / 128, VT), 256>>>();
    bnstats_kernel<<<dim3(3, 32), 256>>>();
    bnfinal_kernel<<<1, Hh_>>>(gamma, beta);
    hsplit_kernel<<<V_, 256>>>();
    gemm2_bf16_kernel<<<dim3(D_ / 128, VT), 256>>>(b2);
    pnorm_kernel<<<V_, 256>>>();
    k5_mma_kernel<<<dim3(B_, VT), 256>>>(out);
    softmax_kernel<<<B_, 1024>>>(out);
}

// round 11
// speedup vs baseline: 4.0716x; 1.3290x over previous
#include <cuda_runtime.h>
#include <cuda_bf16.h>
#include <math.h>
#include <stdint.h>

#define B_  8
#define N_  1024
#define D_  768
#define V_  30000
#define C_  512
#define Hh_ 768
#define INV_T 5.0f
#define BN_EPS 1e-5f
#define MARGIN 0.002f
#define CAND_CAP (4u * 1024u * 1024u)
#define SCAP 2048

// ---------------- scratch (static device globals; no allocs allowed) ----------------
__device__ float g_h[(size_t)V_ * Hh_];
__device__ float g_proto[(size_t)V_ * D_];     // fp32 prototypes (normalized in place)
__device__ float g_ptf[(size_t)B_ * N_ * D_];  // fp32 normalized tokens
__device__ float g_colsum[Hh_], g_colsq[Hh_];
__device__ float g_scale[Hh_], g_shift[Hh_];
// split operands
__device__ __nv_bfloat16 g_vn_hi[(size_t)V_ * C_], g_vn_lo[(size_t)V_ * C_];
__device__ __nv_bfloat16 g_w1t_hi[(size_t)Hh_ * C_], g_w1t_lo[(size_t)Hh_ * C_];
__device__ __nv_bfloat16 g_hb_hi[(size_t)V_ * Hh_], g_hb_lo[(size_t)V_ * Hh_];
__device__ __nv_bfloat16 g_w2t_hi[(size_t)D_ * Hh_], g_w2t_lo[(size_t)D_ * Hh_];
__device__ __nv_bfloat16 g_proto_hi[(size_t)V_ * D_];
__device__ __nv_bfloat16 g_pt_hi[(size_t)B_ * N_ * D_];
// candidate machinery
__device__ unsigned g_ccount;
__device__ unsigned g_cand[CAND_CAP];
__device__ float g_capprox[CAND_CAP];
__device__ float g_amax[(size_t)B_ * V_];
__device__ unsigned g_okey[(size_t)B_ * V_];

// ---------------- helpers ----------------
__device__ __forceinline__ uint32_t smem_u32(const void* p) {
    uint32_t a;
    asm("{ .reg .u64 t; cvta.to.shared.u64 t, %1; cvt.u32.u64 %0, t; }" : "=r"(a) : "l"(p));
    return a;
}
__device__ __forceinline__ float warpSum(float v) {
    #pragma unroll
    for (int o = 16; o; o >>= 1) v += __shfl_xor_sync(0xffffffffu, v, o);
    return v;
}
__device__ float blockSumAll(float v) {
    __shared__ float sb[33];
    int lane = threadIdx.x & 31, w = threadIdx.x >> 5;
    v = warpSum(v);
    if (lane == 0) sb[w] = v;
    __syncthreads();
    if (threadIdx.x == 0) {
        float s = 0.f;
        int nw = (blockDim.x + 31) >> 5;
        for (int i = 0; i < nw; i++) s += sb[i];
        sb[32] = s;
    }
    __syncthreads();
    return sb[32];
}
__device__ __forceinline__ void split_bf16(float x, __nv_bfloat16& hi, __nv_bfloat16& lo) {
    hi = __float2bfloat16_rn(x);
    lo = __float2bfloat16_rn(x - __bfloat162float(hi));
}
__device__ __forceinline__ unsigned fkey(float f) {
    unsigned u = __float_as_uint(f);
    return (u & 0x80000000u) ? ~u : (u | 0x80000000u);
}
__device__ __forceinline__ float funkey(unsigned k) {
    return (k & 0x80000000u) ? __uint_as_float(k ^ 0x80000000u) : __uint_as_float(~k);
}
__device__ __forceinline__ void ldsm_x4(uint32_t addr, uint32_t& r0, uint32_t& r1,
                                        uint32_t& r2, uint32_t& r3) {
    asm volatile("ldmatrix.sync.aligned.m8n8.x4.shared.b16 {%0,%1,%2,%3}, [%4];"
                 : "=r"(r0), "=r"(r1), "=r"(r2), "=r"(r3) : "r"(addr));
}
__device__ __forceinline__ void mma_bf16(float* d, const uint32_t* a, uint32_t b0, uint32_t b1) {
    asm volatile(
        "mma.sync.aligned.m16n8k16.row.col.f32.bf16.bf16.f32 "
        "{%0,%1,%2,%3}, {%4,%5,%6,%7}, {%8,%9}, {%0,%1,%2,%3};"
        : "+f"(d[0]), "+f"(d[1]), "+f"(d[2]), "+f"(d[3])
        : "r"(a[0]), "r"(a[1]), "r"(a[2]), "r"(a[3]), "r"(b0), "r"(b1));
}
// stage one 128x64 bf16 tile (row-major, swizzled) into smem. ldk = source row stride
__device__ __forceinline__ void load_tile(char* dst, const __nv_bfloat16* __restrict__ src,
                                          int rowbase, int kb, int ldk, int rowmax) {
    const int t = threadIdx.x;
    #pragma unroll
    for (int s = 0; s < 4; s++) {
        int idx = t + s * 256;
        int row = idx >> 3, kq = idx & 7;
        int gr = rowbase + row;
        uint4 v = make_uint4(0u, 0u, 0u, 0u);
        if (gr < rowmax) v = *(const uint4*)(src + (size_t)gr * ldk + kb + kq * 8);
        uint32_t off = (uint32_t)(row << 7) + (uint32_t)(kq << 4);
        off ^= (uint32_t)(row & 7) << 4;
        *(uint4*)(dst + off) = v;
    }
}

// ---------------- elementwise / prep kernels ----------------
__global__ void vnorm_split_kernel(const float* __restrict__ vocab) {
    int r = blockIdx.x;
    const float* row = vocab + (size_t)r * C_;
    int t = threadIdx.x;
    float x0 = row[t], x1 = row[t + 256];
    float s = blockSumAll(x0 * x0 + x1 * x1);
    float inv = 1.0f / fmaxf(sqrtf(s), 1e-12f);
    size_t o = (size_t)r * C_;
    __nv_bfloat16 h, l;
    split_bf16(x0 * inv, h, l); g_vn_hi[o + t] = h;       g_vn_lo[o + t] = l;
    split_bf16(x1 * inv, h, l); g_vn_hi[o + t + 256] = h; g_vn_lo[o + t + 256] = l;
}

__global__ void ptnorm_kernel(const float* __restrict__ pt) {
    int r = blockIdx.x;
    const float* row = pt + (size_t)r * D_;
    int t = threadIdx.x;
    float x0 = row[t], x1 = row[t + 256], x2 = row[t + 512];
    float s = blockSumAll(x0 * x0 + x1 * x1 + x2 * x2);
    float inv = 1.0f / fmaxf(sqrtf(s), 1e-12f);
    size_t o = (size_t)r * D_;
    float y0 = x0 * inv, y1 = x1 * inv, y2 = x2 * inv;
    g_ptf[o + t] = y0; g_ptf[o + t + 256] = y1; g_ptf[o + t + 512] = y2;
    g_pt_hi[o + t] = __float2bfloat16_rn(y0);
    g_pt_hi[o + t + 256] = __float2bfloat16_rn(y1);
    g_pt_hi[o + t + 512] = __float2bfloat16_rn(y2);
}

__global__ void w1t_kernel(const float* __restrict__ W1) {
    int n = blockIdx.x;
    for (int k = threadIdx.x; k < C_; k += 256) {
        __nv_bfloat16 h, l;
        split_bf16(W1[(size_t)k * Hh_ + n], h, l);
        g_w1t_hi[(size_t)n * C_ + k] = h;
        g_w1t_lo[(size_t)n * C_ + k] = l;
    }
}
__global__ void w2t_kernel(const float* __restrict__ W2) {
    int n = blockIdx.x;
    for (int k = threadIdx.x; k < Hh_; k += 256) {
        __nv_bfloat16 h, l;
        split_bf16(W2[(size_t)k * D_ + n], h, l);
        g_w2t_hi[(size_t)n * Hh_ + k] = h;
        g_w2t_lo[(size_t)n * Hh_ + k] = l;
    }
}

__global__ void zero_kernel() {
    int i = blockIdx.x * 256 + threadIdx.x;
    if (i < Hh_) { g_colsum[i] = 0.f; g_colsq[i] = 0.f; }
    if (i == 0) g_ccount = 0;
    for (int j = i; j < B_ * V_; j += gridDim.x * 256) g_okey[j] = 0u;
}

__global__ void bnstats_kernel() {
    int c = blockIdx.x * 256 + threadIdx.x;
    int chunk = blockIdx.y;
    const int RC = (V_ + 31) / 32;
    int r0 = chunk * RC, r1 = min(V_, r0 + RC);
    float s = 0.f, sq = 0.f;
    for (int r = r0; r < r1; r++) {
        float x = g_h[(size_t)r * Hh_ + c];
        s += x; sq += x * x;
    }
    atomicAdd(&g_colsum[c], s);
    atomicAdd(&g_colsq[c], sq);
}

__global__ void bnfinal_kernel(const float* __restrict__ gamma, const float* __restrict__ beta) {
    int c = threadIdx.x;
    if (c < Hh_) {
        float mean = g_colsum[c] / (float)V_;
        float var = g_colsq[c] / (float)V_ - mean * mean;
        float sc = gamma[c] / sqrtf(var + BN_EPS);
        g_scale[c] = sc;
        g_shift[c] = beta[c] - mean * sc;
    }
}

__global__ void hsplit_kernel() {
    int r = blockIdx.x;
    int t = threadIdx.x;
    size_t o = (size_t)r * Hh_;
    #pragma unroll
    for (int p = 0; p < 3; p++) {
        int c = t + p * 256;
        float y = fmaxf(fmaf(g_h[o + c], g_scale[c], g_shift[c]), 0.f);
        __nv_bfloat16 h, l;
        split_bf16(y, h, l);
        g_hb_hi[o + c] = h; g_hb_lo[o + c] = l;
    }
}

// proto row norm in place (fp32) + bf16 hi
__global__ void pnorm_kernel() {
    int r = blockIdx.x;
    float* row = g_proto + (size_t)r * D_;
    int t = threadIdx.x;
    float x0 = row[t], x1 = row[t + 256], x2 = row[t + 512];
    float s = blockSumAll(x0 * x0 + x1 * x1 + x2 * x2);
    float inv = 1.0f / fmaxf(sqrtf(s), 1e-12f);
    float y0 = x0 * inv, y1 = x1 * inv, y2 = x2 * inv;
    row[t] = y0; row[t + 256] = y1; row[t + 512] = y2;
    size_t o = (size_t)r * D_;
    g_proto_hi[o + t] = __float2bfloat16_rn(y0);
    g_proto_hi[o + t + 256] = __float2bfloat16_rn(y1);
    g_proto_hi[o + t + 512] = __float2bfloat16_rn(y2);
}

// ---------------- generic 3-pass split-bf16 HMMA GEMM (device body) ----------------
// NOTE: global-symbol pointers must be bound in DEVICE code (wrapper kernels) —
// passing __device__ symbols from host is UB, and GB300 ATS silently dereferences
// the host shadow (root cause of the R7/R8 failures).
__device__ __forceinline__ void hgemm3_body(
    const __nv_bfloat16* __restrict__ Ah, const __nv_bfloat16* __restrict__ Al,
    const __nv_bfloat16* __restrict__ Bth, const __nv_bfloat16* __restrict__ Btl,
    float* __restrict__ C, const float* __restrict__ bias, int K) {
    __shared__ alignas(128) __nv_bfloat16 As[128 * 64];
    __shared__ alignas(128) __nv_bfloat16 Bs[128 * 64];
    const int t = threadIdx.x;
    const int lane = t & 31, wid = t >> 5;
    const int wm = wid >> 1, wn = wid & 1;
    const int mb = blockIdx.y * 128, nb = blockIdx.x * 128;

    const uint32_t sA = smem_u32(As), sB = smem_u32(Bs);
    const int rowA = wm * 32 + (lane & 15);
    const uint32_t swA = (uint32_t)(rowA & 7) << 4;
    const uint32_t kselA = (uint32_t)(lane >> 4) << 4;
    const int rowBn = wn * 64 + ((lane >> 4) << 3) + (lane & 7);
    const uint32_t swB = (uint32_t)(lane & 7) << 4;
    const uint32_t kselB = (uint32_t)((lane >> 3) & 1) << 4;

    float acc[2][8][4];
    #pragma unroll
    for (int mf = 0; mf < 2; mf++)
        #pragma unroll
        for (int nf = 0; nf < 8; nf++)
            #pragma unroll
            for (int e = 0; e < 4; e++) acc[mf][nf][e] = 0.f;

    const int nchunk = K >> 6;
    #pragma unroll 1
    for (int pass = 0; pass < 3; pass++) {
        const __nv_bfloat16* Asrc = (pass < 2) ? Ah : Al;
        const __nv_bfloat16* Bsrc = (pass == 1) ? Btl : Bth;
        #pragma unroll 1
        for (int chunk = 0; chunk < nchunk; chunk++) {
            const int kb = chunk * 64;
            __syncthreads();
            load_tile((char*)As, Asrc, mb, kb, K, V_);
            load_tile((char*)Bs, Bsrc, nb, kb, K, 1 << 30);
            __syncthreads();
            #pragma unroll
            for (int ks = 0; ks < 4; ks++) {
                uint32_t a[2][4];
                #pragma unroll
                for (int mf = 0; mf < 2; mf++) {
                    uint32_t addr = sA + (uint32_t)((rowA + mf * 16) << 7)
                                  + (((uint32_t)(ks * 32) + kselA) ^ swA);
                    ldsm_x4(addr, a[mf][0], a[mf][1], a[mf][2], a[mf][3]);
                }
                uint32_t bf[4][4];
                #pragma unroll
                for (int nf2 = 0; nf2 < 4; nf2++) {
                    uint32_t addr = sB + (uint32_t)((rowBn + nf2 * 16) << 7)
                                  + (((uint32_t)(ks * 32) + kselB) ^ swB);
                    ldsm_x4(addr, bf[nf2][0], bf[nf2][1], bf[nf2][2], bf[nf2][3]);
                }
                #pragma unroll
                for (int mf = 0; mf < 2; mf++)
                    #pragma unroll
                    for (int nf = 0; nf < 8; nf++)
                        mma_bf16(acc[mf][nf], a[mf],
                                 bf[nf >> 1][(nf & 1) * 2], bf[nf >> 1][(nf & 1) * 2 + 1]);
            }
        }
    }
    #pragma unroll
    for (int mf = 0; mf < 2; mf++)
        #pragma unroll
        for (int h = 0; h < 2; h++) {
            int row = mb + wm * 32 + mf * 16 + (lane >> 2) + h * 8;
            if (row >= V_) continue;
            #pragma unroll
            for (int nf = 0; nf < 8; nf++) {
                int col = nb + wn * 64 + nf * 8 + (lane & 3) * 2;
                float2 v;
                v.x = acc[mf][nf][h * 2 + 0];
                v.y = acc[mf][nf][h * 2 + 1];
                if (bias) { v.x += bias[col]; v.y += bias[col + 1]; }
                *(float2*)(C + (size_t)row * 768 + col) = v;
            }
        }
}

__global__ __launch_bounds__(256, 2) void gemm1_bf16_kernel() {
    hgemm3_body(g_vn_hi, g_vn_lo, g_w1t_hi, g_w1t_lo, g_h, nullptr, C_);
}
__global__ __launch_bounds__(256, 2) void gemm2_bf16_kernel(const float* __restrict__ b2) {
    hgemm3_body(g_hb_hi, g_hb_lo, g_w2t_hi, g_w2t_lo, g_proto, b2, Hh_);
}

// ---------------- 1-pass HMMA logits + fused max + candidate recording ----------------
__global__ __launch_bounds__(256, 2) void k5_mma_kernel() {
    __shared__ alignas(128) __nv_bfloat16 As[128 * 64];
    __shared__ alignas(128) __nv_bfloat16 Bs[128 * 64];
    __shared__ float redbuf[2][128];
    __shared__ float rmax[128];
    __shared__ unsigned s_cnt, s_gbase, s_n;
    __shared__ unsigned s_cand[SCAP];
    __shared__ float s_appr[SCAP];

    const int t = threadIdx.x;
    const int lane = t & 31, wid = t >> 5;
    const int wm = wid >> 1, wn = wid & 1;
    const int b = blockIdx.x;                 // batch fastest -> proto tiles shared in L2
    const int vb = blockIdx.y * 128;

    if (t < 128) rmax[t] = -1e30f;
    if (t == 0) s_cnt = 0;

    const uint32_t sA = smem_u32(As), sB = smem_u32(Bs);
    const int rowA = wm * 32 + (lane & 15);
    const uint32_t swA = (uint32_t)(rowA & 7) << 4;
    const uint32_t kselA = (uint32_t)(lane >> 4) << 4;
    const int rowBn = wn * 64 + ((lane >> 4) << 3) + (lane & 7);
    const uint32_t swB = (uint32_t)(lane & 7) << 4;
    const uint32_t kselB = (uint32_t)((lane >> 3) & 1) << 4;

    for (int tt = 0; tt < 8; tt++) {
        float acc[2][8][4];
        #pragma unroll
        for (int mf = 0; mf < 2; mf++)
            #pragma unroll
            for (int nf = 0; nf < 8; nf++)
                #pragma unroll
                for (int e = 0; e < 4; e++) acc[mf][nf][e] = 0.f;

        const int tokbase = b * N_ + tt * 128;
        #pragma unroll 1
        for (int chunk = 0; chunk < 12; chunk++) {
            const int kb = chunk * 64;
            __syncthreads();
            load_tile((char*)As, g_proto_hi, vb, kb, D_, V_);
            load_tile((char*)Bs, g_pt_hi, tokbase, kb, D_, 1 << 30);
            __syncthreads();
            #pragma unroll
            for (int ks = 0; ks < 4; ks++) {
                uint32_t a[2][4];
                #pragma unroll
                for (int mf = 0; mf < 2; mf++) {
                    uint32_t addr = sA + (uint32_t)((rowA + mf * 16) << 7)
                                  + (((uint32_t)(ks * 32) + kselA) ^ swA);
                    ldsm_x4(addr, a[mf][0], a[mf][1], a[mf][2], a[mf][3]);
                }
                uint32_t bf[4][4];
                #pragma unroll
                for (int nf2 = 0; nf2 < 4; nf2++) {
                    uint32_t addr = sB + (uint32_t)((rowBn + nf2 * 16) << 7)
                                  + (((uint32_t)(ks * 32) + kselB) ^ swB);
                    ldsm_x4(addr, bf[nf2][0], bf[nf2][1], bf[nf2][2], bf[nf2][3]);
                }
                #pragma unroll
                for (int mf = 0; mf < 2; mf++)
                    #pragma unroll
                    for (int nf = 0; nf < 8; nf++)
                        mma_bf16(acc[mf][nf], a[mf],
                                 bf[nf >> 1][(nf & 1) * 2], bf[nf >> 1][(nf & 1) * 2 + 1]);
            }
        }

        // ---- per-v max over this 128-token tile ----
        float m4[2][2];
        #pragma unroll
        for (int mf = 0; mf < 2; mf++)
            #pragma unroll
            for (int h = 0; h < 2; h++) {
                float m = -1e30f;
                #pragma unroll
                for (int nf = 0; nf < 8; nf++)
                    m = fmaxf(m, fmaxf(acc[mf][nf][h * 2], acc[mf][nf][h * 2 + 1]));
                m4[mf][h] = m;
            }
        #pragma unroll
        for (int mf = 0; mf < 2; mf++)
            #pragma unroll
            for (int h = 0; h < 2; h++) {
                float m = m4[mf][h];
                m = fmaxf(m, __shfl_xor_sync(0xffffffffu, m, 1));
                m = fmaxf(m, __shfl_xor_sync(0xffffffffu, m, 2));
                m4[mf][h] = m;
            }
        __syncthreads();
        if ((lane & 3) == 0) {
            #pragma unroll
            for (int mf = 0; mf < 2; mf++)
                #pragma unroll
                for (int h = 0; h < 2; h++)
                    redbuf[wn][wm * 32 + mf * 16 + (lane >> 2) + h * 8] = m4[mf][h];
        }
        __syncthreads();
        if (t < 128) rmax[t] = fmaxf(rmax[t], fmaxf(redbuf[0][t], redbuf[1][t]));
        __syncthreads();

        // ---- record candidates within MARGIN of running max ----
        #pragma unroll
        for (int mf = 0; mf < 2; mf++)
            #pragma unroll
            for (int h = 0; h < 2; h++) {
                int lrow = wm * 32 + mf * 16 + (lane >> 2) + h * 8;
                int gv = vb + lrow;
                if (gv >= V_) continue;
                float thr = rmax[lrow] - MARGIN;
                #pragma unroll
                for (int nf = 0; nf < 8; nf++)
                    #pragma unroll
                    for (int e2 = 0; e2 < 2; e2++) {
                        float val = acc[mf][nf][h * 2 + e2];
                        if (val >= thr) {
                            unsigned pos = atomicAdd(&s_cnt, 1u);
                            if (pos < SCAP) {
                                int tok = tt * 128 + wn * 64 + nf * 8 + (lane & 3) * 2 + e2;
                                s_cand[pos] = ((unsigned)(b * V_ + gv) << 10) | (unsigned)tok;
                                s_appr[pos] = val;
                            }
                        }
                    }
            }
        __syncthreads();
        if (t == 0) {
            unsigned n = min(s_cnt, (unsigned)SCAP);
            s_gbase = atomicAdd(&g_ccount, n);
            s_n = n;
            s_cnt = 0;
        }
        __syncthreads();
        for (unsigned i = t; i < s_n; i += 256) {
            unsigned gi = s_gbase + i;
            if (gi < CAND_CAP) { g_cand[gi] = s_cand[i]; g_capprox[gi] = s_appr[i]; }
        }
        __syncthreads();
    }

    if (t < 128) {
        int gv = vb + t;
        if (gv < V_) g_amax[(size_t)b * V_ + gv] = rmax[t];
    }
}

// ---------------- refinement: exact fp32 dots for surviving candidates ----------------
__global__ void refine_kernel() {
    unsigned count = min(g_ccount, CAND_CAP);
    int lane = threadIdx.x & 31;
    unsigned w = (blockIdx.x * blockDim.x + threadIdx.x) >> 5;
    unsigned nw = (gridDim.x * blockDim.x) >> 5;
    for (unsigned i = w; i < count; i += nw) {
        float ap = g_capprox[i];
        unsigned c = g_cand[i];
        unsigned bv = c >> 10;
        if (ap < g_amax[bv] - MARGIN) continue;     // prune vs final approx max
        unsigned tok = c & 1023u;
        unsigned b = bv / V_, v = bv - b * V_;
        const float* x = g_ptf + ((size_t)b * N_ + tok) * D_;
        const float* p = g_proto + (size_t)v * D_;
        float s = 0.f;
        #pragma unroll
        for (int jj = 0; jj < 6; jj++) {
            float4 xa = *(const float4*)(x + ((jj << 5) + lane) * 4);
            float4 pa = *(const float4*)(p + ((jj << 5) + lane) * 4);
            s += xa.x * pa.x + xa.y * pa.y + xa.z * pa.z + xa.w * pa.w;
        }
        s = warpSum(s);
        if (lane == 0) atomicMax(&g_okey[bv], fkey(s));
    }
}

// okey==0 => no refined candidate (overflow drop) -> fall back to approx max (bounded err)
__global__ void finalize_kernel(float* __restrict__ out) {
    int i = blockIdx.x * 256 + threadIdx.x;
    if (i < B_ * V_) {
        unsigned k = g_okey[i];
        out[i] = k ? funkey(k) : g_amax[i];
    }
}

// in-place softmax over V per batch row
__global__ void softmax_kernel(float* __restrict__ out) {
    int b = blockIdx.x;
    float* row = out + (size_t)b * V_;
    __shared__ float sb[33];
    int t = threadIdx.x, lane = t & 31, w = t >> 5;

    float m = -1e30f;
    for (int v = t; v < V_; v += 1024) m = fmaxf(m, row[v]);
    #pragma unroll
    for (int o = 16; o; o >>= 1) m = fmaxf(m, __shfl_xor_sync(0xffffffffu, m, o));
    if (lane == 0) sb[w] = m;
    __syncthreads();
    if (t == 0) {
        float mm = -1e30f;
        for (int i = 0; i < 32; i++) mm = fmaxf(mm, sb[i]);
        sb[32] = mm;
    }
    __syncthreads();
    float M = sb[32];

    float s = 0.f;
    for (int v = t; v < V_; v += 1024) s += expf((row[v] - M) * INV_T);
    s = warpSum(s);
    __syncthreads();
    if (lane == 0) sb[w] = s;
    __syncthreads();
    if (t == 0) {
        float ss = 0.f;
        for (int i = 0; i < 32; i++) ss += sb[i];
        sb[32] = ss;
    }
    __syncthreads();
    float inv = 1.0f / sb[32];
    for (int v = t; v < V_; v += 1024) row[v] = expf((row[v] - M) * INV_T) * inv;
}

// ---------------- launch ----------------
extern "C" void kernel_launch(void* const* d_in, const int* in_sizes, int n_in,
                              void* d_out, int out_size) {
    const float* patch = (const float*)d_in[0];
    const float* vocab = (const float*)d_in[1];
    const float* W1    = (const float*)d_in[2];
    const float* gamma = (const float*)d_in[3];
    const float* beta  = (const float*)d_in[4];
    const float* W2    = (const float*)d_in[5];
    const float* b2    = (const float*)d_in[6];
    float* out = (float*)d_out;

    const int VT = (V_ + 127) / 128;   // 235

    vnorm_split_kernel<<<V_, 256>>>(vocab);
    ptnorm_kernel<<<B_ * N_, 256>>>(patch);
    w1t_kernel<<<Hh_, 256>>>(W1);
    w2t_kernel<<<D_, 256>>>(W2);
    zero_kernel<<<256, 256>>>();
    gemm1_bf16_kernel<<<dim3(Hh_ / 128, VT), 256>>>();
    bnstats_kernel<<<dim3(3, 32), 256>>>();
    bnfinal_kernel<<<1, Hh_>>>(gamma, beta);
    hsplit_kernel<<<V_, 256>>>();
    gemm2_bf16_kernel<<<dim3(D_ / 128, VT), 256>>>(b2);
    pnorm_kernel<<<V_, 256>>>();
    k5_mma_kernel<<<dim3(B_, VT), 256>>>();
    refine_kernel<<<512, 256>>>();
    finalize_kernel<<<(B_ * V_ + 255) / 256, 256>>>(out);
    softmax_kernel<<<B_, 1024>>>(out);
}

// round 12
// speedup vs baseline: 4.1827x; 1.0273x over previous
#include <cuda_runtime.h>
#include <cuda_bf16.h>
#include <math.h>
#include <stdint.h>

#define B_  8
#define N_  1024
#define D_  768
#define V_  30000
#define C_  512
#define Hh_ 768
#define INV_T 5.0f
#define BN_EPS 1e-5f
#define MARGIN 0.002f
#define CAND_CAP (4u * 1024u * 1024u)
#define SCAP 2048
#define TILE_B 16384
#define BUF_B  32768

// ---------------- scratch (static device globals; no allocs allowed) ----------------
__device__ float g_h[(size_t)V_ * Hh_];
__device__ float g_proto[(size_t)V_ * D_];     // fp32 prototypes (normalized in place)
__device__ float g_ptf[(size_t)B_ * N_ * D_];  // fp32 normalized tokens
__device__ float g_colsum[Hh_], g_colsq[Hh_];
__device__ float g_scale[Hh_], g_shift[Hh_];
// split operands
__device__ __nv_bfloat16 g_vn_hi[(size_t)V_ * C_], g_vn_lo[(size_t)V_ * C_];
__device__ __nv_bfloat16 g_w1t_hi[(size_t)Hh_ * C_], g_w1t_lo[(size_t)Hh_ * C_];
__device__ __nv_bfloat16 g_hb_hi[(size_t)V_ * Hh_], g_hb_lo[(size_t)V_ * Hh_];
__device__ __nv_bfloat16 g_w2t_hi[(size_t)D_ * Hh_], g_w2t_lo[(size_t)D_ * Hh_];
__device__ __nv_bfloat16 g_proto_hi[(size_t)V_ * D_];
__device__ __nv_bfloat16 g_pt_hi[(size_t)B_ * N_ * D_];
// candidate machinery
__device__ unsigned g_ccount;
__device__ unsigned g_cand[CAND_CAP];
__device__ float g_capprox[CAND_CAP];
__device__ float g_amax[(size_t)B_ * V_];
__device__ unsigned g_okey[(size_t)B_ * V_];

// ---------------- helpers ----------------
__device__ __forceinline__ uint32_t smem_u32(const void* p) {
    uint32_t a;
    asm("{ .reg .u64 t; cvta.to.shared.u64 t, %1; cvt.u32.u64 %0, t; }" : "=r"(a) : "l"(p));
    return a;
}
__device__ __forceinline__ float warpSum(float v) {
    #pragma unroll
    for (int o = 16; o; o >>= 1) v += __shfl_xor_sync(0xffffffffu, v, o);
    return v;
}
__device__ float blockSumAll(float v) {
    __shared__ float sb[33];
    int lane = threadIdx.x & 31, w = threadIdx.x >> 5;
    v = warpSum(v);
    if (lane == 0) sb[w] = v;
    __syncthreads();
    if (threadIdx.x == 0) {
        float s = 0.f;
        int nw = (blockDim.x + 31) >> 5;
        for (int i = 0; i < nw; i++) s += sb[i];
        sb[32] = s;
    }
    __syncthreads();
    return sb[32];
}
__device__ __forceinline__ void split_bf16(float x, __nv_bfloat16& hi, __nv_bfloat16& lo) {
    hi = __float2bfloat16_rn(x);
    lo = __float2bfloat16_rn(x - __bfloat162float(hi));
}
__device__ __forceinline__ unsigned fkey(float f) {
    unsigned u = __float_as_uint(f);
    return (u & 0x80000000u) ? ~u : (u | 0x80000000u);
}
__device__ __forceinline__ float funkey(unsigned k) {
    return (k & 0x80000000u) ? __uint_as_float(k ^ 0x80000000u) : __uint_as_float(~k);
}
__device__ __forceinline__ void ldsm_x4(uint32_t addr, uint32_t& r0, uint32_t& r1,
                                        uint32_t& r2, uint32_t& r3) {
    asm volatile("ldmatrix.sync.aligned.m8n8.x4.shared.b16 {%0,%1,%2,%3}, [%4];"
                 : "=r"(r0), "=r"(r1), "=r"(r2), "=r"(r3) : "r"(addr));
}
__device__ __forceinline__ void mma_bf16(float* d, const uint32_t* a, uint32_t b0, uint32_t b1) {
    asm volatile(
        "mma.sync.aligned.m16n8k16.row.col.f32.bf16.bf16.f32 "
        "{%0,%1,%2,%3}, {%4,%5,%6,%7}, {%8,%9}, {%0,%1,%2,%3};"
        : "+f"(d[0]), "+f"(d[1]), "+f"(d[2]), "+f"(d[3])
        : "r"(a[0]), "r"(a[1]), "r"(a[2]), "r"(a[3]), "r"(b0), "r"(b1));
}
#define CP_COMMIT() asm volatile("cp.async.commit_group;" ::: "memory")
#define CP_WAIT(n)  asm volatile("cp.async.wait_group %0;" :: "n"(n) : "memory")

// async stage one 128x64 bf16 tile (row-major, swizzled) into smem at dstbase
__device__ __forceinline__ void load_tile_async(uint32_t dstbase,
                                                const __nv_bfloat16* __restrict__ src,
                                                int rowbase, int kb, int ldk, int rowmax) {
    const int t = threadIdx.x;
    #pragma unroll
    for (int s = 0; s < 4; s++) {
        int idx = t + s * 256;
        int row = idx >> 3, kq = idx & 7;
        int gr = rowbase + row;
        uint32_t off = (uint32_t)(row << 7) + (uint32_t)(kq << 4);
        off ^= (uint32_t)(row & 7) << 4;
        const void* gp = (const void*)(src + (size_t)gr * ldk + kb + kq * 8);
        int sz = (gr < rowmax) ? 16 : 0;
        asm volatile("cp.async.cg.shared.global [%0], [%1], 16, %2;"
                     :: "r"(dstbase + off), "l"(gp), "r"(sz) : "memory");
    }
}

// ---------------- elementwise / prep kernels ----------------
__global__ void vnorm_split_kernel(const float* __restrict__ vocab) {
    int r = blockIdx.x;
    const float* row = vocab + (size_t)r * C_;
    int t = threadIdx.x;
    float x0 = row[t], x1 = row[t + 256];
    float s = blockSumAll(x0 * x0 + x1 * x1);
    float inv = 1.0f / fmaxf(sqrtf(s), 1e-12f);
    size_t o = (size_t)r * C_;
    __nv_bfloat16 h, l;
    split_bf16(x0 * inv, h, l); g_vn_hi[o + t] = h;       g_vn_lo[o + t] = l;
    split_bf16(x1 * inv, h, l); g_vn_hi[o + t + 256] = h; g_vn_lo[o + t + 256] = l;
}

__global__ void ptnorm_kernel(const float* __restrict__ pt) {
    int r = blockIdx.x;
    const float* row = pt + (size_t)r * D_;
    int t = threadIdx.x;
    float x0 = row[t], x1 = row[t + 256], x2 = row[t + 512];
    float s = blockSumAll(x0 * x0 + x1 * x1 + x2 * x2);
    float inv = 1.0f / fmaxf(sqrtf(s), 1e-12f);
    size_t o = (size_t)r * D_;
    float y0 = x0 * inv, y1 = x1 * inv, y2 = x2 * inv;
    g_ptf[o + t] = y0; g_ptf[o + t + 256] = y1; g_ptf[o + t + 512] = y2;
    g_pt_hi[o + t] = __float2bfloat16_rn(y0);
    g_pt_hi[o + t + 256] = __float2bfloat16_rn(y1);
    g_pt_hi[o + t + 512] = __float2bfloat16_rn(y2);
}

__global__ void w1t_kernel(const float* __restrict__ W1) {
    int n = blockIdx.x;
    for (int k = threadIdx.x; k < C_; k += 256) {
        __nv_bfloat16 h, l;
        split_bf16(W1[(size_t)k * Hh_ + n], h, l);
        g_w1t_hi[(size_t)n * C_ + k] = h;
        g_w1t_lo[(size_t)n * C_ + k] = l;
    }
}
__global__ void w2t_kernel(const float* __restrict__ W2) {
    int n = blockIdx.x;
    for (int k = threadIdx.x; k < Hh_; k += 256) {
        __nv_bfloat16 h, l;
        split_bf16(W2[(size_t)k * D_ + n], h, l);
        g_w2t_hi[(size_t)n * Hh_ + k] = h;
        g_w2t_lo[(size_t)n * Hh_ + k] = l;
    }
}

__global__ void zero_kernel() {
    int i = blockIdx.x * 256 + threadIdx.x;
    if (i < Hh_) { g_colsum[i] = 0.f; g_colsq[i] = 0.f; }
    if (i == 0) g_ccount = 0;
    for (int j = i; j < B_ * V_; j += gridDim.x * 256) g_okey[j] = 0u;
}

__global__ void bnstats_kernel() {
    int c = blockIdx.x * 256 + threadIdx.x;
    int chunk = blockIdx.y;
    const int RC = (V_ + 31) / 32;
    int r0 = chunk * RC, r1 = min(V_, r0 + RC);
    float s = 0.f, sq = 0.f;
    for (int r = r0; r < r1; r++) {
        float x = g_h[(size_t)r * Hh_ + c];
        s += x; sq += x * x;
    }
    atomicAdd(&g_colsum[c], s);
    atomicAdd(&g_colsq[c], sq);
}

__global__ void bnfinal_kernel(const float* __restrict__ gamma, const float* __restrict__ beta) {
    int c = threadIdx.x;
    if (c < Hh_) {
        float mean = g_colsum[c] / (float)V_;
        float var = g_colsq[c] / (float)V_ - mean * mean;
        float sc = gamma[c] / sqrtf(var + BN_EPS);
        g_scale[c] = sc;
        g_shift[c] = beta[c] - mean * sc;
    }
}

__global__ void hsplit_kernel() {
    int r = blockIdx.x;
    int t = threadIdx.x;
    size_t o = (size_t)r * Hh_;
    #pragma unroll
    for (int p = 0; p < 3; p++) {
        int c = t + p * 256;
        float y = fmaxf(fmaf(g_h[o + c], g_scale[c], g_shift[c]), 0.f);
        __nv_bfloat16 h, l;
        split_bf16(y, h, l);
        g_hb_hi[o + c] = h; g_hb_lo[o + c] = l;
    }
}

// proto row norm in place (fp32) + bf16 hi
__global__ void pnorm_kernel() {
    int r = blockIdx.x;
    float* row = g_proto + (size_t)r * D_;
    int t = threadIdx.x;
    float x0 = row[t], x1 = row[t + 256], x2 = row[t + 512];
    float s = blockSumAll(x0 * x0 + x1 * x1 + x2 * x2);
    float inv = 1.0f / fmaxf(sqrtf(s), 1e-12f);
    float y0 = x0 * inv, y1 = x1 * inv, y2 = x2 * inv;
    row[t] = y0; row[t + 256] = y1; row[t + 512] = y2;
    size_t o = (size_t)r * D_;
    g_proto_hi[o + t] = __float2bfloat16_rn(y0);
    g_proto_hi[o + t + 256] = __float2bfloat16_rn(y1);
    g_proto_hi[o + t + 512] = __float2bfloat16_rn(y2);
}

// ---------------- MMA fragment compute on one buffered chunk ----------------
__device__ __forceinline__ void mma_chunk(uint32_t sA, uint32_t sB, float acc[2][8][4],
                                          int rowA, uint32_t swA, uint32_t kselA,
                                          int rowBn, uint32_t swB, uint32_t kselB) {
    #pragma unroll
    for (int ks = 0; ks < 4; ks++) {
        uint32_t a[2][4];
        #pragma unroll
        for (int mf = 0; mf < 2; mf++) {
            uint32_t addr = sA + (uint32_t)((rowA + mf * 16) << 7)
                          + (((uint32_t)(ks * 32) + kselA) ^ swA);
            ldsm_x4(addr, a[mf][0], a[mf][1], a[mf][2], a[mf][3]);
        }
        uint32_t bf[4][4];
        #pragma unroll
        for (int nf2 = 0; nf2 < 4; nf2++) {
            uint32_t addr = sB + (uint32_t)((rowBn + nf2 * 16) << 7)
                          + (((uint32_t)(ks * 32) + kselB) ^ swB);
            ldsm_x4(addr, bf[nf2][0], bf[nf2][1], bf[nf2][2], bf[nf2][3]);
        }
        #pragma unroll
        for (int mf = 0; mf < 2; mf++)
            #pragma unroll
            for (int nf = 0; nf < 8; nf++)
                mma_bf16(acc[mf][nf], a[mf],
                         bf[nf >> 1][(nf & 1) * 2], bf[nf >> 1][(nf & 1) * 2 + 1]);
    }
}

// ---------------- double-buffered 3-pass split-bf16 HMMA GEMM (device body) ----------------
// NOTE: global-symbol pointers bound in DEVICE code (wrappers) — host-side symbol
// passing is UB; GB300 ATS silently dereferences the host shadow (R7/R8 root cause).
__device__ __forceinline__ void hgemm3_body(
    const __nv_bfloat16* __restrict__ Ah, const __nv_bfloat16* __restrict__ Al,
    const __nv_bfloat16* __restrict__ Bth, const __nv_bfloat16* __restrict__ Btl,
    float* __restrict__ C, const float* __restrict__ bias, int K) {
    extern __shared__ char dynsmem[];
    const uint32_t sbase = smem_u32(dynsmem);
    const int t = threadIdx.x;
    const int lane = t & 31, wid = t >> 5;
    const int wm = wid >> 1, wn = wid & 1;
    const int mb = blockIdx.y * 128, nb = blockIdx.x * 128;

    const int rowA = wm * 32 + (lane & 15);
    const uint32_t swA = (uint32_t)(rowA & 7) << 4;
    const uint32_t kselA = (uint32_t)(lane >> 4) << 4;
    const int rowBn = wn * 64 + ((lane >> 4) << 3) + (lane & 7);
    const uint32_t swB = (uint32_t)(lane & 7) << 4;
    const uint32_t kselB = (uint32_t)((lane >> 3) & 1) << 4;

    float acc[2][8][4];
    #pragma unroll
    for (int mf = 0; mf < 2; mf++)
        #pragma unroll
        for (int nf = 0; nf < 8; nf++)
            #pragma unroll
            for (int e = 0; e < 4; e++) acc[mf][nf][e] = 0.f;

    const int nchunk = K >> 6;
    const int TOT = 3 * nchunk;

    // prefetch iteration 0
    {
        load_tile_async(sbase, Ah, mb, 0, K, V_);
        load_tile_async(sbase + TILE_B, Bth, nb, 0, K, 1 << 30);
        CP_COMMIT();
    }
    #pragma unroll 1
    for (int it = 0; it < TOT; it++) {
        uint32_t bufb = sbase + (uint32_t)(it & 1) * BUF_B;
        if (it + 1 < TOT) {
            int it2 = it + 1;
            int pass2 = it2 / nchunk, ch2 = it2 - pass2 * nchunk;
            const __nv_bfloat16* Asrc = (pass2 < 2) ? Ah : Al;
            const __nv_bfloat16* Bsrc = (pass2 == 1) ? Btl : Bth;
            uint32_t nxt = sbase + (uint32_t)(it2 & 1) * BUF_B;
            load_tile_async(nxt, Asrc, mb, ch2 * 64, K, V_);
            load_tile_async(nxt + TILE_B, Bsrc, nb, ch2 * 64, K, 1 << 30);
            CP_COMMIT();
            CP_WAIT(1);
        } else {
            CP_WAIT(0);
        }
        __syncthreads();
        mma_chunk(bufb, bufb + TILE_B, acc, rowA, swA, kselA, rowBn, swB, kselB);
        __syncthreads();
    }
    #pragma unroll
    for (int mf = 0; mf < 2; mf++)
        #pragma unroll
        for (int h = 0; h < 2; h++) {
            int row = mb + wm * 32 + mf * 16 + (lane >> 2) + h * 8;
            if (row >= V_) continue;
            #pragma unroll
            for (int nf = 0; nf < 8; nf++) {
                int col = nb + wn * 64 + nf * 8 + (lane & 3) * 2;
                float2 v;
                v.x = acc[mf][nf][h * 2 + 0];
                v.y = acc[mf][nf][h * 2 + 1];
                if (bias) { v.x += bias[col]; v.y += bias[col + 1]; }
                *(float2*)(C + (size_t)row * 768 + col) = v;
            }
        }
}

__global__ __launch_bounds__(256, 2) void gemm1_bf16_kernel() {
    hgemm3_body(g_vn_hi, g_vn_lo, g_w1t_hi, g_w1t_lo, g_h, nullptr, C_);
}
__global__ __launch_bounds__(256, 2) void gemm2_bf16_kernel(const float* __restrict__ b2) {
    hgemm3_body(g_hb_hi, g_hb_lo, g_w2t_hi, g_w2t_lo, g_proto, b2, Hh_);
}

// ---------------- 1-pass double-buffered HMMA logits + fused max + candidates ----------------
__global__ __launch_bounds__(256, 2) void k5_mma_kernel() {
    extern __shared__ char dynsmem[];
    __shared__ float redbuf[2][128];
    __shared__ float rmax[128];
    __shared__ unsigned s_cnt, s_gbase, s_n;
    __shared__ unsigned s_cand[SCAP];
    __shared__ float s_appr[SCAP];

    const uint32_t sbase = smem_u32(dynsmem);
    const int t = threadIdx.x;
    const int lane = t & 31, wid = t >> 5;
    const int wm = wid >> 1, wn = wid & 1;
    const int b = blockIdx.x;                 // batch fastest -> proto tiles shared in L2
    const int vb = blockIdx.y * 128;

    if (t < 128) rmax[t] = -1e30f;
    if (t == 0) s_cnt = 0;

    const int rowA = wm * 32 + (lane & 15);
    const uint32_t swA = (uint32_t)(rowA & 7) << 4;
    const uint32_t kselA = (uint32_t)(lane >> 4) << 4;
    const int rowBn = wn * 64 + ((lane >> 4) << 3) + (lane & 7);
    const uint32_t swB = (uint32_t)(lane & 7) << 4;
    const uint32_t kselB = (uint32_t)((lane >> 3) & 1) << 4;

    float acc[2][8][4];
    const int TOT = 96;                       // 8 token tiles x 12 chunks

    // prefetch iteration 0
    load_tile_async(sbase, g_proto_hi, vb, 0, D_, V_);
    load_tile_async(sbase + TILE_B, g_pt_hi, b * N_, 0, D_, 1 << 30);
    CP_COMMIT();

    #pragma unroll 1
    for (int it = 0; it < TOT; it++) {
        const int tt = it / 12, chunk = it - tt * 12;
        if (chunk == 0) {
            #pragma unroll
            for (int mf = 0; mf < 2; mf++)
                #pragma unroll
                for (int nf = 0; nf < 8; nf++)
                    #pragma unroll
                    for (int e = 0; e < 4; e++) acc[mf][nf][e] = 0.f;
        }
        uint32_t bufb = sbase + (uint32_t)(it & 1) * BUF_B;
        if (it + 1 < TOT) {
            int it2 = it + 1;
            int tt2 = it2 / 12, ch2 = it2 - tt2 * 12;
            uint32_t nxt = sbase + (uint32_t)(it2 & 1) * BUF_B;
            load_tile_async(nxt, g_proto_hi, vb, ch2 * 64, D_, V_);
            load_tile_async(nxt + TILE_B, g_pt_hi, b * N_ + tt2 * 128, ch2 * 64, D_, 1 << 30);
            CP_COMMIT();
            CP_WAIT(1);
        } else {
            CP_WAIT(0);
        }
        __syncthreads();
        mma_chunk(bufb, bufb + TILE_B, acc, rowA, swA, kselA, rowBn, swB, kselB);

        if (chunk == 11) {
            // ---- per-v max over this 128-token tile ----
            float m4[2][2];
            #pragma unroll
            for (int mf = 0; mf < 2; mf++)
                #pragma unroll
                for (int h = 0; h < 2; h++) {
                    float m = -1e30f;
                    #pragma unroll
                    for (int nf = 0; nf < 8; nf++)
                        m = fmaxf(m, fmaxf(acc[mf][nf][h * 2], acc[mf][nf][h * 2 + 1]));
                    m4[mf][h] = m;
                }
            #pragma unroll
            for (int mf = 0; mf < 2; mf++)
                #pragma unroll
                for (int h = 0; h < 2; h++) {
                    float m = m4[mf][h];
                    m = fmaxf(m, __shfl_xor_sync(0xffffffffu, m, 1));
                    m = fmaxf(m, __shfl_xor_sync(0xffffffffu, m, 2));
                    m4[mf][h] = m;
                }
            __syncthreads();
            if ((lane & 3) == 0) {
                #pragma unroll
                for (int mf = 0; mf < 2; mf++)
                    #pragma unroll
                    for (int h = 0; h < 2; h++)
                        redbuf[wn][wm * 32 + mf * 16 + (lane >> 2) + h * 8] = m4[mf][h];
            }
            __syncthreads();
            if (t < 128) rmax[t] = fmaxf(rmax[t], fmaxf(redbuf[0][t], redbuf[1][t]));
            __syncthreads();

            // ---- record candidates within MARGIN of running max ----
            #pragma unroll
            for (int mf = 0; mf < 2; mf++)
                #pragma unroll
                for (int h = 0; h < 2; h++) {
                    int lrow = wm * 32 + mf * 16 + (lane >> 2) + h * 8;
                    int gv = vb + lrow;
                    if (gv >= V_) continue;
                    float thr = rmax[lrow] - MARGIN;
                    #pragma unroll
                    for (int nf = 0; nf < 8; nf++)
                        #pragma unroll
                        for (int e2 = 0; e2 < 2; e2++) {
                            float val = acc[mf][nf][h * 2 + e2];
                            if (val >= thr) {
                                unsigned pos = atomicAdd(&s_cnt, 1u);
                                if (pos < SCAP) {
                                    int tok = tt * 128 + wn * 64 + nf * 8 + (lane & 3) * 2 + e2;
                                    s_cand[pos] = ((unsigned)(b * V_ + gv) << 10) | (unsigned)tok;
                                    s_appr[pos] = val;
                                }
                            }
                        }
                }
            __syncthreads();
            if (t == 0) {
                unsigned n = min(s_cnt, (unsigned)SCAP);
                s_gbase = atomicAdd(&g_ccount, n);
                s_n = n;
                s_cnt = 0;
            }
            __syncthreads();
            for (unsigned i = t; i < s_n; i += 256) {
                unsigned gi = s_gbase + i;
                if (gi < CAND_CAP) { g_cand[gi] = s_cand[i]; g_capprox[gi] = s_appr[i]; }
            }
        }
        __syncthreads();
    }

    if (t < 128) {
        int gv = vb + t;
        if (gv < V_) g_amax[(size_t)b * V_ + gv] = rmax[t];
    }
}

// ---------------- refinement: exact fp32 dots for surviving candidates ----------------
__global__ void refine_kernel() {
    unsigned count = min(g_ccount, CAND_CAP);
    int lane = threadIdx.x & 31;
    unsigned w = (blockIdx.x * blockDim.x + threadIdx.x) >> 5;
    unsigned nw = (gridDim.x * blockDim.x) >> 5;
    for (unsigned i = w; i < count; i += nw) {
        float ap = g_capprox[i];
        unsigned c = g_cand[i];
        unsigned bv = c >> 10;
        if (ap < g_amax[bv] - MARGIN) continue;     // prune vs final approx max
        unsigned tok = c & 1023u;
        unsigned b = bv / V_, v = bv - b * V_;
        const float* x = g_ptf + ((size_t)b * N_ + tok) * D_;
        const float* p = g_proto + (size_t)v * D_;
        float s = 0.f;
        #pragma unroll
        for (int jj = 0; jj < 6; jj++) {
            float4 xa = *(const float4*)(x + ((jj << 5) + lane) * 4);
            float4 pa = *(const float4*)(p + ((jj << 5) + lane) * 4);
            s += xa.x * pa.x + xa.y * pa.y + xa.z * pa.z + xa.w * pa.w;
        }
        s = warpSum(s);
        if (lane == 0) atomicMax(&g_okey[bv], fkey(s));
    }
}

// okey==0 => no refined candidate (overflow drop) -> fall back to approx max (bounded err)
__global__ void finalize_kernel(float* __restrict__ out) {
    int i = blockIdx.x * 256 + threadIdx.x;
    if (i < B_ * V_) {
        unsigned k = g_okey[i];
        out[i] = k ? funkey(k) : g_amax[i];
    }
}

// in-place softmax over V per batch row
__global__ void softmax_kernel(float* __restrict__ out) {
    int b = blockIdx.x;
    float* row = out + (size_t)b * V_;
    __shared__ float sb[33];
    int t = threadIdx.x, lane = t & 31, w = t >> 5;

    float m = -1e30f;
    for (int v = t; v < V_; v += 1024) m = fmaxf(m, row[v]);
    #pragma unroll
    for (int o = 16; o; o >>= 1) m = fmaxf(m, __shfl_xor_sync(0xffffffffu, m, o));
    if (lane == 0) sb[w] = m;
    __syncthreads();
    if (t == 0) {
        float mm = -1e30f;
        for (int i = 0; i < 32; i++) mm = fmaxf(mm, sb[i]);
        sb[32] = mm;
    }
    __syncthreads();
    float M = sb[32];

    float s = 0.f;
    for (int v = t; v < V_; v += 1024) s += expf((row[v] - M) * INV_T);
    s = warpSum(s);
    __syncthreads();
    if (lane == 0) sb[w] = s;
    __syncthreads();
    if (t == 0) {
        float ss = 0.f;
        for (int i = 0; i < 32; i++) ss += sb[i];
        sb[32] = ss;
    }
    __syncthreads();
    float inv = 1.0f / sb[32];
    for (int v = t; v < V_; v += 1024) row[v] = expf((row[v] - M) * INV_T) * inv;
}

// ---------------- launch ----------------
extern "C" void kernel_launch(void* const* d_in, const int* in_sizes, int n_in,
                              void* d_out, int out_size) {
    const float* patch = (const float*)d_in[0];
    const float* vocab = (const float*)d_in[1];
    const float* W1    = (const float*)d_in[2];
    const float* gamma = (const float*)d_in[3];
    const float* beta  = (const float*)d_in[4];
    const float* W2    = (const float*)d_in[5];
    const float* b2    = (const float*)d_in[6];
    float* out = (float*)d_out;

    const int VT = (V_ + 127) / 128;   // 235
    const int DYN = 2 * BUF_B;         // 64KB double buffer

    cudaFuncSetAttribute(gemm1_bf16_kernel, cudaFuncAttributeMaxDynamicSharedMemorySize, DYN);
    cudaFuncSetAttribute(gemm2_bf16_kernel, cudaFuncAttributeMaxDynamicSharedMemorySize, DYN);
    cudaFuncSetAttribute(k5_mma_kernel, cudaFuncAttributeMaxDynamicSharedMemorySize, DYN);

    vnorm_split_kernel<<<V_, 256>>>(vocab);
    ptnorm_kernel<<<B_ * N_, 256>>>(patch);
    w1t_kernel<<<Hh_, 256>>>(W1);
    w2t_kernel<<<D_, 256>>>(W2);
    zero_kernel<<<256, 256>>>();
    gemm1_bf16_kernel<<<dim3(Hh_ / 128, VT), 256, DYN>>>();
    bnstats_kernel<<<dim3(3, 32), 256>>>();
    bnfinal_kernel<<<1, Hh_>>>(gamma, beta);
    hsplit_kernel<<<V_, 256>>>();
    gemm2_bf16_kernel<<<dim3(D_ / 128, VT), 256, DYN>>>(b2);
    pnorm_kernel<<<V_, 256>>>();
    k5_mma_kernel<<<dim3(B_, VT), 256, DYN>>>();
    refine_kernel<<<512, 256>>>();
    finalize_kernel<<<(B_ * V_ + 255) / 256, 256>>>(out);
    softmax_kernel<<<B_, 1024>>>(out);
}

// round 14
// speedup vs baseline: 4.2865x; 1.0248x over previous
#include <cuda_runtime.h>
#include <cuda_bf16.h>
#include <math.h>
#include <stdint.h>

#define B_  8
#define N_  1024
#define D_  768
#define V_  30000
#define C_  512
#define Hh_ 768
#define INV_T 5.0f
#define BN_EPS 1e-5f
#define MARGIN 0.002f
#define RMARGIN 0.001f
#define CAND_CAP (4u * 1024u * 1024u)
#define SCAP 2048
#define TILE_B 16384
#define BUF_B  32768

// ---------------- scratch (static device globals; no allocs allowed) ----------------
__device__ float g_h[(size_t)V_ * Hh_];
__device__ float g_proto[(size_t)V_ * D_];     // fp32 prototypes (normalized in place)
__device__ float g_ptf[(size_t)B_ * N_ * D_];  // fp32 normalized tokens
__device__ float g_colsum[Hh_], g_colsq[Hh_];
__device__ float g_scale[Hh_], g_shift[Hh_];
// split operands
__device__ __nv_bfloat16 g_vn_hi[(size_t)V_ * C_], g_vn_lo[(size_t)V_ * C_];
__device__ __nv_bfloat16 g_w1t_hi[(size_t)Hh_ * C_], g_w1t_lo[(size_t)Hh_ * C_];
__device__ __nv_bfloat16 g_hb_hi[(size_t)V_ * Hh_], g_hb_lo[(size_t)V_ * Hh_];
__device__ __nv_bfloat16 g_w2t_hi[(size_t)D_ * Hh_], g_w2t_lo[(size_t)D_ * Hh_];
__device__ __nv_bfloat16 g_proto_hi[(size_t)V_ * D_];
__device__ __nv_bfloat16 g_pt_hi[(size_t)B_ * N_ * D_];
// candidate machinery
__device__ unsigned g_ccount;
__device__ unsigned g_cand[CAND_CAP];
__device__ float g_capprox[CAND_CAP];
__device__ float g_amax[(size_t)B_ * V_];
__device__ unsigned g_okey[(size_t)B_ * V_];

// ---------------- helpers ----------------
__device__ __forceinline__ uint32_t smem_u32(const void* p) {
    uint32_t a;
    asm("{ .reg .u64 t; cvta.to.shared.u64 t, %1; cvt.u32.u64 %0, t; }" : "=r"(a) : "l"(p));
    return a;
}
__device__ __forceinline__ float warpSum(float v) {
    #pragma unroll
    for (int o = 16; o; o >>= 1) v += __shfl_xor_sync(0xffffffffu, v, o);
    return v;
}
__device__ float blockSumAll(float v) {
    __shared__ float sb[33];
    int lane = threadIdx.x & 31, w = threadIdx.x >> 5;
    v = warpSum(v);
    if (lane == 0) sb[w] = v;
    __syncthreads();
    if (threadIdx.x == 0) {
        float s = 0.f;
        int nw = (blockDim.x + 31) >> 5;
        for (int i = 0; i < nw; i++) s += sb[i];
        sb[32] = s;
    }
    __syncthreads();
    return sb[32];
}
__device__ __forceinline__ void split_bf16(float x, __nv_bfloat16& hi, __nv_bfloat16& lo) {
    hi = __float2bfloat16_rn(x);
    lo = __float2bfloat16_rn(x - __bfloat162float(hi));
}
__device__ __forceinline__ unsigned fkey(float f) {
    unsigned u = __float_as_uint(f);
    return (u & 0x80000000u) ? ~u : (u | 0x80000000u);
}
__device__ __forceinline__ float funkey(unsigned k) {
    return (k & 0x80000000u) ? __uint_as_float(k ^ 0x80000000u) : __uint_as_float(~k);
}
__device__ __forceinline__ void ldsm_x4(uint32_t addr, uint32_t& r0, uint32_t& r1,
                                        uint32_t& r2, uint32_t& r3) {
    asm volatile("ldmatrix.sync.aligned.m8n8.x4.shared.b16 {%0,%1,%2,%3}, [%4];"
                 : "=r"(r0), "=r"(r1), "=r"(r2), "=r"(r3) : "r"(addr));
}
__device__ __forceinline__ void mma_bf16(float* d, const uint32_t* a, uint32_t b0, uint32_t b1) {
    asm volatile(
        "mma.sync.aligned.m16n8k16.row.col.f32.bf16.bf16.f32 "
        "{%0,%1,%2,%3}, {%4,%5,%6,%7}, {%8,%9}, {%0,%1,%2,%3};"
        : "+f"(d[0]), "+f"(d[1]), "+f"(d[2]), "+f"(d[3])
        : "r"(a[0]), "r"(a[1]), "r"(a[2]), "r"(a[3]), "r"(b0), "r"(b1));
}
#define CP_COMMIT() asm volatile("cp.async.commit_group;" ::: "memory")
#define CP_WAIT(n)  asm volatile("cp.async.wait_group %0;" :: "n"(n) : "memory")

// async stage one 128x64 bf16 tile (row-major, swizzled) into smem at dstbase
__device__ __forceinline__ void load_tile_async(uint32_t dstbase,
                                                const __nv_bfloat16* __restrict__ src,
                                                int rowbase, int kb, int ldk, int rowmax) {
    const int t = threadIdx.x;
    #pragma unroll
    for (int s = 0; s < 4; s++) {
        int idx = t + s * 256;
        int row = idx >> 3, kq = idx & 7;
        int gr = rowbase + row;
        uint32_t off = (uint32_t)(row << 7) + (uint32_t)(kq << 4);
        off ^= (uint32_t)(row & 7) << 4;
        const void* gp = (const void*)(src + (size_t)gr * ldk + kb + kq * 8);
        int sz = (gr < rowmax) ? 16 : 0;
        asm volatile("cp.async.cg.shared.global [%0], [%1], 16, %2;"
                     :: "r"(dstbase + off), "l"(gp), "r"(sz) : "memory");
    }
}

// ---------------- elementwise / prep kernels ----------------
__global__ void vnorm_split_kernel(const float* __restrict__ vocab) {
    int r = blockIdx.x;
    const float* row = vocab + (size_t)r * C_;
    int t = threadIdx.x;
    float x0 = row[t], x1 = row[t + 256];
    float s = blockSumAll(x0 * x0 + x1 * x1);
    float inv = 1.0f / fmaxf(sqrtf(s), 1e-12f);
    size_t o = (size_t)r * C_;
    __nv_bfloat16 h, l;
    split_bf16(x0 * inv, h, l); g_vn_hi[o + t] = h;       g_vn_lo[o + t] = l;
    split_bf16(x1 * inv, h, l); g_vn_hi[o + t + 256] = h; g_vn_lo[o + t + 256] = l;
}

__global__ void ptnorm_kernel(const float* __restrict__ pt) {
    int r = blockIdx.x;
    const float* row = pt + (size_t)r * D_;
    int t = threadIdx.x;
    float x0 = row[t], x1 = row[t + 256], x2 = row[t + 512];
    float s = blockSumAll(x0 * x0 + x1 * x1 + x2 * x2);
    float inv = 1.0f / fmaxf(sqrtf(s), 1e-12f);
    size_t o = (size_t)r * D_;
    float y0 = x0 * inv, y1 = x1 * inv, y2 = x2 * inv;
    g_ptf[o + t] = y0; g_ptf[o + t + 256] = y1; g_ptf[o + t + 512] = y2;
    g_pt_hi[o + t] = __float2bfloat16_rn(y0);
    g_pt_hi[o + t + 256] = __float2bfloat16_rn(y1);
    g_pt_hi[o + t + 512] = __float2bfloat16_rn(y2);
}

// merged: W1T split rows [0,Hh), W2T split rows [Hh, Hh+D), zeroing [Hh+D, Hh+D+128)
__global__ void prep_kernel(const float* __restrict__ W1, const float* __restrict__ W2) {
    int blk = blockIdx.x;
    if (blk < Hh_) {
        int n = blk;
        for (int k = threadIdx.x; k < C_; k += 256) {
            __nv_bfloat16 h, l;
            split_bf16(W1[(size_t)k * Hh_ + n], h, l);
            g_w1t_hi[(size_t)n * C_ + k] = h;
            g_w1t_lo[(size_t)n * C_ + k] = l;
        }
    } else if (blk < Hh_ + D_) {
        int n = blk - Hh_;
        for (int k = threadIdx.x; k < Hh_; k += 256) {
            __nv_bfloat16 h, l;
            split_bf16(W2[(size_t)k * D_ + n], h, l);
            g_w2t_hi[(size_t)n * Hh_ + k] = h;
            g_w2t_lo[(size_t)n * Hh_ + k] = l;
        }
    } else {
        int i = (blk - Hh_ - D_) * 256 + threadIdx.x;   // 0..32767
        if (i < Hh_) { g_colsum[i] = 0.f; g_colsq[i] = 0.f; }
        if (i == 0) g_ccount = 0;
        for (int j = i; j < B_ * V_; j += 128 * 256) g_okey[j] = 0u;
    }
}

__global__ void bnfinal_kernel(const float* __restrict__ gamma, const float* __restrict__ beta) {
    int c = threadIdx.x;
    if (c < Hh_) {
        float mean = g_colsum[c] / (float)V_;
        float var = g_colsq[c] / (float)V_ - mean * mean;
        float sc = gamma[c] / sqrtf(var + BN_EPS);
        g_scale[c] = sc;
        g_shift[c] = beta[c] - mean * sc;
    }
}

__global__ void hsplit_kernel() {
    int r = blockIdx.x;
    int t = threadIdx.x;
    size_t o = (size_t)r * Hh_;
    #pragma unroll
    for (int p = 0; p < 3; p++) {
        int c = t + p * 256;
        float y = fmaxf(fmaf(g_h[o + c], g_scale[c], g_shift[c]), 0.f);
        __nv_bfloat16 h, l;
        split_bf16(y, h, l);
        g_hb_hi[o + c] = h; g_hb_lo[o + c] = l;
    }
}

// proto row norm in place (fp32) + bf16 hi
__global__ void pnorm_kernel() {
    int r = blockIdx.x;
    float* row = g_proto + (size_t)r * D_;
    int t = threadIdx.x;
    float x0 = row[t], x1 = row[t + 256], x2 = row[t + 512];
    float s = blockSumAll(x0 * x0 + x1 * x1 + x2 * x2);
    float inv = 1.0f / fmaxf(sqrtf(s), 1e-12f);
    float y0 = x0 * inv, y1 = x1 * inv, y2 = x2 * inv;
    row[t] = y0; row[t + 256] = y1; row[t + 512] = y2;
    size_t o = (size_t)r * D_;
    g_proto_hi[o + t] = __float2bfloat16_rn(y0);
    g_proto_hi[o + t + 256] = __float2bfloat16_rn(y1);
    g_proto_hi[o + t + 512] = __float2bfloat16_rn(y2);
}

// ---------------- MMA fragment compute on one buffered chunk ----------------
__device__ __forceinline__ void mma_chunk(uint32_t sA, uint32_t sB, float acc[2][8][4],
                                          int rowA, uint32_t swA, uint32_t kselA,
                                          int rowBn, uint32_t swB, uint32_t kselB) {
    #pragma unroll
    for (int ks = 0; ks < 4; ks++) {
        uint32_t a[2][4];
        #pragma unroll
        for (int mf = 0; mf < 2; mf++) {
            uint32_t addr = sA + (uint32_t)((rowA + mf * 16) << 7)
                          + (((uint32_t)(ks * 32) + kselA) ^ swA);
            ldsm_x4(addr, a[mf][0], a[mf][1], a[mf][2], a[mf][3]);
        }
        uint32_t bf[4][4];
        #pragma unroll
        for (int nf2 = 0; nf2 < 4; nf2++) {
            uint32_t addr = sB + (uint32_t)((rowBn + nf2 * 16) << 7)
                          + (((uint32_t)(ks * 32) + kselB) ^ swB);
            ldsm_x4(addr, bf[nf2][0], bf[nf2][1], bf[nf2][2], bf[nf2][3]);
        }
        #pragma unroll
        for (int mf = 0; mf < 2; mf++)
            #pragma unroll
            for (int nf = 0; nf < 8; nf++)
                mma_bf16(acc[mf][nf], a[mf],
                         bf[nf >> 1][(nf & 1) * 2], bf[nf >> 1][(nf & 1) * 2 + 1]);
    }
}

// ---------------- double-buffered 3-pass split-bf16 HMMA GEMM (device body) ----------------
// NOTE: global-symbol pointers bound in DEVICE code (wrappers) — host-side symbol
// passing is UB; GB300 ATS silently dereferences the host shadow (R7/R8 root cause).
// do_stats: fused BN column statistics (exact — zero-filled rows >= V_ contribute 0).
__device__ __forceinline__ void hgemm3_body(
    const __nv_bfloat16* __restrict__ Ah, const __nv_bfloat16* __restrict__ Al,
    const __nv_bfloat16* __restrict__ Bth, const __nv_bfloat16* __restrict__ Btl,
    float* __restrict__ C, const float* __restrict__ bias, int K, bool do_stats) {
    extern __shared__ char dynsmem[];
    const uint32_t sbase = smem_u32(dynsmem);
    const int t = threadIdx.x;
    const int lane = t & 31, wid = t >> 5;
    const int wm = wid >> 1, wn = wid & 1;
    const int mb = blockIdx.y * 128, nb = blockIdx.x * 128;

    const int rowA = wm * 32 + (lane & 15);
    const uint32_t swA = (uint32_t)(rowA & 7) << 4;
    const uint32_t kselA = (uint32_t)(lane >> 4) << 4;
    const int rowBn = wn * 64 + ((lane >> 4) << 3) + (lane & 7);
    const uint32_t swB = (uint32_t)(lane & 7) << 4;
    const uint32_t kselB = (uint32_t)((lane >> 3) & 1) << 4;

    float acc[2][8][4];
    #pragma unroll
    for (int mf = 0; mf < 2; mf++)
        #pragma unroll
        for (int nf = 0; nf < 8; nf++)
            #pragma unroll
            for (int e = 0; e < 4; e++) acc[mf][nf][e] = 0.f;

    const int nchunk = K >> 6;
    const int TOT = 3 * nchunk;

    load_tile_async(sbase, Ah, mb, 0, K, V_);
    load_tile_async(sbase + TILE_B, Bth, nb, 0, K, 1 << 30);
    CP_COMMIT();

    #pragma unroll 1
    for (int it = 0; it < TOT; it++) {
        uint32_t bufb = sbase + (uint32_t)(it & 1) * BUF_B;
        if (it + 1 < TOT) {
            int it2 = it + 1;
            int pass2 = it2 / nchunk, ch2 = it2 - pass2 * nchunk;
            const __nv_bfloat16* Asrc = (pass2 < 2) ? Ah : Al;
            const __nv_bfloat16* Bsrc = (pass2 == 1) ? Btl : Bth;
            uint32_t nxt = sbase + (uint32_t)(it2 & 1) * BUF_B;
            load_tile_async(nxt, Asrc, mb, ch2 * 64, K, V_);
            load_tile_async(nxt + TILE_B, Bsrc, nb, ch2 * 64, K, 1 << 30);
            CP_COMMIT();
            CP_WAIT(1);
        } else {
            CP_WAIT(0);
        }
        __syncthreads();
        mma_chunk(bufb, bufb + TILE_B, acc, rowA, swA, kselA, rowBn, swB, kselB);
        __syncthreads();
    }

    #pragma unroll
    for (int mf = 0; mf < 2; mf++)
        #pragma unroll
        for (int h = 0; h < 2; h++) {
            int row = mb + wm * 32 + mf * 16 + (lane >> 2) + h * 8;
            if (row >= V_) continue;
            #pragma unroll
            for (int nf = 0; nf < 8; nf++) {
                int col = nb + wn * 64 + nf * 8 + (lane & 3) * 2;
                float2 v;
                v.x = acc[mf][nf][h * 2 + 0];
                v.y = acc[mf][nf][h * 2 + 1];
                if (bias) { v.x += bias[col]; v.y += bias[col + 1]; }
                *(float2*)(C + (size_t)row * 768 + col) = v;
            }
        }

    // fused BN column stats: reduce this CTA's 128 rows per column, one atomic per (warp,col)
    if (do_stats) {
        #pragma unroll
        for (int nf = 0; nf < 8; nf++)
            #pragma unroll
            for (int e2 = 0; e2 < 2; e2++) {
                float s = 0.f, sq = 0.f;
                #pragma unroll
                for (int mf = 0; mf < 2; mf++)
                    #pragma unroll
                    for (int h = 0; h < 2; h++) {
                        float v = acc[mf][nf][h * 2 + e2];
                        s += v; sq += v * v;
                    }
                #pragma unroll
                for (int o = 4; o <= 16; o <<= 1) {
                    s += __shfl_xor_sync(0xffffffffu, s, o);
                    sq += __shfl_xor_sync(0xffffffffu, sq, o);
                }
                if (lane < 4) {
                    int col = nb + wn * 64 + nf * 8 + lane * 2 + e2;
                    atomicAdd(&g_colsum[col], s);
                    atomicAdd(&g_colsq[col], sq);
                }
            }
    }
}

__global__ __launch_bounds__(256, 2) void gemm1_bf16_kernel() {
    hgemm3_body(g_vn_hi, g_vn_lo, g_w1t_hi, g_w1t_lo, g_h, nullptr, C_, true);
}
__global__ __launch_bounds__(256, 2) void gemm2_bf16_kernel(const float* __restrict__ b2) {
    hgemm3_body(g_hb_hi, g_hb_lo, g_w2t_hi, g_w2t_lo, g_proto, b2, Hh_, false);
}

// ---------------- 1-pass double-buffered HMMA logits + fused max + candidates ----------------
__global__ __launch_bounds__(256, 2) void k5_mma_kernel() {
    extern __shared__ char dynsmem[];
    __shared__ float redbuf[2][128];
    __shared__ float rmax[128];
    __shared__ unsigned s_cnt, s_gbase, s_n;
    __shared__ unsigned s_cand[SCAP];
    __shared__ float s_appr[SCAP];

    const uint32_t sbase = smem_u32(dynsmem);
    const int t = threadIdx.x;
    const int lane = t & 31, wid = t >> 5;
    const int wm = wid >> 1, wn = wid & 1;
    const int b = blockIdx.x;                 // batch fastest -> proto tiles shared in L2
    const int vb = blockIdx.y * 128;

    if (t < 128) rmax[t] = -1e30f;
    if (t == 0) s_cnt = 0;

    const int rowA = wm * 32 + (lane & 15);
    const uint32_t swA = (uint32_t)(rowA & 7) << 4;
    const uint32_t kselA = (uint32_t)(lane >> 4) << 4;
    const int rowBn = wn * 64 + ((lane >> 4) << 3) + (lane & 7);
    const uint32_t swB = (uint32_t)(lane & 7) << 4;
    const uint32_t kselB = (uint32_t)((lane >> 3) & 1) << 4;

    float acc[2][8][4];
    const int TOT = 96;                       // 8 token tiles x 12 chunks

    load_tile_async(sbase, g_proto_hi, vb, 0, D_, V_);
    load_tile_async(sbase + TILE_B, g_pt_hi, b * N_, 0, D_, 1 << 30);
    CP_COMMIT();

    #pragma unroll 1
    for (int it = 0; it < TOT; it++) {
        const int tt = it / 12, chunk = it - tt * 12;
        if (chunk == 0) {
            #pragma unroll
            for (int mf = 0; mf < 2; mf++)
                #pragma unroll
                for (int nf = 0; nf < 8; nf++)
                    #pragma unroll
                    for (int e = 0; e < 4; e++) acc[mf][nf][e] = 0.f;
        }
        uint32_t bufb = sbase + (uint32_t)(it & 1) * BUF_B;
        if (it + 1 < TOT) {
            int it2 = it + 1;
            int tt2 = it2 / 12, ch2 = it2 - tt2 * 12;
            uint32_t nxt = sbase + (uint32_t)(it2 & 1) * BUF_B;
            load_tile_async(nxt, g_proto_hi, vb, ch2 * 64, D_, V_);
            load_tile_async(nxt + TILE_B, g_pt_hi, b * N_ + tt2 * 128, ch2 * 64, D_, 1 << 30);
            CP_COMMIT();
            CP_WAIT(1);
        } else {
            CP_WAIT(0);
        }
        __syncthreads();
        mma_chunk(bufb, bufb + TILE_B, acc, rowA, swA, kselA, rowBn, swB, kselB);

        if (chunk == 11) {
            // ---- per-v max over this 128-token tile ----
            float m4[2][2];
            #pragma unroll
            for (int mf = 0; mf < 2; mf++)
                #pragma unroll
                for (int h = 0; h < 2; h++) {
                    float m = -1e30f;
                    #pragma unroll
                    for (int nf = 0; nf < 8; nf++)
                        m = fmaxf(m, fmaxf(acc[mf][nf][h * 2], acc[mf][nf][h * 2 + 1]));
                    m4[mf][h] = m;
                }
            #pragma unroll
            for (int mf = 0; mf < 2; mf++)
                #pragma unroll
                for (int h = 0; h < 2; h++) {
                    float m = m4[mf][h];
                    m = fmaxf(m, __shfl_xor_sync(0xffffffffu, m, 1));
                    m = fmaxf(m, __shfl_xor_sync(0xffffffffu, m, 2));
                    m4[mf][h] = m;
                }
            __syncthreads();
            if ((lane & 3) == 0) {
                #pragma unroll
                for (int mf = 0; mf < 2; mf++)
                    #pragma unroll
                    for (int h = 0; h < 2; h++)
                        redbuf[wn][wm * 32 + mf * 16 + (lane >> 2) + h * 8] = m4[mf][h];
            }
            __syncthreads();
            if (t < 128) rmax[t] = fmaxf(rmax[t], fmaxf(redbuf[0][t], redbuf[1][t]));
            __syncthreads();

            // ---- record candidates within MARGIN of running max ----
            #pragma unroll
            for (int mf = 0; mf < 2; mf++)
                #pragma unroll
                for (int h = 0; h < 2; h++) {
                    int lrow = wm * 32 + mf * 16 + (lane >> 2) + h * 8;
                    int gv = vb + lrow;
                    if (gv >= V_) continue;
                    float thr = rmax[lrow] - MARGIN;
                    #pragma unroll
                    for (int nf = 0; nf < 8; nf++)
                        #pragma unroll
                        for (int e2 = 0; e2 < 2; e2++) {
                            float val = acc[mf][nf][h * 2 + e2];
                            if (val >= thr) {
                                unsigned pos = atomicAdd(&s_cnt, 1u);
                                if (pos < SCAP) {
                                    int tok = tt * 128 + wn * 64 + nf * 8 + (lane & 3) * 2 + e2;
                                    s_cand[pos] = ((unsigned)(b * V_ + gv) << 10) | (unsigned)tok;
                                    s_appr[pos] = val;
                                }
                            }
                        }
                }
            __syncthreads();
            if (t == 0) {
                unsigned n = min(s_cnt, (unsigned)SCAP);
                s_gbase = atomicAdd(&g_ccount, n);
                s_n = n;
                s_cnt = 0;
            }
            __syncthreads();
            for (unsigned i = t; i < s_n; i += 256) {
                unsigned gi = s_gbase + i;
                if (gi < CAND_CAP) { g_cand[gi] = s_cand[i]; g_capprox[gi] = s_appr[i]; }
            }
        }
        __syncthreads();
    }

    if (t < 128) {
        int gv = vb + t;
        if (gv < V_) g_amax[(size_t)b * V_ + gv] = rmax[t];
    }
}

// ---------------- refinement: exact fp32 dots for surviving candidates ----------------
// prune margin RMARGIN < recording MARGIN: amax holder always survives; misses need
// >7 sigma of bf16 logit noise (sigma ~ 1.4e-4) -> negligible, bounded by RMARGIN.
__global__ void refine_kernel() {
    unsigned count = min(g_ccount, CAND_CAP);
    int lane = threadIdx.x & 31;
    unsigned w = (blockIdx.x * blockDim.x + threadIdx.x) >> 5;
    unsigned nw = (gridDim.x * blockDim.x) >> 5;
    for (unsigned i = w; i < count; i += nw) {
        float ap = g_capprox[i];
        unsigned c = g_cand[i];
        unsigned bv = c >> 10;
        if (ap < g_amax[bv] - RMARGIN) continue;
        unsigned tok = c & 1023u;
        unsigned b = bv / V_, v = bv - b * V_;
        const float* x = g_ptf + ((size_t)b * N_ + tok) * D_;
        const float* p = g_proto + (size_t)v * D_;
        float s = 0.f;
        #pragma unroll
        for (int jj = 0; jj < 6; jj++) {
            float4 xa = *(const float4*)(x + ((jj << 5) + lane) * 4);
            float4 pa = *(const float4*)(p + ((jj << 5) + lane) * 4);
            s += xa.x * pa.x + xa.y * pa.y + xa.z * pa.z + xa.w * pa.w;
        }
        s = warpSum(s);
        if (lane == 0) atomicMax(&g_okey[bv], fkey(s));
    }
}

// ---------------- fused finalize + softmax (values staged in smem) ----------------
// okey==0 => no refined candidate (overflow drop) -> fall back to approx max
__global__ void softmax_fused_kernel(float* __restrict__ out) {
    extern __shared__ float sv[];              // V_ floats
    __shared__ float sb[33];
    int b = blockIdx.x;
    int t = threadIdx.x, lane = t & 31, w = t >> 5;
    size_t base = (size_t)b * V_;

    float m = -1e30f;
    for (int v = t; v < V_; v += 1024) {
        unsigned k = g_okey[base + v];
        float val = k ? funkey(k) : g_amax[base + v];
        sv[v] = val;
        m = fmaxf(m, val);
    }
    #pragma unroll
    for (int o = 16; o; o >>= 1) m = fmaxf(m, __shfl_xor_sync(0xffffffffu, m, o));
    if (lane == 0) sb[w] = m;
    __syncthreads();
    if (t == 0) {
        float mm = -1e30f;
        for (int i = 0; i < 32; i++) mm = fmaxf(mm, sb[i]);
        sb[32] = mm;
    }
    __syncthreads();
    float M = sb[32];

    float s = 0.f;
    for (int v = t; v < V_; v += 1024) {
        float e = expf((sv[v] - M) * INV_T);
        sv[v] = e;
        s += e;
    }
    s = warpSum(s);
    __syncthreads();
    if (lane == 0) sb[w] = s;
    __syncthreads();
    if (t == 0) {
        float ss = 0.f;
        for (int i = 0; i < 32; i++) ss += sb[i];
        sb[32] = ss;
    }
    __syncthreads();
    float inv = 1.0f / sb[32];
    for (int v = t; v < V_; v += 1024) out[base + v] = sv[v] * inv;
}

// ---------------- launch ----------------
extern "C" void kernel_launch(void* const* d_in, const int* in_sizes, int n_in,
                              void* d_out, int out_size) {
    const float* patch = (const float*)d_in[0];
    const float* vocab = (const float*)d_in[1];
    const float* W1    = (const float*)d_in[2];
    const float* gamma = (const float*)d_in[3];
    const float* beta  = (const float*)d_in[4];
    const float* W2    = (const float*)d_in[5];
    const float* b2    = (const float*)d_in[6];
    float* out = (float*)d_out;

    const int VT = (V_ + 127) / 128;   // 235
    const int DYN = 2 * BUF_B;         // 64KB double buffer
    const int SMX = V_ * 4;            // 120KB softmax value cache

    cudaFuncSetAttribute(gemm1_bf16_kernel, cudaFuncAttributeMaxDynamicSharedMemorySize, DYN);
    cudaFuncSetAttribute(gemm2_bf16_kernel, cudaFuncAttributeMaxDynamicSharedMemorySize, DYN);
    cudaFuncSetAttribute(k5_mma_kernel, cudaFuncAttributeMaxDynamicSharedMemorySize, DYN);
    cudaFuncSetAttribute(softmax_fused_kernel, cudaFuncAttributeMaxDynamicSharedMemorySize, SMX);

    vnorm_split_kernel<<<V_, 256>>>(vocab);
    ptnorm_kernel<<<B_ * N_, 256>>>(patch);
    prep_kernel<<<Hh_ + D_ + 128, 256>>>(W1, W2);
    gemm1_bf16_kernel<<<dim3(Hh_ / 128, VT), 256, DYN>>>();
    bnfinal_kernel<<<1, Hh_>>>(gamma, beta);
    hsplit_kernel<<<V_, 256>>>();
    gemm2_bf16_kernel<<<dim3(D_ / 128, VT), 256, DYN>>>(b2);
    pnorm_kernel<<<V_, 256>>>();
    k5_mma_kernel<<<dim3(B_, VT), 256, DYN>>>();
    refine_kernel<<<512, 256>>>();
    softmax_fused_kernel<<<B_, 1024, SMX>>>(out);
}

// round 15
// speedup vs baseline: 4.7600x; 1.1105x over previous
#include <cuda_runtime.h>
#include <cuda_bf16.h>
#include <math.h>
#include <stdint.h>

#define B_  8
#define N_  1024
#define D_  768
#define V_  30000
#define C_  512
#define Hh_ 768
#define INV_T 5.0f
#define BN_EPS 1e-5f
#define MARGIN 0.002f
#define RMARGIN 0.001f
#define CAND_CAP (4u * 1024u * 1024u)
#define SCAP 2048
#define TILE_B 16384
#define BUF_B  32768

// ---------------- scratch (static device globals; no allocs allowed) ----------------
__device__ float g_h[(size_t)V_ * Hh_];
__device__ float g_proto[(size_t)V_ * D_];     // fp32 prototypes (normalized in place)
__device__ float g_ptf[(size_t)B_ * N_ * D_];  // fp32 normalized tokens
__device__ float g_colsum[Hh_], g_colsq[Hh_];
__device__ float g_scale[Hh_], g_shift[Hh_];
// split operands (2-pass gemms: only A carries lo; weights are hi-only)
__device__ __nv_bfloat16 g_vn_hi[(size_t)V_ * C_], g_vn_lo[(size_t)V_ * C_];
__device__ __nv_bfloat16 g_w1t_hi[(size_t)Hh_ * C_];
__device__ __nv_bfloat16 g_hb_hi[(size_t)V_ * Hh_], g_hb_lo[(size_t)V_ * Hh_];
__device__ __nv_bfloat16 g_w2t_hi[(size_t)D_ * Hh_];
__device__ __nv_bfloat16 g_proto_hi[(size_t)V_ * D_];
__device__ __nv_bfloat16 g_pt_hi[(size_t)B_ * N_ * D_];
// candidate machinery
__device__ unsigned g_ccount;
__device__ unsigned g_cand[CAND_CAP];
__device__ float g_capprox[CAND_CAP];
__device__ float g_amax[(size_t)B_ * V_];
__device__ unsigned g_okey[(size_t)B_ * V_];

// ---------------- helpers ----------------
__device__ __forceinline__ uint32_t smem_u32(const void* p) {
    uint32_t a;
    asm("{ .reg .u64 t; cvta.to.shared.u64 t, %1; cvt.u32.u64 %0, t; }" : "=r"(a) : "l"(p));
    return a;
}
__device__ __forceinline__ float warpSum(float v) {
    #pragma unroll
    for (int o = 16; o; o >>= 1) v += __shfl_xor_sync(0xffffffffu, v, o);
    return v;
}
__device__ __forceinline__ void split_bf16(float x, __nv_bfloat16& hi, __nv_bfloat16& lo) {
    hi = __float2bfloat16_rn(x);
    lo = __float2bfloat16_rn(x - __bfloat162float(hi));
}
__device__ __forceinline__ uint2 pack_hi4(float4 v) {
    __nv_bfloat162 p0 = __floats2bfloat162_rn(v.x, v.y);
    __nv_bfloat162 p1 = __floats2bfloat162_rn(v.z, v.w);
    uint2 u;
    u.x = *(uint32_t*)&p0; u.y = *(uint32_t*)&p1;
    return u;
}
__device__ __forceinline__ void split4(float4 v, uint2& hi, uint2& lo) {
    __nv_bfloat16 h0, l0, h1, l1, h2, l2, h3, l3;
    split_bf16(v.x, h0, l0); split_bf16(v.y, h1, l1);
    split_bf16(v.z, h2, l2); split_bf16(v.w, h3, l3);
    __nv_bfloat162 ph0{h0, h1}, ph1{h2, h3}, pl0{l0, l1}, pl1{l2, l3};
    hi.x = *(uint32_t*)&ph0; hi.y = *(uint32_t*)&ph1;
    lo.x = *(uint32_t*)&pl0; lo.y = *(uint32_t*)&pl1;
}
__device__ __forceinline__ unsigned fkey(float f) {
    unsigned u = __float_as_uint(f);
    return (u & 0x80000000u) ? ~u : (u | 0x80000000u);
}
__device__ __forceinline__ float funkey(unsigned k) {
    return (k & 0x80000000u) ? __uint_as_float(k ^ 0x80000000u) : __uint_as_float(~k);
}
__device__ __forceinline__ void ldsm_x4(uint32_t addr, uint32_t& r0, uint32_t& r1,
                                        uint32_t& r2, uint32_t& r3) {
    asm volatile("ldmatrix.sync.aligned.m8n8.x4.shared.b16 {%0,%1,%2,%3}, [%4];"
                 : "=r"(r0), "=r"(r1), "=r"(r2), "=r"(r3) : "r"(addr));
}
__device__ __forceinline__ void mma_bf16(float* d, const uint32_t* a, uint32_t b0, uint32_t b1) {
    asm volatile(
        "mma.sync.aligned.m16n8k16.row.col.f32.bf16.bf16.f32 "
        "{%0,%1,%2,%3}, {%4,%5,%6,%7}, {%8,%9}, {%0,%1,%2,%3};"
        : "+f"(d[0]), "+f"(d[1]), "+f"(d[2]), "+f"(d[3])
        : "r"(a[0]), "r"(a[1]), "r"(a[2]), "r"(a[3]), "r"(b0), "r"(b1));
}
#define CP_COMMIT() asm volatile("cp.async.commit_group;" ::: "memory")
#define CP_WAIT(n)  asm volatile("cp.async.wait_group %0;" :: "n"(n) : "memory")

// async stage one 128x64 bf16 tile (row-major, swizzled) into smem at dstbase
__device__ __forceinline__ void load_tile_async(uint32_t dstbase,
                                                const __nv_bfloat16* __restrict__ src,
                                                int rowbase, int kb, int ldk, int rowmax) {
    const int t = threadIdx.x;
    #pragma unroll
    for (int s = 0; s < 4; s++) {
        int idx = t + s * 256;
        int row = idx >> 3, kq = idx & 7;
        int gr = rowbase + row;
        uint32_t off = (uint32_t)(row << 7) + (uint32_t)(kq << 4);
        off ^= (uint32_t)(row & 7) << 4;
        const void* gp = (const void*)(src + (size_t)gr * ldk + kb + kq * 8);
        int sz = (gr < rowmax) ? 16 : 0;
        asm volatile("cp.async.cg.shared.global [%0], [%1], 16, %2;"
                     :: "r"(dstbase + off), "l"(gp), "r"(sz) : "memory");
    }
}

// ---------------- elementwise / prep kernels (warp-per-row, vectorized) ----------------
// vocab row norm + split: 8 warps/CTA, one row each. C=512 -> 4 float4 per lane.
__global__ void vnorm_split_kernel(const float* __restrict__ vocab) {
    int w = threadIdx.x >> 5, lane = threadIdx.x & 31;
    int r = blockIdx.x * 8 + w;                 // grid 3750 covers V exactly
    const float4* row = (const float4*)(vocab + (size_t)r * C_);
    float4 v[4];
    float s = 0.f;
    #pragma unroll
    for (int i = 0; i < 4; i++) {
        v[i] = row[lane + 32 * i];
        s += v[i].x * v[i].x + v[i].y * v[i].y + v[i].z * v[i].z + v[i].w * v[i].w;
    }
    s = warpSum(s);
    float inv = 1.0f / fmaxf(sqrtf(s), 1e-12f);
    uint2* oh = (uint2*)(g_vn_hi + (size_t)r * C_);
    uint2* ol = (uint2*)(g_vn_lo + (size_t)r * C_);
    #pragma unroll
    for (int i = 0; i < 4; i++) {
        float4 y = make_float4(v[i].x * inv, v[i].y * inv, v[i].z * inv, v[i].w * inv);
        uint2 hi, lo; split4(y, hi, lo);
        oh[lane + 32 * i] = hi; ol[lane + 32 * i] = lo;
    }
}

// patch token norm: D=768 -> 6 float4 per lane; writes fp32 + bf16 hi
__global__ void ptnorm_kernel(const float* __restrict__ pt) {
    int w = threadIdx.x >> 5, lane = threadIdx.x & 31;
    int r = blockIdx.x * 8 + w;                 // grid 1024 covers B*N exactly
    const float4* row = (const float4*)(pt + (size_t)r * D_);
    float4 v[6];
    float s = 0.f;
    #pragma unroll
    for (int i = 0; i < 6; i++) {
        v[i] = row[lane + 32 * i];
        s += v[i].x * v[i].x + v[i].y * v[i].y + v[i].z * v[i].z + v[i].w * v[i].w;
    }
    s = warpSum(s);
    float inv = 1.0f / fmaxf(sqrtf(s), 1e-12f);
    float4* of = (float4*)(g_ptf + (size_t)r * D_);
    uint2* oh = (uint2*)(g_pt_hi + (size_t)r * D_);
    #pragma unroll
    for (int i = 0; i < 6; i++) {
        float4 y = make_float4(v[i].x * inv, v[i].y * inv, v[i].z * inv, v[i].w * inv);
        of[lane + 32 * i] = y;
        oh[lane + 32 * i] = pack_hi4(y);
    }
}

// merged prep: W1T hi [0,Hh), W2T hi [Hh,Hh+D), zeroing [Hh+D, +128)
__global__ void prep_kernel(const float* __restrict__ W1, const float* __restrict__ W2) {
    int blk = blockIdx.x;
    if (blk < Hh_) {
        int n = blk;
        for (int k = threadIdx.x; k < C_; k += 256)
            g_w1t_hi[(size_t)n * C_ + k] = __float2bfloat16_rn(W1[(size_t)k * Hh_ + n]);
    } else if (blk < Hh_ + D_) {
        int n = blk - Hh_;
        for (int k = threadIdx.x; k < Hh_; k += 256)
            g_w2t_hi[(size_t)n * Hh_ + k] = __float2bfloat16_rn(W2[(size_t)k * D_ + n]);
    } else {
        int i = (blk - Hh_ - D_) * 256 + threadIdx.x;
        if (i < Hh_) { g_colsum[i] = 0.f; g_colsq[i] = 0.f; }
        if (i == 0) g_ccount = 0;
        for (int j = i; j < B_ * V_; j += 128 * 256) g_okey[j] = 0u;
    }
}

__global__ void bnfinal_kernel(const float* __restrict__ gamma, const float* __restrict__ beta) {
    int c = threadIdx.x;
    if (c < Hh_) {
        float mean = g_colsum[c] / (float)V_;
        float var = g_colsq[c] / (float)V_ - mean * mean;
        float sc = gamma[c] / sqrtf(var + BN_EPS);
        g_scale[c] = sc;
        g_shift[c] = beta[c] - mean * sc;
    }
}

// bn + relu + split, flat grid-stride over float4s (exact cover: 22500x256)
__global__ void hsplit_kernel() {
    int i = blockIdx.x * 256 + threadIdx.x;     // float4 index, < V*Hh/4
    int c4 = i % 192;
    float4 v = ((const float4*)g_h)[i];
    float4 sc = ((const float4*)g_scale)[c4];
    float4 sh = ((const float4*)g_shift)[c4];
    float4 y;
    y.x = fmaxf(fmaf(v.x, sc.x, sh.x), 0.f);
    y.y = fmaxf(fmaf(v.y, sc.y, sh.y), 0.f);
    y.z = fmaxf(fmaf(v.z, sc.z, sh.z), 0.f);
    y.w = fmaxf(fmaf(v.w, sc.w, sh.w), 0.f);
    uint2 hi, lo; split4(y, hi, lo);
    ((uint2*)g_hb_hi)[i] = hi;
    ((uint2*)g_hb_lo)[i] = lo;
}

// proto row norm in place (fp32) + bf16 hi; warp-per-row
__global__ void pnorm_kernel() {
    int w = threadIdx.x >> 5, lane = threadIdx.x & 31;
    int r = blockIdx.x * 8 + w;                 // grid 3750 covers V exactly
    float4* row = (float4*)(g_proto + (size_t)r * D_);
    float4 v[6];
    float s = 0.f;
    #pragma unroll
    for (int i = 0; i < 6; i++) {
        v[i] = row[lane + 32 * i];
        s += v[i].x * v[i].x + v[i].y * v[i].y + v[i].z * v[i].z + v[i].w * v[i].w;
    }
    s = warpSum(s);
    float inv = 1.0f / fmaxf(sqrtf(s), 1e-12f);
    uint2* oh = (uint2*)(g_proto_hi + (size_t)r * D_);
    #pragma unroll
    for (int i = 0; i < 6; i++) {
        float4 y = make_float4(v[i].x * inv, v[i].y * inv, v[i].z * inv, v[i].w * inv);
        row[lane + 32 * i] = y;
        oh[lane + 32 * i] = pack_hi4(y);
    }
}

// ---------------- MMA fragment compute on one buffered chunk ----------------
__device__ __forceinline__ void mma_chunk(uint32_t sA, uint32_t sB, float acc[2][8][4],
                                          int rowA, uint32_t swA, uint32_t kselA,
                                          int rowBn, uint32_t swB, uint32_t kselB) {
    #pragma unroll
    for (int ks = 0; ks < 4; ks++) {
        uint32_t a[2][4];
        #pragma unroll
        for (int mf = 0; mf < 2; mf++) {
            uint32_t addr = sA + (uint32_t)((rowA + mf * 16) << 7)
                          + (((uint32_t)(ks * 32) + kselA) ^ swA);
            ldsm_x4(addr, a[mf][0], a[mf][1], a[mf][2], a[mf][3]);
        }
        uint32_t bf[4][4];
        #pragma unroll
        for (int nf2 = 0; nf2 < 4; nf2++) {
            uint32_t addr = sB + (uint32_t)((rowBn + nf2 * 16) << 7)
                          + (((uint32_t)(ks * 32) + kselB) ^ swB);
            ldsm_x4(addr, bf[nf2][0], bf[nf2][1], bf[nf2][2], bf[nf2][3]);
        }
        #pragma unroll
        for (int mf = 0; mf < 2; mf++)
            #pragma unroll
            for (int nf = 0; nf < 8; nf++)
                mma_bf16(acc[mf][nf], a[mf],
                         bf[nf >> 1][(nf & 1) * 2], bf[nf >> 1][(nf & 1) * 2 + 1]);
    }
}

// ---------------- double-buffered 2-pass split-bf16 HMMA GEMM (device body) ----------------
// pass0: A_hi . B_hi ; pass1: A_lo . B_hi (dropped A_hi.B_lo: ~3e-4 end-to-end, calibrated)
// NOTE: global-symbol pointers bound in DEVICE code (wrappers) — host-side symbol
// passing is UB; GB300 ATS silently dereferences the host shadow (R7/R8 root cause).
__device__ __forceinline__ void hgemm2_body(
    const __nv_bfloat16* __restrict__ Ah, const __nv_bfloat16* __restrict__ Al,
    const __nv_bfloat16* __restrict__ Bth,
    float* __restrict__ C, const float* __restrict__ bias, int K, bool do_stats) {
    extern __shared__ char dynsmem[];
    const uint32_t sbase = smem_u32(dynsmem);
    const int t = threadIdx.x;
    const int lane = t & 31, wid = t >> 5;
    const int wm = wid >> 1, wn = wid & 1;
    const int mb = blockIdx.y * 128, nb = blockIdx.x * 128;

    const int rowA = wm * 32 + (lane & 15);
    const uint32_t swA = (uint32_t)(rowA & 7) << 4;
    const uint32_t kselA = (uint32_t)(lane >> 4) << 4;
    const int rowBn = wn * 64 + ((lane >> 4) << 3) + (lane & 7);
    const uint32_t swB = (uint32_t)(lane & 7) << 4;
    const uint32_t kselB = (uint32_t)((lane >> 3) & 1) << 4;

    float acc[2][8][4];
    #pragma unroll
    for (int mf = 0; mf < 2; mf++)
        #pragma unroll
        for (int nf = 0; nf < 8; nf++)
            #pragma unroll
            for (int e = 0; e < 4; e++) acc[mf][nf][e] = 0.f;

    const int nchunk = K >> 6;
    const int TOT = 2 * nchunk;

    load_tile_async(sbase, Ah, mb, 0, K, V_);
    load_tile_async(sbase + TILE_B, Bth, nb, 0, K, 1 << 30);
    CP_COMMIT();

    #pragma unroll 1
    for (int it = 0; it < TOT; it++) {
        uint32_t bufb = sbase + (uint32_t)(it & 1) * BUF_B;
        if (it + 1 < TOT) {
            int it2 = it + 1;
            int pass2 = it2 / nchunk, ch2 = it2 - pass2 * nchunk;
            const __nv_bfloat16* Asrc = pass2 ? Al : Ah;
            uint32_t nxt = sbase + (uint32_t)(it2 & 1) * BUF_B;
            load_tile_async(nxt, Asrc, mb, ch2 * 64, K, V_);
            load_tile_async(nxt + TILE_B, Bth, nb, ch2 * 64, K, 1 << 30);
            CP_COMMIT();
            CP_WAIT(1);
        } else {
            CP_WAIT(0);
        }
        __syncthreads();
        mma_chunk(bufb, bufb + TILE_B, acc, rowA, swA, kselA, rowBn, swB, kselB);
        __syncthreads();
    }

    #pragma unroll
    for (int mf = 0; mf < 2; mf++)
        #pragma unroll
        for (int h = 0; h < 2; h++) {
            int row = mb + wm * 32 + mf * 16 + (lane >> 2) + h * 8;
            if (row >= V_) continue;
            #pragma unroll
            for (int nf = 0; nf < 8; nf++) {
                int col = nb + wn * 64 + nf * 8 + (lane & 3) * 2;
                float2 v;
                v.x = acc[mf][nf][h * 2 + 0];
                v.y = acc[mf][nf][h * 2 + 1];
                if (bias) { v.x += bias[col]; v.y += bias[col + 1]; }
                *(float2*)(C + (size_t)row * 768 + col) = v;
            }
        }

    // fused BN column stats: reduce this CTA's 128 rows per column, one atomic per (warp,col)
    if (do_stats) {
        #pragma unroll
        for (int nf = 0; nf < 8; nf++)
            #pragma unroll
            for (int e2 = 0; e2 < 2; e2++) {
                float s = 0.f, sq = 0.f;
                #pragma unroll
                for (int mf = 0; mf < 2; mf++)
                    #pragma unroll
                    for (int h = 0; h < 2; h++) {
                        float v = acc[mf][nf][h * 2 + e2];
                        s += v; sq += v * v;
                    }
                #pragma unroll
                for (int o = 4; o <= 16; o <<= 1) {
                    s += __shfl_xor_sync(0xffffffffu, s, o);
                    sq += __shfl_xor_sync(0xffffffffu, sq, o);
                }
                if (lane < 4) {
                    int col = nb + wn * 64 + nf * 8 + lane * 2 + e2;
                    atomicAdd(&g_colsum[col], s);
                    atomicAdd(&g_colsq[col], sq);
                }
            }
    }
}

__global__ __launch_bounds__(256, 2) void gemm1_bf16_kernel() {
    hgemm2_body(g_vn_hi, g_vn_lo, g_w1t_hi, g_h, nullptr, C_, true);
}
__global__ __launch_bounds__(256, 2) void gemm2_bf16_kernel(const float* __restrict__ b2) {
    hgemm2_body(g_hb_hi, g_hb_lo, g_w2t_hi, g_proto, b2, Hh_, false);
}

// ---------------- 1-pass double-buffered HMMA logits + fused max + candidates ----------------
__global__ __launch_bounds__(256, 2) void k5_mma_kernel() {
    extern __shared__ char dynsmem[];
    __shared__ float redbuf[2][128];
    __shared__ float rmax[128];
    __shared__ unsigned s_cnt, s_gbase, s_n;
    __shared__ unsigned s_cand[SCAP];
    __shared__ float s_appr[SCAP];

    const uint32_t sbase = smem_u32(dynsmem);
    const int t = threadIdx.x;
    const int lane = t & 31, wid = t >> 5;
    const int wm = wid >> 1, wn = wid & 1;
    const int b = blockIdx.x;                 // batch fastest -> proto tiles shared in L2
    const int vb = blockIdx.y * 128;

    if (t < 128) rmax[t] = -1e30f;
    if (t == 0) s_cnt = 0;

    const int rowA = wm * 32 + (lane & 15);
    const uint32_t swA = (uint32_t)(rowA & 7) << 4;
    const uint32_t kselA = (uint32_t)(lane >> 4) << 4;
    const int rowBn = wn * 64 + ((lane >> 4) << 3) + (lane & 7);
    const uint32_t swB = (uint32_t)(lane & 7) << 4;
    const uint32_t kselB = (uint32_t)((lane >> 3) & 1) << 4;

    float acc[2][8][4];
    const int TOT = 96;                       // 8 token tiles x 12 chunks

    load_tile_async(sbase, g_proto_hi, vb, 0, D_, V_);
    load_tile_async(sbase + TILE_B, g_pt_hi, b * N_, 0, D_, 1 << 30);
    CP_COMMIT();

    #pragma unroll 1
    for (int it = 0; it < TOT; it++) {
        const int tt = it / 12, chunk = it - tt * 12;
        if (chunk == 0) {
            #pragma unroll
            for (int mf = 0; mf < 2; mf++)
                #pragma unroll
                for (int nf = 0; nf < 8; nf++)
                    #pragma unroll
                    for (int e = 0; e < 4; e++) acc[mf][nf][e] = 0.f;
        }
        uint32_t bufb = sbase + (uint32_t)(it & 1) * BUF_B;
        if (it + 1 < TOT) {
            int it2 = it + 1;
            int tt2 = it2 / 12, ch2 = it2 - tt2 * 12;
            uint32_t nxt = sbase + (uint32_t)(it2 & 1) * BUF_B;
            load_tile_async(nxt, g_proto_hi, vb, ch2 * 64, D_, V_);
            load_tile_async(nxt + TILE_B, g_pt_hi, b * N_ + tt2 * 128, ch2 * 64, D_, 1 << 30);
            CP_COMMIT();
            CP_WAIT(1);
        } else {
            CP_WAIT(0);
        }
        __syncthreads();
        mma_chunk(bufb, bufb + TILE_B, acc, rowA, swA, kselA, rowBn, swB, kselB);

        if (chunk == 11) {
            // ---- per-v max over this 128-token tile ----
            float m4[2][2];
            #pragma unroll
            for (int mf = 0; mf < 2; mf++)
                #pragma unroll
                for (int h = 0; h < 2; h++) {
                    float m = -1e30f;
                    #pragma unroll
                    for (int nf = 0; nf < 8; nf++)
                        m = fmaxf(m, fmaxf(acc[mf][nf][h * 2], acc[mf][nf][h * 2 + 1]));
                    m4[mf][h] = m;
                }
            #pragma unroll
            for (int mf = 0; mf < 2; mf++)
                #pragma unroll
                for (int h = 0; h < 2; h++) {
                    float m = m4[mf][h];
                    m = fmaxf(m, __shfl_xor_sync(0xffffffffu, m, 1));
                    m = fmaxf(m, __shfl_xor_sync(0xffffffffu, m, 2));
                    m4[mf][h] = m;
                }
            __syncthreads();
            if ((lane & 3) == 0) {
                #pragma unroll
                for (int mf = 0; mf < 2; mf++)
                    #pragma unroll
                    for (int h = 0; h < 2; h++)
                        redbuf[wn][wm * 32 + mf * 16 + (lane >> 2) + h * 8] = m4[mf][h];
            }
            __syncthreads();
            if (t < 128) rmax[t] = fmaxf(rmax[t], fmaxf(redbuf[0][t], redbuf[1][t]));
            __syncthreads();

            // ---- record candidates within MARGIN of running max ----
            #pragma unroll
            for (int mf = 0; mf < 2; mf++)
                #pragma unroll
                for (int h = 0; h < 2; h++) {
                    int lrow = wm * 32 + mf * 16 + (lane >> 2) + h * 8;
                    int gv = vb + lrow;
                    if (gv >= V_) continue;
                    float thr = rmax[lrow] - MARGIN;
                    #pragma unroll
                    for (int nf = 0; nf < 8; nf++)
                        #pragma unroll
                        for (int e2 = 0; e2 < 2; e2++) {
                            float val = acc[mf][nf][h * 2 + e2];
                            if (val >= thr) {
                                unsigned pos = atomicAdd(&s_cnt, 1u);
                                if (pos < SCAP) {
                                    int tok = tt * 128 + wn * 64 + nf * 8 + (lane & 3) * 2 + e2;
                                    s_cand[pos] = ((unsigned)(b * V_ + gv) << 10) | (unsigned)tok;
                                    s_appr[pos] = val;
                                }
                            }
                        }
                }
            __syncthreads();
            if (t == 0) {
                unsigned n = min(s_cnt, (unsigned)SCAP);
                s_gbase = atomicAdd(&g_ccount, n);
                s_n = n;
                s_cnt = 0;
            }
            __syncthreads();
            for (unsigned i = t; i < s_n; i += 256) {
                unsigned gi = s_gbase + i;
                if (gi < CAND_CAP) { g_cand[gi] = s_cand[i]; g_capprox[gi] = s_appr[i]; }
            }
        }
        __syncthreads();
    }

    if (t < 128) {
        int gv = vb + t;
        if (gv < V_) g_amax[(size_t)b * V_ + gv] = rmax[t];
    }
}

// ---------------- refinement: exact fp32 dots for surviving candidates ----------------
__global__ void refine_kernel() {
    unsigned count = min(g_ccount, CAND_CAP);
    int lane = threadIdx.x & 31;
    unsigned w = (blockIdx.x * blockDim.x + threadIdx.x) >> 5;
    unsigned nw = (gridDim.x * blockDim.x) >> 5;
    for (unsigned i = w; i < count; i += nw) {
        float ap = g_capprox[i];
        unsigned c = g_cand[i];
        unsigned bv = c >> 10;
        if (ap < g_amax[bv] - RMARGIN) continue;
        unsigned tok = c & 1023u;
        unsigned b = bv / V_, v = bv - b * V_;
        const float* x = g_ptf + ((size_t)b * N_ + tok) * D_;
        const float* p = g_proto + (size_t)v * D_;
        float s = 0.f;
        #pragma unroll
        for (int jj = 0; jj < 6; jj++) {
            float4 xa = *(const float4*)(x + ((jj << 5) + lane) * 4);
            float4 pa = *(const float4*)(p + ((jj << 5) + lane) * 4);
            s += xa.x * pa.x + xa.y * pa.y + xa.z * pa.z + xa.w * pa.w;
        }
        s = warpSum(s);
        if (lane == 0) atomicMax(&g_okey[bv], fkey(s));
    }
}

// ---------------- fused finalize + softmax (values staged in smem) ----------------
__global__ void softmax_fused_kernel(float* __restrict__ out) {
    extern __shared__ float sv[];              // V_ floats
    __shared__ float sb[33];
    int b = blockIdx.x;
    int t = threadIdx.x, lane = t & 31, w = t >> 5;
    size_t base = (size_t)b * V_;

    float m = -1e30f;
    for (int v = t; v < V_; v += 1024) {
        unsigned k = g_okey[base + v];
        float val = k ? funkey(k) : g_amax[base + v];
        sv[v] = val;
        m = fmaxf(m, val);
    }
    #pragma unroll
    for (int o = 16; o; o >>= 1) m = fmaxf(m, __shfl_xor_sync(0xffffffffu, m, o));
    if (lane == 0) sb[w] = m;
    __syncthreads();
    if (t == 0) {
        float mm = -1e30f;
        for (int i = 0; i < 32; i++) mm = fmaxf(mm, sb[i]);
        sb[32] = mm;
    }
    __syncthreads();
    float M = sb[32];

    float s = 0.f;
    for (int v = t; v < V_; v += 1024) {
        float e = expf((sv[v] - M) * INV_T);
        sv[v] = e;
        s += e;
    }
    s = warpSum(s);
    __syncthreads();
    if (lane == 0) sb[w] = s;
    __syncthreads();
    if (t == 0) {
        float ss = 0.f;
        for (int i = 0; i < 32; i++) ss += sb[i];
        sb[32] = ss;
    }
    __syncthreads();
    float inv = 1.0f / sb[32];
    for (int v = t; v < V_; v += 1024) out[base + v] = sv[v] * inv;
}

// ---------------- launch ----------------
extern "C" void kernel_launch(void* const* d_in, const int* in_sizes, int n_in,
                              void* d_out, int out_size) {
    const float* patch = (const float*)d_in[0];
    const float* vocab = (const float*)d_in[1];
    const float* W1    = (const float*)d_in[2];
    const float* gamma = (const float*)d_in[3];
    const float* beta  = (const float*)d_in[4];
    const float* W2    = (const float*)d_in[5];
    const float* b2    = (const float*)d_in[6];
    float* out = (float*)d_out;

    const int VT = (V_ + 127) / 128;   // 235
    const int DYN = 2 * BUF_B;         // 64KB double buffer
    const int SMX = V_ * 4;            // 120KB softmax value cache

    cudaFuncSetAttribute(gemm1_bf16_kernel, cudaFuncAttributeMaxDynamicSharedMemorySize, DYN);
    cudaFuncSetAttribute(gemm2_bf16_kernel, cudaFuncAttributeMaxDynamicSharedMemorySize, DYN);
    cudaFuncSetAttribute(k5_mma_kernel, cudaFuncAttributeMaxDynamicSharedMemorySize, DYN);
    cudaFuncSetAttribute(softmax_fused_kernel, cudaFuncAttributeMaxDynamicSharedMemorySize, SMX);

    vnorm_split_kernel<<<V_ / 8, 256>>>(vocab);
    ptnorm_kernel<<<B_ * N_ / 8, 256>>>(patch);
    prep_kernel<<<Hh_ + D_ + 128, 256>>>(W1, W2);
    gemm1_bf16_kernel<<<dim3(Hh_ / 128, VT), 256, DYN>>>();
    bnfinal_kernel<<<1, Hh_>>>(gamma, beta);
    hsplit_kernel<<<V_ * Hh_ / 4 / 256, 256>>>();
    gemm2_bf16_kernel<<<dim3(D_ / 128, VT), 256, DYN>>>(b2);
    pnorm_kernel<<<V_ / 8, 256>>>();
    k5_mma_kernel<<<dim3(B_, VT), 256, DYN>>>();
    refine_kernel<<<512, 256>>>();
    softmax_fused_kernel<<<B_, 1024, SMX>>>(out);
}

// round 17
// speedup vs baseline: 4.9093x; 1.0314x over previous
#include <cuda_runtime.h>
#include <cuda_bf16.h>
#include <math.h>
#include <stdint.h>

#define B_  8
#define N_  1024
#define D_  768
#define V_  30000
#define C_  512
#define Hh_ 768
#define INV_T 5.0f
#define BN_EPS 1e-5f
#define MARGIN 0.002f
#define RMARGIN 0.001f
#define CAND_CAP (4u * 1024u * 1024u)
#define SCAP 1024
#define TILE_B 16384
#define BUF_B  32768
#define NSTAGE 3

// ---------------- scratch (static device globals; no allocs allowed) ----------------
__device__ float g_h[(size_t)V_ * Hh_];
__device__ float g_proto[(size_t)V_ * D_];     // fp32 prototypes (normalized in place)
__device__ float g_ptf[(size_t)B_ * N_ * D_];  // fp32 normalized tokens
__device__ float g_colsum[Hh_], g_colsq[Hh_];
__device__ float g_scale[Hh_], g_shift[Hh_];
// split operands (2-pass gemms: only A carries lo; weights are hi-only)
__device__ __nv_bfloat16 g_vn_hi[(size_t)V_ * C_], g_vn_lo[(size_t)V_ * C_];
__device__ __nv_bfloat16 g_w1t_hi[(size_t)Hh_ * C_];
__device__ __nv_bfloat16 g_hb_hi[(size_t)V_ * Hh_], g_hb_lo[(size_t)V_ * Hh_];
__device__ __nv_bfloat16 g_w2t_hi[(size_t)D_ * Hh_];
__device__ __nv_bfloat16 g_proto_hi[(size_t)V_ * D_];
__device__ __nv_bfloat16 g_pt_hi[(size_t)B_ * N_ * D_];
// candidate machinery
__device__ unsigned g_ccount;
__device__ unsigned g_cand[CAND_CAP];
__device__ float g_capprox[CAND_CAP];
__device__ float g_amax[(size_t)B_ * V_];
__device__ unsigned g_okey[(size_t)B_ * V_];

// ---------------- helpers ----------------
__device__ __forceinline__ uint32_t smem_u32(const void* p) {
    uint32_t a;
    asm("{ .reg .u64 t; cvta.to.shared.u64 t, %1; cvt.u32.u64 %0, t; }" : "=r"(a) : "l"(p));
    return a;
}
__device__ __forceinline__ float warpSum(float v) {
    #pragma unroll
    for (int o = 16; o; o >>= 1) v += __shfl_xor_sync(0xffffffffu, v, o);
    return v;
}
__device__ __forceinline__ void split_bf16(float x, __nv_bfloat16& hi, __nv_bfloat16& lo) {
    hi = __float2bfloat16_rn(x);
    lo = __float2bfloat16_rn(x - __bfloat162float(hi));
}
__device__ __forceinline__ uint2 pack_hi4(float4 v) {
    __nv_bfloat162 p0 = __floats2bfloat162_rn(v.x, v.y);
    __nv_bfloat162 p1 = __floats2bfloat162_rn(v.z, v.w);
    uint2 u;
    u.x = *(uint32_t*)&p0; u.y = *(uint32_t*)&p1;
    return u;
}
__device__ __forceinline__ void split4(float4 v, uint2& hi, uint2& lo) {
    __nv_bfloat16 h0, l0, h1, l1, h2, l2, h3, l3;
    split_bf16(v.x, h0, l0); split_bf16(v.y, h1, l1);
    split_bf16(v.z, h2, l2); split_bf16(v.w, h3, l3);
    __nv_bfloat162 ph0{h0, h1}, ph1{h2, h3}, pl0{l0, l1}, pl1{l2, l3};
    hi.x = *(uint32_t*)&ph0; hi.y = *(uint32_t*)&ph1;
    lo.x = *(uint32_t*)&pl0; lo.y = *(uint32_t*)&pl1;
}
__device__ __forceinline__ unsigned fkey(float f) {
    unsigned u = __float_as_uint(f);
    return (u & 0x80000000u) ? ~u : (u | 0x80000000u);
}
__device__ __forceinline__ float funkey(unsigned k) {
    return (k & 0x80000000u) ? __uint_as_float(k ^ 0x80000000u) : __uint_as_float(~k);
}
__device__ __forceinline__ void ldsm_x4(uint32_t addr, uint32_t& r0, uint32_t& r1,
                                        uint32_t& r2, uint32_t& r3) {
    asm volatile("ldmatrix.sync.aligned.m8n8.x4.shared.b16 {%0,%1,%2,%3}, [%4];"
                 : "=r"(r0), "=r"(r1), "=r"(r2), "=r"(r3) : "r"(addr));
}
__device__ __forceinline__ void mma_bf16(float* d, const uint32_t* a, uint32_t b0, uint32_t b1) {
    asm volatile(
        "mma.sync.aligned.m16n8k16.row.col.f32.bf16.bf16.f32 "
        "{%0,%1,%2,%3}, {%4,%5,%6,%7}, {%8,%9}, {%0,%1,%2,%3};"
        : "+f"(d[0]), "+f"(d[1]), "+f"(d[2]), "+f"(d[3])
        : "r"(a[0]), "r"(a[1]), "r"(a[2]), "r"(a[3]), "r"(b0), "r"(b1));
}
#define CP_COMMIT() asm volatile("cp.async.commit_group;" ::: "memory")
#define CP_WAIT(n)  asm volatile("cp.async.wait_group %0;" :: "n"(n) : "memory")

// async stage one 128x64 bf16 tile (row-major, swizzled) into smem at dstbase
__device__ __forceinline__ void load_tile_async(uint32_t dstbase,
                                                const __nv_bfloat16* __restrict__ src,
                                                int rowbase, int kb, int ldk, int rowmax) {
    const int t = threadIdx.x;
    #pragma unroll
    for (int s = 0; s < 4; s++) {
        int idx = t + s * 256;
        int row = idx >> 3, kq = idx & 7;
        int gr = rowbase + row;
        uint32_t off = (uint32_t)(row << 7) + (uint32_t)(kq << 4);
        off ^= (uint32_t)(row & 7) << 4;
        const void* gp = (const void*)(src + (size_t)gr * ldk + kb + kq * 8);
        int sz = (gr < rowmax) ? 16 : 0;
        asm volatile("cp.async.cg.shared.global [%0], [%1], 16, %2;"
                     :: "r"(dstbase + off), "l"(gp), "r"(sz) : "memory");
    }
}

// ---------------- elementwise / prep kernels (warp-per-row, vectorized) ----------------
__global__ void vnorm_split_kernel(const float* __restrict__ vocab) {
    int w = threadIdx.x >> 5, lane = threadIdx.x & 31;
    int r = blockIdx.x * 8 + w;
    const float4* row = (const float4*)(vocab + (size_t)r * C_);
    float4 v[4];
    float s = 0.f;
    #pragma unroll
    for (int i = 0; i < 4; i++) {
        v[i] = row[lane + 32 * i];
        s += v[i].x * v[i].x + v[i].y * v[i].y + v[i].z * v[i].z + v[i].w * v[i].w;
    }
    s = warpSum(s);
    float inv = 1.0f / fmaxf(sqrtf(s), 1e-12f);
    uint2* oh = (uint2*)(g_vn_hi + (size_t)r * C_);
    uint2* ol = (uint2*)(g_vn_lo + (size_t)r * C_);
    #pragma unroll
    for (int i = 0; i < 4; i++) {
        float4 y = make_float4(v[i].x * inv, v[i].y * inv, v[i].z * inv, v[i].w * inv);
        uint2 hi, lo; split4(y, hi, lo);
        oh[lane + 32 * i] = hi; ol[lane + 32 * i] = lo;
    }
}

__global__ void ptnorm_kernel(const float* __restrict__ pt) {
    int w = threadIdx.x >> 5, lane = threadIdx.x & 31;
    int r = blockIdx.x * 8 + w;
    const float4* row = (const float4*)(pt + (size_t)r * D_);
    float4 v[6];
    float s = 0.f;
    #pragma unroll
    for (int i = 0; i < 6; i++) {
        v[i] = row[lane + 32 * i];
        s += v[i].x * v[i].x + v[i].y * v[i].y + v[i].z * v[i].z + v[i].w * v[i].w;
    }
    s = warpSum(s);
    float inv = 1.0f / fmaxf(sqrtf(s), 1e-12f);
    float4* of = (float4*)(g_ptf + (size_t)r * D_);
    uint2* oh = (uint2*)(g_pt_hi + (size_t)r * D_);
    #pragma unroll
    for (int i = 0; i < 6; i++) {
        float4 y = make_float4(v[i].x * inv, v[i].y * inv, v[i].z * inv, v[i].w * inv);
        of[lane + 32 * i] = y;
        oh[lane + 32 * i] = pack_hi4(y);
    }
}

__global__ void prep_kernel(const float* __restrict__ W1, const float* __restrict__ W2) {
    int blk = blockIdx.x;
    if (blk < Hh_) {
        int n = blk;
        for (int k = threadIdx.x; k < C_; k += 256)
            g_w1t_hi[(size_t)n * C_ + k] = __float2bfloat16_rn(W1[(size_t)k * Hh_ + n]);
    } else if (blk < Hh_ + D_) {
        int n = blk - Hh_;
        for (int k = threadIdx.x; k < Hh_; k += 256)
            g_w2t_hi[(size_t)n * Hh_ + k] = __float2bfloat16_rn(W2[(size_t)k * D_ + n]);
    } else {
        int i = (blk - Hh_ - D_) * 256 + threadIdx.x;
        if (i < Hh_) { g_colsum[i] = 0.f; g_colsq[i] = 0.f; }
        if (i == 0) g_ccount = 0;
        for (int j = i; j < B_ * V_; j += 128 * 256) g_okey[j] = 0u;
    }
}

__global__ void bnfinal_kernel(const float* __restrict__ gamma, const float* __restrict__ beta) {
    int c = threadIdx.x;
    if (c < Hh_) {
        float mean = g_colsum[c] / (float)V_;
        float var = g_colsq[c] / (float)V_ - mean * mean;
        float sc = gamma[c] / sqrtf(var + BN_EPS);
        g_scale[c] = sc;
        g_shift[c] = beta[c] - mean * sc;
    }
}

__global__ void hsplit_kernel() {
    int i = blockIdx.x * 256 + threadIdx.x;     // float4 index
    int c4 = i % 192;
    float4 v = ((const float4*)g_h)[i];
    float4 sc = ((const float4*)g_scale)[c4];
    float4 sh = ((const float4*)g_shift)[c4];
    float4 y;
    y.x = fmaxf(fmaf(v.x, sc.x, sh.x), 0.f);
    y.y = fmaxf(fmaf(v.y, sc.y, sh.y), 0.f);
    y.z = fmaxf(fmaf(v.z, sc.z, sh.z), 0.f);
    y.w = fmaxf(fmaf(v.w, sc.w, sh.w), 0.f);
    uint2 hi, lo; split4(y, hi, lo);
    ((uint2*)g_hb_hi)[i] = hi;
    ((uint2*)g_hb_lo)[i] = lo;
}

__global__ void pnorm_kernel() {
    int w = threadIdx.x >> 5, lane = threadIdx.x & 31;
    int r = blockIdx.x * 8 + w;
    float4* row = (float4*)(g_proto + (size_t)r * D_);
    float4 v[6];
    float s = 0.f;
    #pragma unroll
    for (int i = 0; i < 6; i++) {
        v[i] = row[lane + 32 * i];
        s += v[i].x * v[i].x + v[i].y * v[i].y + v[i].z * v[i].z + v[i].w * v[i].w;
    }
    s = warpSum(s);
    float inv = 1.0f / fmaxf(sqrtf(s), 1e-12f);
    uint2* oh = (uint2*)(g_proto_hi + (size_t)r * D_);
    #pragma unroll
    for (int i = 0; i < 6; i++) {
        float4 y = make_float4(v[i].x * inv, v[i].y * inv, v[i].z * inv, v[i].w * inv);
        row[lane + 32 * i] = y;
        oh[lane + 32 * i] = pack_hi4(y);
    }
}

// ---------------- MMA fragment compute on one buffered chunk ----------------
__device__ __forceinline__ void mma_chunk(uint32_t sA, uint32_t sB, float acc[2][8][4],
                                          int rowA, uint32_t swA, uint32_t kselA,
                                          int rowBn, uint32_t swB, uint32_t kselB) {
    #pragma unroll
    for (int ks = 0; ks < 4; ks++) {
        uint32_t a[2][4];
        #pragma unroll
        for (int mf = 0; mf < 2; mf++) {
            uint32_t addr = sA + (uint32_t)((rowA + mf * 16) << 7)
                          + (((uint32_t)(ks * 32) + kselA) ^ swA);
            ldsm_x4(addr, a[mf][0], a[mf][1], a[mf][2], a[mf][3]);
        }
        uint32_t bf[4][4];
        #pragma unroll
        for (int nf2 = 0; nf2 < 4; nf2++) {
            uint32_t addr = sB + (uint32_t)((rowBn + nf2 * 16) << 7)
                          + (((uint32_t)(ks * 32) + kselB) ^ swB);
            ldsm_x4(addr, bf[nf2][0], bf[nf2][1], bf[nf2][2], bf[nf2][3]);
        }
        #pragma unroll
        for (int mf = 0; mf < 2; mf++)
            #pragma unroll
            for (int nf = 0; nf < 8; nf++)
                mma_bf16(acc[mf][nf], a[mf],
                         bf[nf >> 1][(nf & 1) * 2], bf[nf >> 1][(nf & 1) * 2 + 1]);
    }
}

// ---------------- 3-stage pipelined 2-pass split-bf16 HMMA GEMM (device body) ----------------
// Single __syncthreads per K-chunk: reuse distance 3 makes the prefetch-into-
// buf((it+2)%3) safe once all warps passed the sync at iter it (mma(it-1) done).
// Empty commit groups keep wait_group(1) exact at the tail.
// NOTE: global-symbol pointers bound in DEVICE code (wrappers) — host-side symbol
// passing is UB; GB300 ATS silently dereferences the host shadow (R7/R8 root cause).
__device__ __forceinline__ void hgemm2_body(
    const __nv_bfloat16* __restrict__ Ah, const __nv_bfloat16* __restrict__ Al,
    const __nv_bfloat16* __restrict__ Bth,
    float* __restrict__ C, const float* __restrict__ bias, int K, bool do_stats) {
    extern __shared__ char dynsmem[];
    const uint32_t sbase = smem_u32(dynsmem);
    const int t = threadIdx.x;
    const int lane = t & 31, wid = t >> 5;
    const int wm = wid >> 1, wn = wid & 1;
    const int mb = blockIdx.y * 128, nb = blockIdx.x * 128;

    const int rowA = wm * 32 + (lane & 15);
    const uint32_t swA = (uint32_t)(rowA & 7) << 4;
    const uint32_t kselA = (uint32_t)(lane >> 4) << 4;
    const int rowBn = wn * 64 + ((lane >> 4) << 3) + (lane & 7);
    const uint32_t swB = (uint32_t)(lane & 7) << 4;
    const uint32_t kselB = (uint32_t)((lane >> 3) & 1) << 4;

    float acc[2][8][4];
    #pragma unroll
    for (int mf = 0; mf < 2; mf++)
        #pragma unroll
        for (int nf = 0; nf < 8; nf++)
            #pragma unroll
            for (int e = 0; e < 4; e++) acc[mf][nf][e] = 0.f;

    const int nchunk = K >> 6;
    const int TOT = 2 * nchunk;

    // prologue: commit groups for it = 0, 1
    #pragma unroll
    for (int p = 0; p < 2; p++) {
        int pass = p / nchunk, ch = p - pass * nchunk;
        const __nv_bfloat16* Asrc = pass ? Al : Ah;
        uint32_t st = sbase + (uint32_t)(p % NSTAGE) * BUF_B;
        load_tile_async(st, Asrc, mb, ch * 64, K, V_);
        load_tile_async(st + TILE_B, Bth, nb, ch * 64, K, 1 << 30);
        CP_COMMIT();
    }

    #pragma unroll 1
    for (int it = 0; it < TOT; it++) {
        CP_WAIT(1);
        __syncthreads();
        int it2 = it + 2;
        if (it2 < TOT) {
            int pass2 = it2 / nchunk, ch2 = it2 - pass2 * nchunk;
            const __nv_bfloat16* Asrc = pass2 ? Al : Ah;
            uint32_t st = sbase + (uint32_t)(it2 % NSTAGE) * BUF_B;
            load_tile_async(st, Asrc, mb, ch2 * 64, K, V_);
            load_tile_async(st + TILE_B, Bth, nb, ch2 * 64, K, 1 << 30);
        }
        CP_COMMIT();   // possibly empty — keeps group numbering uniform
        uint32_t bufb = sbase + (uint32_t)(it % NSTAGE) * BUF_B;
        mma_chunk(bufb, bufb + TILE_B, acc, rowA, swA, kselA, rowBn, swB, kselB);
    }

    #pragma unroll
    for (int mf = 0; mf < 2; mf++)
        #pragma unroll
        for (int h = 0; h < 2; h++) {
            int row = mb + wm * 32 + mf * 16 + (lane >> 2) + h * 8;
            if (row >= V_) continue;
            #pragma unroll
            for (int nf = 0; nf < 8; nf++) {
                int col = nb + wn * 64 + nf * 8 + (lane & 3) * 2;
                float2 v;
                v.x = acc[mf][nf][h * 2 + 0];
                v.y = acc[mf][nf][h * 2 + 1];
                if (bias) { v.x += bias[col]; v.y += bias[col + 1]; }
                *(float2*)(C + (size_t)row * 768 + col) = v;
            }
        }

    if (do_stats) {
        #pragma unroll
        for (int nf = 0; nf < 8; nf++)
            #pragma unroll
            for (int e2 = 0; e2 < 2; e2++) {
                float s = 0.f, sq = 0.f;
                #pragma unroll
                for (int mf = 0; mf < 2; mf++)
                    #pragma unroll
                    for (int h = 0; h < 2; h++) {
                        float v = acc[mf][nf][h * 2 + e2];
                        s += v; sq += v * v;
                    }
                #pragma unroll
                for (int o = 4; o <= 16; o <<= 1) {
                    s += __shfl_xor_sync(0xffffffffu, s, o);
                    sq += __shfl_xor_sync(0xffffffffu, sq, o);
                }
                if (lane < 4) {
                    int col = nb + wn * 64 + nf * 8 + lane * 2 + e2;
                    atomicAdd(&g_colsum[col], s);
                    atomicAdd(&g_colsq[col], sq);
                }
            }
    }
}

__global__ __launch_bounds__(256, 2) void gemm1_bf16_kernel() {
    hgemm2_body(g_vn_hi, g_vn_lo, g_w1t_hi, g_h, nullptr, C_, true);
}
__global__ __launch_bounds__(256, 2) void gemm2_bf16_kernel(const float* __restrict__ b2) {
    hgemm2_body(g_hb_hi, g_hb_lo, g_w2t_hi, g_proto, b2, Hh_, false);
}

// ---------------- 1-pass 3-stage HMMA logits + fused max + candidates ----------------
__global__ __launch_bounds__(256, 2) void k5_mma_kernel() {
    extern __shared__ char dynsmem[];
    __shared__ float redbuf[2][128];
    __shared__ float rmax[128];
    __shared__ unsigned s_cnt, s_gbase, s_n;
    __shared__ unsigned s_cand[SCAP];
    __shared__ float s_appr[SCAP];

    const uint32_t sbase = smem_u32(dynsmem);
    const int t = threadIdx.x;
    const int lane = t & 31, wid = t >> 5;
    const int wm = wid >> 1, wn = wid & 1;
    const int b = blockIdx.x;                 // batch fastest -> proto tiles shared in L2
    const int vb = blockIdx.y * 128;

    if (t < 128) rmax[t] = -1e30f;
    if (t == 0) s_cnt = 0;

    const int rowA = wm * 32 + (lane & 15);
    const uint32_t swA = (uint32_t)(rowA & 7) << 4;
    const uint32_t kselA = (uint32_t)(lane >> 4) << 4;
    const int rowBn = wn * 64 + ((lane >> 4) << 3) + (lane & 7);
    const uint32_t swB = (uint32_t)(lane & 7) << 4;
    const uint32_t kselB = (uint32_t)((lane >> 3) & 1) << 4;

    float acc[2][8][4];
    const int TOT = 96;                       // 8 token tiles x 12 chunks

    // prologue: commit groups for it = 0, 1
    #pragma unroll
    for (int p = 0; p < 2; p++) {
        int tt = p / 12, ch = p - tt * 12;
        uint32_t st = sbase + (uint32_t)(p % NSTAGE) * BUF_B;
        load_tile_async(st, g_proto_hi, vb, ch * 64, D_, V_);
        load_tile_async(st + TILE_B, g_pt_hi, b * N_ + tt * 128, ch * 64, D_, 1 << 30);
        CP_COMMIT();
    }

    #pragma unroll 1
    for (int it = 0; it < TOT; it++) {
        const int tt = it / 12, chunk = it - tt * 12;
        if (chunk == 0) {
            #pragma unroll
            for (int mf = 0; mf < 2; mf++)
                #pragma unroll
                for (int nf = 0; nf < 8; nf++)
                    #pragma unroll
                    for (int e = 0; e < 4; e++) acc[mf][nf][e] = 0.f;
        }
        CP_WAIT(1);
        __syncthreads();
        int it2 = it + 2;
        if (it2 < TOT) {
            int tt2 = it2 / 12, ch2 = it2 - tt2 * 12;
            uint32_t st = sbase + (uint32_t)(it2 % NSTAGE) * BUF_B;
            load_tile_async(st, g_proto_hi, vb, ch2 * 64, D_, V_);
            load_tile_async(st + TILE_B, g_pt_hi, b * N_ + tt2 * 128, ch2 * 64, D_, 1 << 30);
        }
        CP_COMMIT();
        uint32_t bufb = sbase + (uint32_t)(it % NSTAGE) * BUF_B;
        mma_chunk(bufb, bufb + TILE_B, acc, rowA, swA, kselA, rowBn, swB, kselB);

        if (chunk == 11) {
            // ---- per-v max over this 128-token tile ----
            float m4[2][2];
            #pragma unroll
            for (int mf = 0; mf < 2; mf++)
                #pragma unroll
                for (int h = 0; h < 2; h++) {
                    float m = -1e30f;
                    #pragma unroll
                    for (int nf = 0; nf < 8; nf++)
                        m = fmaxf(m, fmaxf(acc[mf][nf][h * 2], acc[mf][nf][h * 2 + 1]));
                    m4[mf][h] = m;
                }
            #pragma unroll
            for (int mf = 0; mf < 2; mf++)
                #pragma unroll
                for (int h = 0; h < 2; h++) {
                    float m = m4[mf][h];
                    m = fmaxf(m, __shfl_xor_sync(0xffffffffu, m, 1));
                    m = fmaxf(m, __shfl_xor_sync(0xffffffffu, m, 2));
                    m4[mf][h] = m;
                }
            __syncthreads();
            if ((lane & 3) == 0) {
                #pragma unroll
                for (int mf = 0; mf < 2; mf++)
                    #pragma unroll
                    for (int h = 0; h < 2; h++)
                        redbuf[wn][wm * 32 + mf * 16 + (lane >> 2) + h * 8] = m4[mf][h];
            }
            __syncthreads();
            if (t < 128) rmax[t] = fmaxf(rmax[t], fmaxf(redbuf[0][t], redbuf[1][t]));
            __syncthreads();

            // ---- record candidates within MARGIN of running max ----
            #pragma unroll
            for (int mf = 0; mf < 2; mf++)
                #pragma unroll
                for (int h = 0; h < 2; h++) {
                    int lrow = wm * 32 + mf * 16 + (lane >> 2) + h * 8;
                    int gv = vb + lrow;
                    if (gv >= V_) continue;
                    float thr = rmax[lrow] - MARGIN;
                    #pragma unroll
                    for (int nf = 0; nf < 8; nf++)
                        #pragma unroll
                        for (int e2 = 0; e2 < 2; e2++) {
                            float val = acc[mf][nf][h * 2 + e2];
                            if (val >= thr) {
                                unsigned pos = atomicAdd(&s_cnt, 1u);
                                if (pos < SCAP) {
                                    int tok = tt * 128 + wn * 64 + nf * 8 + (lane & 3) * 2 + e2;
                                    s_cand[pos] = ((unsigned)(b * V_ + gv) << 10) | (unsigned)tok;
                                    s_appr[pos] = val;
                                }
                            }
                        }
                }
            __syncthreads();
            if (t == 0) {
                unsigned n = min(s_cnt, (unsigned)SCAP);
                s_gbase = atomicAdd(&g_ccount, n);
                s_n = n;
                s_cnt = 0;
            }
            __syncthreads();
            for (unsigned i = t; i < s_n; i += 256) {
                unsigned gi = s_gbase + i;
                if (gi < CAND_CAP) { g_cand[gi] = s_cand[i]; g_capprox[gi] = s_appr[i]; }
            }
            __syncthreads();
        }
    }

    if (t < 128) {
        int gv = vb + t;
        if (gv < V_) g_amax[(size_t)b * V_ + gv] = rmax[t];
    }
}

// ---------------- refinement: exact fp32 dots for surviving candidates ----------------
__global__ void refine_kernel() {
    unsigned count = min(g_ccount, CAND_CAP);
    int lane = threadIdx.x & 31;
    unsigned w = (blockIdx.x * blockDim.x + threadIdx.x) >> 5;
    unsigned nw = (gridDim.x * blockDim.x) >> 5;
    for (unsigned i = w; i < count; i += nw) {
        float ap = g_capprox[i];
        unsigned c = g_cand[i];
        unsigned bv = c >> 10;
        if (ap < g_amax[bv] - RMARGIN) continue;
        unsigned tok = c & 1023u;
        unsigned b = bv / V_, v = bv - b * V_;
        const float* x = g_ptf + ((size_t)b * N_ + tok) * D_;
        const float* p = g_proto + (size_t)v * D_;
        float s = 0.f;
        #pragma unroll
        for (int jj = 0; jj < 6; jj++) {
            float4 xa = *(const float4*)(x + ((jj << 5) + lane) * 4);
            float4 pa = *(const float4*)(p + ((jj << 5) + lane) * 4);
            s += xa.x * pa.x + xa.y * pa.y + xa.z * pa.z + xa.w * pa.w;
        }
        s = warpSum(s);
        if (lane == 0) atomicMax(&g_okey[bv], fkey(s));
    }
}

// ---------------- fused finalize + softmax (values staged in smem) ----------------
__global__ void softmax_fused_kernel(float* __restrict__ out) {
    extern __shared__ float sv[];              // V_ floats
    __shared__ float sb[33];
    int b = blockIdx.x;
    int t = threadIdx.x, lane = t & 31, w = t >> 5;
    size_t base = (size_t)b * V_;

    float m = -1e30f;
    for (int v = t; v < V_; v += 1024) {
        unsigned k = g_okey[base + v];
        float val = k ? funkey(k) : g_amax[base + v];
        sv[v] = val;
        m = fmaxf(m, val);
    }
    #pragma unroll
    for (int o = 16; o; o >>= 1) m = fmaxf(m, __shfl_xor_sync(0xffffffffu, m, o));
    if (lane == 0) sb[w] = m;
    __syncthreads();
    if (t == 0) {
        float mm = -1e30f;
        for (int i = 0; i < 32; i++) mm = fmaxf(mm, sb[i]);
        sb[32] = mm;
    }
    __syncthreads();
    float M = sb[32];

    float s = 0.f;
    for (int v = t; v < V_; v += 1024) {
        float e = expf((sv[v] - M) * INV_T);
        sv[v] = e;
        s += e;
    }
    s = warpSum(s);
    __syncthreads();
    if (lane == 0) sb[w] = s;
    __syncthreads();
    if (t == 0) {
        float ss = 0.f;
        for (int i = 0; i < 32; i++) ss += sb[i];
        sb[32] = ss;
    }
    __syncthreads();
    float inv = 1.0f / sb[32];
    for (int v = t; v < V_; v += 1024) out[base + v] = sv[v] * inv;
}

// ---------------- launch ----------------
extern "C" void kernel_launch(void* const* d_in, const int* in_sizes, int n_in,
                              void* d_out, int out_size) {
    const float* patch = (const float*)d_in[0];
    const float* vocab = (const float*)d_in[1];
    const float* W1    = (const float*)d_in[2];
    const float* gamma = (const float*)d_in[3];
    const float* beta  = (const float*)d_in[4];
    const float* W2    = (const float*)d_in[5];
    const float* b2    = (const float*)d_in[6];
    float* out = (float*)d_out;

    const int VT = (V_ + 127) / 128;   // 235
    const int DYN = NSTAGE * BUF_B;    // 96KB triple buffer
    const int SMX = V_ * 4;            // 120KB softmax value cache

    cudaFuncSetAttribute(gemm1_bf16_kernel, cudaFuncAttributeMaxDynamicSharedMemorySize, DYN);
    cudaFuncSetAttribute(gemm2_bf16_kernel, cudaFuncAttributeMaxDynamicSharedMemorySize, DYN);
    cudaFuncSetAttribute(k5_mma_kernel, cudaFuncAttributeMaxDynamicSharedMemorySize, DYN);
    cudaFuncSetAttribute(softmax_fused_kernel, cudaFuncAttributeMaxDynamicSharedMemorySize, SMX);

    vnorm_split_kernel<<<V_ / 8, 256>>>(vocab);
    ptnorm_kernel<<<B_ * N_ / 8, 256>>>(patch);
    prep_kernel<<<Hh_ + D_ + 128, 256>>>(W1, W2);
    gemm1_bf16_kernel<<<dim3(Hh_ / 128, VT), 256, DYN>>>();
    bnfinal_kernel<<<1, Hh_>>>(gamma, beta);
    hsplit_kernel<<<V_ * Hh_ / 4 / 256, 256>>>();
    gemm2_bf16_kernel<<<dim3(D_ / 128, VT), 256, DYN>>>(b2);
    pnorm_kernel<<<V_ / 8, 256>>>();
    k5_mma_kernel<<<dim3(B_, VT), 256, DYN>>>();
    refine_kernel<<<512, 256>>>();
    softmax_fused_kernel<<<B_, 1024, SMX>>>(out);
}